// round 3
// baseline (speedup 1.0000x reference)
#include <cuda_runtime.h>
#include <math.h>

#define HH 192
#define WW 448
#define HWSZ (HH*WW)
#define BB 4

// Scratch (allocation-free rule: __device__ globals)
__device__ float g_x[BB*131*HWSZ];   // assembled input to conv chain
__device__ float g_a[BB*128*HWSZ];   // ping
__device__ float g_b[BB*128*HWSZ];   // pong
__device__ float g_d1[BB*25*HWSZ];   // dist after 5x1 conv
__device__ float g_mean[BB*2];

__device__ __forceinline__ float lrelu(float v){ return v >= 0.f ? v : 0.1f*v; }

__device__ __forceinline__ void ffma2(unsigned long long &d, unsigned long long a, unsigned long long b){
    asm("fma.rn.f32x2 %0, %1, %2, %0;" : "+l"(d) : "l"(a), "l"(b));
}
__device__ __forceinline__ unsigned long long pk2(float lo, float hi){
    unsigned long long r;
    asm("mov.b64 %0, {%1, %2};" : "=l"(r) : "f"(lo), "f"(hi));
    return r;
}
__device__ __forceinline__ void upk2(float &lo, float &hi, unsigned long long v){
    asm("mov.b64 {%0, %1}, %2;" : "=f"(lo), "=f"(hi) : "l"(v));
}

// ---------------- flow mean over H,W per (b,c) ----------------
__global__ void flow_mean_kernel(const float* __restrict__ flow){
    int bc = blockIdx.x;                 // 0..7
    const float* p = flow + bc*HWSZ;
    float s = 0.f;
    for (int i = threadIdx.x; i < HWSZ; i += 256) s += p[i];
    __shared__ float red[256];
    red[threadIdx.x] = s; __syncthreads();
    for (int o = 128; o > 0; o >>= 1){
        if (threadIdx.x < o) red[threadIdx.x] += red[threadIdx.x+o];
        __syncthreads();
    }
    if (threadIdx.x == 0) g_mean[bc] = red[0] / (float)HWSZ;
}

// ---------------- backwarp diff + centered flow -> g_x ch 0..2 ----------------
__global__ void assemble_kernel(const float* __restrict__ t1,
                                const float* __restrict__ t2,
                                const float* __restrict__ flow){
    int idx = blockIdx.x*256 + threadIdx.x;
    if (idx >= BB*HWSZ) return;
    int b = idx / HWSZ, p = idx % HWSZ;
    int h = p / WW, w = p % WW;
    float f0 = flow[(b*2+0)*HWSZ + p];
    float f1 = flow[(b*2+1)*HWSZ + p];
    float x = (float)w + f0*5.0f;
    float y = (float)h + f1*5.0f;
    float x0f = floorf(x), y0f = floorf(y);
    int x0 = (int)x0f, y0 = (int)y0f;
    float wx1 = x - x0f, wy1 = y - y0f;
    float wx0 = 1.f - wx1, wy0 = 1.f - wy1;
    float d2 = 0.f;
    #pragma unroll
    for (int c = 0; c < 3; c++){
        const float* img = t2 + (b*3+c)*HWSZ;
        float v00 = (y0   >= 0 && y0   < HH && x0   >= 0 && x0   < WW) ? img[y0*WW + x0]       : 0.f;
        float v01 = (y0   >= 0 && y0   < HH && x0+1 >= 0 && x0+1 < WW) ? img[y0*WW + x0+1]     : 0.f;
        float v10 = (y0+1 >= 0 && y0+1 < HH && x0   >= 0 && x0   < WW) ? img[(y0+1)*WW + x0]   : 0.f;
        float v11 = (y0+1 >= 0 && y0+1 < HH && x0+1 >= 0 && x0+1 < WW) ? img[(y0+1)*WW + x0+1] : 0.f;
        float warp = v00*(wy0*wx0) + v01*(wy0*wx1) + v10*(wy1*wx0) + v11*(wy1*wx1);
        float dv = t1[(b*3+c)*HWSZ + p] - warp;
        d2 += dv*dv;
    }
    g_x[(b*131+0)*HWSZ + p] = sqrtf(d2);
    g_x[(b*131+1)*HWSZ + p] = f0 - g_mean[b*2+0];
    g_x[(b*131+2)*HWSZ + p] = f1 - g_mean[b*2+1];
}

// ---------------- feat: 1x1 conv 64->128 + lrelu -> g_x ch 3..130 ----------------
// gridDim.x = HWSZ/512 (pixel pairs within ONE batch); blockIdx.z = b*4 + co_group
__global__ void __launch_bounds__(256) feat_kernel(const float* __restrict__ fin,
                                                   const float* __restrict__ fw,
                                                   const float* __restrict__ fb){
    int b   = blockIdx.z >> 2;
    int co0 = (blockIdx.z & 3) * 32;
    __shared__ __align__(8) float2 sw[64][32];
    for (int i = threadIdx.x; i < 64*32; i += 256){
        int ci = i >> 5, co = i & 31;
        float wv = fw[(co0+co)*64 + ci];
        sw[ci][co] = make_float2(wv, wv);
    }
    __syncthreads();
    // each thread: 2 adjacent pixels, packed; p0 in [0, HWSZ)
    int p0 = (blockIdx.x*256 + threadIdx.x) * 2;
    unsigned long long acc[32];
    #pragma unroll
    for (int co = 0; co < 32; co++) acc[co] = 0ull;
    const float* base = fin + b*64*HWSZ;
    for (int ci = 0; ci < 64; ci++){
        float2 v = *reinterpret_cast<const float2*>(base + ci*HWSZ + p0);
        unsigned long long vp = pk2(v.x, v.y);
        const unsigned long long* wrow = reinterpret_cast<const unsigned long long*>(&sw[ci][0]);
        #pragma unroll
        for (int co = 0; co < 32; co++)
            ffma2(acc[co], vp, wrow[co]);
    }
    #pragma unroll
    for (int co = 0; co < 32; co++){
        float bv = fb[co0+co];
        float a0, a1; upk2(a0, a1, acc[co]);
        float* ob = g_x + (b*131 + 3 + co0 + co)*HWSZ + p0;
        ob[0] = lrelu(a0 + bv);
        ob[1] = lrelu(a1 + bv);
    }
}

// ---------------- 3x3 conv + lrelu, packed f32x2 ----------------
// block: 256 threads; pixel tile 64x32; 8 Cout per block;
// thread: 2-wide (packed) x 4-tall pixels x 8 co
template<int UR>
__global__ void __launch_bounds__(256, 2) conv3x3_lrelu_kernel(
        const float* __restrict__ in, int Cin,
        const float* __restrict__ wgt, const float* __restrict__ bias,
        float* __restrict__ out, int Cout){
    const int CO = 8;
    int cogroups = Cout >> 3;
    int b   = blockIdx.z / cogroups;
    int co0 = (blockIdx.z % cogroups) * CO;
    int tile_x = blockIdx.x * 64;
    int tile_y = blockIdx.y * 32;
    int tid = threadIdx.x;
    int tx = tid & 31, ty = tid >> 5;      // tx: x-pair index, ty: 4-row group

    __shared__ float s_in[UR][34][66];
    __shared__ __align__(8) float2 s_w[UR][CO][9];

    unsigned long long acc[CO][4];
    #pragma unroll
    for (int co = 0; co < CO; co++)
        #pragma unroll
        for (int r = 0; r < 4; r++) acc[co][r] = 0ull;

    const float* inb = in + b*Cin*HWSZ;
    for (int c0 = 0; c0 < Cin; c0 += UR){
        int nc = min(UR, Cin - c0);
        for (int i = tid; i < nc*34*66; i += 256){
            int c = i / (34*66); int r = i % (34*66);
            int yy = r / 66, xx = r % 66;
            int gy = tile_y + yy - 1, gx = tile_x + xx - 1;
            float v = 0.f;
            if (gy >= 0 && gy < HH && gx >= 0 && gx < WW)
                v = inb[(c0+c)*HWSZ + gy*WW + gx];
            s_in[c][yy][xx] = v;
        }
        for (int i = tid; i < nc*CO*9; i += 256){
            int c = i / (CO*9); int r = i % (CO*9);
            int co = r / 9, t = r % 9;
            float wv = wgt[((co0+co)*Cin + c0 + c)*9 + t];
            s_w[c][co][t] = make_float2(wv, wv);
        }
        __syncthreads();
        for (int c = 0; c < nc; c++){
            // input packs: 6 halo rows x 3 tap positions
            unsigned long long pa[6][3];
            #pragma unroll
            for (int r = 0; r < 6; r++){
                float v0 = s_in[c][ty*4 + r][tx*2 + 0];
                float v1 = s_in[c][ty*4 + r][tx*2 + 1];
                float v2 = s_in[c][ty*4 + r][tx*2 + 2];
                float v3 = s_in[c][ty*4 + r][tx*2 + 3];
                pa[r][0] = pk2(v0, v1);
                pa[r][1] = pk2(v1, v2);
                pa[r][2] = pk2(v2, v3);
            }
            #pragma unroll
            for (int co = 0; co < CO; co++){
                const unsigned long long* wp =
                    reinterpret_cast<const unsigned long long*>(&s_w[c][co][0]);
                #pragma unroll
                for (int t = 0; t < 9; t++){
                    unsigned long long w = wp[t];
                    const int ky = t / 3, kx = t % 3;
                    #pragma unroll
                    for (int r = 0; r < 4; r++)
                        ffma2(acc[co][r], pa[r + ky][kx], w);
                }
            }
        }
        __syncthreads();
    }
    int x0 = tile_x + tx*2;
    int y0 = tile_y + ty*4;
    #pragma unroll
    for (int co = 0; co < CO; co++){
        float bv = bias[co0+co];
        float* ob = out + (b*Cout + co0 + co)*HWSZ;
        #pragma unroll
        for (int r = 0; r < 4; r++){
            float a0, a1; upk2(a0, a1, acc[co][r]);
            float2 o = make_float2(lrelu(a0 + bv), lrelu(a1 + bv));
            *reinterpret_cast<float2*>(&ob[(y0 + r)*WW + x0]) = o;
        }
    }
}

// ---------------- dist1: 5x1 conv 32->25, pad H by 2 ----------------
__global__ void __launch_bounds__(256) dist1_kernel(const float* __restrict__ in,
                                                    const float* __restrict__ w1,
                                                    const float* __restrict__ b1){
    __shared__ float sw[25*32*5];
    for (int i = threadIdx.x; i < 25*32*5; i += 256) sw[i] = w1[i];
    __syncthreads();
    int idx = blockIdx.x*256 + threadIdx.x;
    int b = idx / HWSZ, p = idx % HWSZ;
    int h = p / WW, w = p % WW;
    float acc[25];
    #pragma unroll
    for (int co = 0; co < 25; co++) acc[co] = 0.f;
    const float* inb = in + b*32*HWSZ;
    for (int ci = 0; ci < 32; ci++){
        #pragma unroll
        for (int kh = 0; kh < 5; kh++){
            int gy = h + kh - 2;
            float v = (gy >= 0 && gy < HH) ? inb[ci*HWSZ + gy*WW + w] : 0.f;
            #pragma unroll
            for (int co = 0; co < 25; co++)
                acc[co] = fmaf(v, sw[(co*32+ci)*5 + kh], acc[co]);
        }
    }
    for (int co = 0; co < 25; co++)
        g_d1[(b*25+co)*HWSZ + p] = acc[co] + b1[co];
}

// ---------------- dist2 (1x5) + softmax + unfold-weighted flow avg ----------------
__global__ void __launch_bounds__(224) final_kernel(
        const float* __restrict__ w2, const float* __restrict__ b2,
        const float* __restrict__ flow,
        const float* __restrict__ sxw, const float* __restrict__ sxb,
        const float* __restrict__ syw, const float* __restrict__ syb,
        float* __restrict__ out){
    int blk  = blockIdx.x;             // 0 .. B*H*2-1
    int half = blk & 1;
    int bh   = blk >> 1;
    int b = bh / HH, h = bh % HH;
    int x0 = half * 224;

    __shared__ float sd[25][228];
    __shared__ float sw2[25*25*5];
    for (int i = threadIdx.x; i < 25*228; i += 224){
        int ci = i / 228, xx = i % 228;
        int gx = x0 + xx - 2;
        sd[ci][xx] = (gx >= 0 && gx < WW) ? g_d1[(b*25+ci)*HWSZ + h*WW + gx] : 0.f;
    }
    for (int i = threadIdx.x; i < 25*25*5; i += 224) sw2[i] = w2[i];
    __syncthreads();

    int lx = threadIdx.x;
    int x  = x0 + lx;
    float acc[25];
    #pragma unroll
    for (int co = 0; co < 25; co++) acc[co] = 0.f;
    for (int ci = 0; ci < 25; ci++){
        #pragma unroll
        for (int kw = 0; kw < 5; kw++){
            float v = sd[ci][lx + kw];
            #pragma unroll
            for (int co = 0; co < 25; co++)
                acc[co] = fmaf(v, sw2[(co*25+ci)*5 + kw], acc[co]);
        }
    }
    float m = -1e30f;
    #pragma unroll
    for (int co = 0; co < 25; co++){
        float d = acc[co] + b2[co];
        d = -(d*d);
        acc[co] = d;
        m = fmaxf(m, d);
    }
    float s = 0.f;
    #pragma unroll
    for (int co = 0; co < 25; co++){ acc[co] = expf(acc[co] - m); s += acc[co]; }
    float dv = 1.f / s;

    const float* f0 = flow + (b*2+0)*HWSZ;
    const float* f1 = flow + (b*2+1)*HWSZ;
    float sx = sxb[0], sy = syb[0];
    #pragma unroll
    for (int k = 0; k < 25; k++){
        int kh = k / 5, kw = k % 5;
        int gy = h + kh - 2, gx = x + kw - 2;
        float u1 = 0.f, u2 = 0.f;
        if (gy >= 0 && gy < HH && gx >= 0 && gx < WW){
            u1 = f0[gy*WW + gx];
            u2 = f1[gy*WW + gx];
        }
        sx = fmaf(sxw[k], acc[k]*u1, sx);
        sy = fmaf(syw[k], acc[k]*u2, sy);
    }
    out[(b*2+0)*HWSZ + h*WW + x] = sx * dv;
    out[(b*2+1)*HWSZ + h*WW + x] = sy * dv;
}

extern "C" void kernel_launch(void* const* d_in, const int* in_sizes, int n_in,
                              void* d_out, int out_size){
    const float* t1     = (const float*)d_in[0];
    const float* t2     = (const float*)d_in[1];
    const float* ft1    = (const float*)d_in[2];
    // d_in[3] = features_tensor2 (unused by reference)
    const float* flow   = (const float*)d_in[4];
    const float* feat_w = (const float*)d_in[5];
    const float* feat_b = (const float*)d_in[6];
    const float* mw1 = (const float*)d_in[7];  const float* mb1 = (const float*)d_in[8];
    const float* mw2 = (const float*)d_in[9];  const float* mb2 = (const float*)d_in[10];
    const float* mw3 = (const float*)d_in[11]; const float* mb3 = (const float*)d_in[12];
    const float* mw4 = (const float*)d_in[13]; const float* mb4 = (const float*)d_in[14];
    const float* mw5 = (const float*)d_in[15]; const float* mb5 = (const float*)d_in[16];
    const float* mw6 = (const float*)d_in[17]; const float* mb6 = (const float*)d_in[18];
    const float* dw1 = (const float*)d_in[19]; const float* db1 = (const float*)d_in[20];
    const float* dw2 = (const float*)d_in[21]; const float* db2 = (const float*)d_in[22];
    const float* sxw = (const float*)d_in[23]; const float* sxb = (const float*)d_in[24];
    const float* syw = (const float*)d_in[25]; const float* syb = (const float*)d_in[26];
    float* out = (float*)d_out;

    float *px = nullptr, *pa = nullptr, *pb = nullptr;
    cudaGetSymbolAddress((void**)&px, g_x);
    cudaGetSymbolAddress((void**)&pa, g_a);
    cudaGetSymbolAddress((void**)&pb, g_b);

    flow_mean_kernel<<<8, 256>>>(flow);
    assemble_kernel<<<(BB*HWSZ + 255)/256, 256>>>(t1, t2, flow);
    feat_kernel<<<dim3(HWSZ/512, 1, 16), 256>>>(ft1, feat_w, feat_b);

    // conv chain: tiles 7 x 6 over 448x192 (64x32 px), 8 Cout per block
    conv3x3_lrelu_kernel<4><<<dim3(7,6,BB*16), 256>>>(px, 131, mw1, mb1, pa, 128);
    conv3x3_lrelu_kernel<4><<<dim3(7,6,BB*16), 256>>>(pa, 128, mw2, mb2, pb, 128);
    conv3x3_lrelu_kernel<4><<<dim3(7,6,BB*8),  256>>>(pb, 128, mw3, mb3, pa, 64);
    conv3x3_lrelu_kernel<4><<<dim3(7,6,BB*8),  256>>>(pa, 64,  mw4, mb4, pb, 64);
    conv3x3_lrelu_kernel<4><<<dim3(7,6,BB*4),  256>>>(pb, 64,  mw5, mb5, pa, 32);
    conv3x3_lrelu_kernel<4><<<dim3(7,6,BB*4),  256>>>(pa, 32,  mw6, mb6, pb, 32);

    dist1_kernel<<<(BB*HWSZ)/256, 256>>>(pb, dw1, db1);
    final_kernel<<<BB*HH*2, 224>>>(dw2, db2, flow, sxw, sxb, syw, syb, out);
}

// round 5
// speedup vs baseline: 7.0555x; 7.0555x over previous
#include <cuda_runtime.h>
#include <cuda_fp16.h>
#include <math.h>
#include <stdint.h>

#define HH 192
#define WW 448
#define HWSZ (HH*WW)
#define BB 4

// ---------------- scratch (__device__ globals; no allocation) ----------------
__device__ __half g_x[BB*131*HWSZ];   // assembled input to conv chain (fp16)
__device__ __half g_a[BB*128*HWSZ];   // ping (fp16)
__device__ __half g_b[BB*128*HWSZ];   // pong (fp16)
__device__ float  g_d1[BB*25*HWSZ];   // dist after 5x1 conv
__device__ float  g_mean[8];
// packed fp16 weights: per layer, [tap][kc][krow16][Cout]
#define WP_TOTAL 460800
__device__ __align__(16) __half g_wp[WP_TOTAL];

__device__ __forceinline__ float lrelu(float v){ return v >= 0.f ? v : 0.1f*v; }

__device__ __forceinline__ uint32_t smem_u32(const void* p){
    uint32_t a;
    asm("{ .reg .u64 t; cvta.to.shared.u64 t, %1; cvt.u32.u64 %0, t; }" : "=r"(a) : "l"(p));
    return a;
}

__device__ __forceinline__ void ldsm_x4(uint32_t* r, uint32_t a){
    asm volatile("ldmatrix.sync.aligned.m8n8.x4.shared.b16 {%0,%1,%2,%3}, [%4];"
        : "=r"(r[0]),"=r"(r[1]),"=r"(r[2]),"=r"(r[3]) : "r"(a));
}
__device__ __forceinline__ void ldsm_x4t(uint32_t* r, uint32_t a){
    asm volatile("ldmatrix.sync.aligned.m8n8.x4.trans.shared.b16 {%0,%1,%2,%3}, [%4];"
        : "=r"(r[0]),"=r"(r[1]),"=r"(r[2]),"=r"(r[3]) : "r"(a));
}
__device__ __forceinline__ void mma16816(float* c, const uint32_t* a, const uint32_t* b){
    asm volatile("mma.sync.aligned.m16n8k16.row.col.f32.f16.f16.f32 "
        "{%0,%1,%2,%3}, {%4,%5,%6,%7}, {%8,%9}, {%0,%1,%2,%3};"
        : "+f"(c[0]),"+f"(c[1]),"+f"(c[2]),"+f"(c[3])
        : "r"(a[0]),"r"(a[1]),"r"(a[2]),"r"(a[3]), "r"(b[0]),"r"(b[1]));
}

// ---------------- weight prep: fp32 [Cout][Cin][9] -> [tap][kc][krow16][Cout] fp16 ----------------
__global__ void prep_w(const float* __restrict__ w, int Cout, int Cin, int KC, int base){
    int idx = blockIdx.x*256 + threadIdx.x;
    int total = 9*KC*16*Cout;
    if (idx >= total) return;
    int tap = idx / (KC*16*Cout);
    int r   = idx % (KC*16*Cout);
    int kc  = r / (16*Cout);
    int r2  = r % (16*Cout);
    int krow = r2 / Cout, co = r2 % Cout;
    int ci = kc*16 + krow;
    float v = (ci < Cin) ? w[(co*Cin + ci)*9 + tap] : 0.f;
    g_wp[base + ((tap*KC + kc)*16 + krow)*Cout + co] = __float2half(v);
}

// ---------------- flow mean ----------------
__global__ void flow_mean_kernel(const float* __restrict__ flow){
    int bc = blockIdx.x;
    const float* p = flow + bc*HWSZ;
    float s = 0.f;
    for (int i = threadIdx.x; i < HWSZ; i += 256) s += p[i];
    __shared__ float red[256];
    red[threadIdx.x] = s; __syncthreads();
    for (int o = 128; o > 0; o >>= 1){
        if (threadIdx.x < o) red[threadIdx.x] += red[threadIdx.x+o];
        __syncthreads();
    }
    if (threadIdx.x == 0) g_mean[bc] = red[0] / (float)HWSZ;
}

// ---------------- backwarp diff + centered flow -> g_x ch 0..2 (fp16) ----------------
__global__ void assemble_kernel(const float* __restrict__ t1,
                                const float* __restrict__ t2,
                                const float* __restrict__ flow){
    int idx = blockIdx.x*256 + threadIdx.x;
    if (idx >= BB*HWSZ) return;
    int b = idx / HWSZ, p = idx % HWSZ;
    int h = p / WW, w = p % WW;
    float f0 = flow[(b*2+0)*HWSZ + p];
    float f1 = flow[(b*2+1)*HWSZ + p];
    float x = (float)w + f0*5.0f;
    float y = (float)h + f1*5.0f;
    float x0f = floorf(x), y0f = floorf(y);
    int x0 = (int)x0f, y0 = (int)y0f;
    float wx1 = x - x0f, wy1 = y - y0f;
    float wx0 = 1.f - wx1, wy0 = 1.f - wy1;
    float d2 = 0.f;
    #pragma unroll
    for (int c = 0; c < 3; c++){
        const float* img = t2 + (b*3+c)*HWSZ;
        float v00 = (y0   >= 0 && y0   < HH && x0   >= 0 && x0   < WW) ? img[y0*WW + x0]       : 0.f;
        float v01 = (y0   >= 0 && y0   < HH && x0+1 >= 0 && x0+1 < WW) ? img[y0*WW + x0+1]     : 0.f;
        float v10 = (y0+1 >= 0 && y0+1 < HH && x0   >= 0 && x0   < WW) ? img[(y0+1)*WW + x0]   : 0.f;
        float v11 = (y0+1 >= 0 && y0+1 < HH && x0+1 >= 0 && x0+1 < WW) ? img[(y0+1)*WW + x0+1] : 0.f;
        float warp = v00*(wy0*wx0) + v01*(wy0*wx1) + v10*(wy1*wx0) + v11*(wy1*wx1);
        float dv = t1[(b*3+c)*HWSZ + p] - warp;
        d2 += dv*dv;
    }
    g_x[(b*131+0)*HWSZ + p] = __float2half(sqrtf(d2));
    g_x[(b*131+1)*HWSZ + p] = __float2half(f0 - g_mean[b*2+0]);
    g_x[(b*131+2)*HWSZ + p] = __float2half(f1 - g_mean[b*2+1]);
}

// ---------------- feat: 1x1 conv 64->128 + lrelu -> g_x ch 3..130 (fp16) ----------------
__global__ void __launch_bounds__(256) feat_kernel(const float* __restrict__ fin,
                                                   const float* __restrict__ fw,
                                                   const float* __restrict__ fb){
    int b   = blockIdx.z >> 2;
    int co0 = (blockIdx.z & 3) * 32;
    __shared__ float sw[64][32];
    for (int i = threadIdx.x; i < 64*32; i += 256){
        int ci = i >> 5, co = i & 31;
        sw[ci][co] = fw[(co0+co)*64 + ci];
    }
    __syncthreads();
    int p0 = blockIdx.x*512 + threadIdx.x;
    int p1 = p0 + 256;
    float acc0[32], acc1[32];
    #pragma unroll
    for (int co = 0; co < 32; co++){ acc0[co] = 0.f; acc1[co] = 0.f; }
    const float* base = fin + b*64*HWSZ;
    for (int ci = 0; ci < 64; ci++){
        float v0 = base[ci*HWSZ + p0];
        float v1 = base[ci*HWSZ + p1];
        #pragma unroll
        for (int co = 0; co < 32; co++){
            float wv = sw[ci][co];
            acc0[co] = fmaf(v0, wv, acc0[co]);
            acc1[co] = fmaf(v1, wv, acc1[co]);
        }
    }
    for (int co = 0; co < 32; co++){
        float bv = fb[co0+co];
        __half* ob = g_x + ((size_t)b*131 + 3 + co0 + co)*HWSZ;
        ob[p0] = __float2half(lrelu(acc0[co] + bv));
        ob[p1] = __float2half(lrelu(acc1[co] + bv));
    }
}

// ---------------- implicit-GEMM 3x3 conv via mma.sync (fp16 in, fp32 acc) ----------------
// CTA: 128-px x-strip (M) x BN=Cout (N). 8 warps: 4(m) x 2(n); warp = 32 x BN/2.
template<int BN>
__global__ void __launch_bounds__(256) conv3x3_mma(
        const __half* __restrict__ act, int Cin, int KC,
        const float* __restrict__ bias, __half* __restrict__ out, int wp_base){
    constexpr int NT = BN/16;          // n8 tiles per warp (WN=BN/2)
    constexpr int SBS = BN + 8;        // sB row stride (halfs)
    __shared__ __half sA[128*24];
    __shared__ __half sB[16*SBS];

    int tid = threadIdx.x, wid = tid >> 5, lane = tid & 31;
    int b = blockIdx.z, y = blockIdx.y;
    int x0 = blockIdx.x * 128; if (x0 > WW-128) x0 = WW-128;
    int warp_m = wid & 3, warp_n = wid >> 2;
    int m_off = warp_m * 32, n_off = warp_n * (BN/2);

    uint32_t sAu = smem_u32(sA), sBu = smem_u32(sB);
    uint32_t addrA = sAu + (uint32_t)(((m_off + (lane & 15))*24 + (lane >> 4)*8) * 2);
    uint32_t addrB = sBu + (uint32_t)((((lane & 15))*SBS + n_off + (lane >> 4)*8) * 2);

    float acc[2][NT][4];
    #pragma unroll
    for (int mt = 0; mt < 2; mt++)
        #pragma unroll
        for (int nt = 0; nt < NT; nt++)
            #pragma unroll
            for (int r = 0; r < 4; r++) acc[mt][nt][r] = 0.f;

    int m_px = tid & 127, hs = tid >> 7;
    uint32_t sA_st = sAu + (uint32_t)((m_px*24 + hs*8) * 2);

    for (int tap = 0; tap < 9; tap++){
        int gy = y + tap/3 - 1;
        if (gy < 0 || gy >= HH) continue;
        int gx = x0 + m_px + (tap%3) - 1;
        bool xok = (gx >= 0) && (gx < WW);
        const __half* acol = act + (size_t)b*Cin*HWSZ + (size_t)gy*WW + gx;
        const __half* wtap = g_wp + wp_base + (size_t)tap*KC*16*BN;
        for (int kc = 0; kc < KC; kc++){
            __syncthreads();
            // ---- stage A[128][16] (row-major, stride 24) ----
            {
                int cib = kc*16 + hs*8;
                uint32_t pk[4];
                #pragma unroll
                for (int k2 = 0; k2 < 4; k2++){
                    int c0 = cib + k2*2;
                    __half h0 = (xok && c0   < Cin) ? acol[(size_t)c0*HWSZ]     : __float2half(0.f);
                    __half h1 = (xok && c0+1 < Cin) ? acol[(size_t)(c0+1)*HWSZ] : __float2half(0.f);
                    __half2 h2 = __halves2half2(h0, h1);
                    pk[k2] = *reinterpret_cast<uint32_t*>(&h2);
                }
                asm volatile("st.shared.v4.b32 [%0], {%1,%2,%3,%4};"
                    :: "r"(sA_st), "r"(pk[0]), "r"(pk[1]), "r"(pk[2]), "r"(pk[3]) : "memory");
            }
            // ---- stage B[16][BN] (stride SBS) ----
            {
                const uint4* src = reinterpret_cast<const uint4*>(wtap + (size_t)kc*16*BN);
                #pragma unroll 2
                for (int u = tid; u < 2*BN; u += 256){
                    int row = u / (BN/8), cu = u % (BN/8);
                    uint4 vv = src[u];
                    uint32_t dst = sBu + (uint32_t)((row*SBS + cu*8) * 2);
                    asm volatile("st.shared.v4.b32 [%0], {%1,%2,%3,%4};"
                        :: "r"(dst), "r"(vv.x), "r"(vv.y), "r"(vv.z), "r"(vv.w) : "memory");
                }
            }
            __syncthreads();
            // ---- fragments + mma ----
            uint32_t afr[2][4];
            ldsm_x4(afr[0], addrA);
            ldsm_x4(afr[1], addrA + 16*24*2);
            uint32_t bfr[NT][2];
            #pragma unroll
            for (int np = 0; np < NT/2; np++){
                uint32_t r4[4];
                ldsm_x4t(r4, addrB + (uint32_t)(np*16*2));
                bfr[2*np][0] = r4[0]; bfr[2*np][1] = r4[1];
                bfr[2*np+1][0] = r4[2]; bfr[2*np+1][1] = r4[3];
            }
            #pragma unroll
            for (int mt = 0; mt < 2; mt++)
                #pragma unroll
                for (int nt = 0; nt < NT; nt++)
                    mma16816(acc[mt][nt], afr[mt], bfr[nt]);
        }
    }

    // ---- epilogue: bias + lrelu -> fp16 CHW ----
    int row = lane >> 2, col = (lane & 3)*2;
    #pragma unroll
    for (int mt = 0; mt < 2; mt++){
        #pragma unroll
        for (int nt = 0; nt < NT; nt++){
            int n0 = n_off + nt*8 + col;
            float bv0 = bias[n0], bv1 = bias[n0+1];
            int m0 = m_off + mt*16 + row;
            __half* o0 = out + ((size_t)b*BN + n0)*HWSZ + (size_t)y*WW + x0;
            __half* o1 = o0 + HWSZ;
            o0[m0]     = __float2half(lrelu(acc[mt][nt][0] + bv0));
            o1[m0]     = __float2half(lrelu(acc[mt][nt][1] + bv1));
            o0[m0 + 8] = __float2half(lrelu(acc[mt][nt][2] + bv0));
            o1[m0 + 8] = __float2half(lrelu(acc[mt][nt][3] + bv1));
        }
    }
}

// ---------------- dist1: 5x1 conv 32->25 (fp16 in, fp32 out) ----------------
__global__ void __launch_bounds__(256) dist1_kernel(const __half* __restrict__ in,
                                                    const float* __restrict__ w1,
                                                    const float* __restrict__ b1){
    __shared__ float sw[25*32*5];
    for (int i = threadIdx.x; i < 25*32*5; i += 256) sw[i] = w1[i];
    __syncthreads();
    int idx = blockIdx.x*256 + threadIdx.x;
    int b = idx / HWSZ, p = idx % HWSZ;
    int h = p / WW, w = p % WW;
    float acc[25];
    #pragma unroll
    for (int co = 0; co < 25; co++) acc[co] = 0.f;
    const __half* inb = in + (size_t)b*32*HWSZ;
    for (int ci = 0; ci < 32; ci++){
        #pragma unroll
        for (int kh = 0; kh < 5; kh++){
            int gy = h + kh - 2;
            float v = (gy >= 0 && gy < HH) ? __half2float(inb[(size_t)ci*HWSZ + gy*WW + w]) : 0.f;
            #pragma unroll
            for (int co = 0; co < 25; co++)
                acc[co] = fmaf(v, sw[(co*32+ci)*5 + kh], acc[co]);
        }
    }
    for (int co = 0; co < 25; co++)
        g_d1[(b*25+co)*HWSZ + p] = acc[co] + b1[co];
}

// ---------------- dist2 (1x5) + softmax + unfold-weighted flow avg ----------------
__global__ void __launch_bounds__(224) final_kernel(
        const float* __restrict__ w2, const float* __restrict__ b2,
        const float* __restrict__ flow,
        const float* __restrict__ sxw, const float* __restrict__ sxb,
        const float* __restrict__ syw, const float* __restrict__ syb,
        float* __restrict__ out){
    int blk  = blockIdx.x;
    int half = blk & 1;
    int bh   = blk >> 1;
    int b = bh / HH, h = bh % HH;
    int x0 = half * 224;

    __shared__ float sd[25][228];
    __shared__ float sw2[25*25*5];
    for (int i = threadIdx.x; i < 25*228; i += 224){
        int ci = i / 228, xx = i % 228;
        int gx = x0 + xx - 2;
        sd[ci][xx] = (gx >= 0 && gx < WW) ? g_d1[(b*25+ci)*HWSZ + h*WW + gx] : 0.f;
    }
    for (int i = threadIdx.x; i < 25*25*5; i += 224) sw2[i] = w2[i];
    __syncthreads();

    int lx = threadIdx.x;
    int x  = x0 + lx;
    float acc[25];
    #pragma unroll
    for (int co = 0; co < 25; co++) acc[co] = 0.f;
    for (int ci = 0; ci < 25; ci++){
        #pragma unroll
        for (int kw = 0; kw < 5; kw++){
            float v = sd[ci][lx + kw];
            #pragma unroll
            for (int co = 0; co < 25; co++)
                acc[co] = fmaf(v, sw2[(co*25+ci)*5 + kw], acc[co]);
        }
    }
    float m = -1e30f;
    #pragma unroll
    for (int co = 0; co < 25; co++){
        float d = acc[co] + b2[co];
        d = -(d*d);
        acc[co] = d;
        m = fmaxf(m, d);
    }
    float s = 0.f;
    #pragma unroll
    for (int co = 0; co < 25; co++){ acc[co] = expf(acc[co] - m); s += acc[co]; }
    float dv = 1.f / s;

    const float* f0 = flow + (b*2+0)*HWSZ;
    const float* f1 = flow + (b*2+1)*HWSZ;
    float sx = sxb[0], sy = syb[0];
    #pragma unroll
    for (int k = 0; k < 25; k++){
        int kh = k / 5, kw = k % 5;
        int gy = h + kh - 2, gx = x + kw - 2;
        float u1 = 0.f, u2 = 0.f;
        if (gy >= 0 && gy < HH && gx >= 0 && gx < WW){
            u1 = f0[gy*WW + gx];
            u2 = f1[gy*WW + gx];
        }
        sx = fmaf(sxw[k], acc[k]*u1, sx);
        sy = fmaf(syw[k], acc[k]*u2, sy);
    }
    out[(b*2+0)*HWSZ + h*WW + x] = sx * dv;
    out[(b*2+1)*HWSZ + h*WW + x] = sy * dv;
}

extern "C" void kernel_launch(void* const* d_in, const int* in_sizes, int n_in,
                              void* d_out, int out_size){
    const float* t1     = (const float*)d_in[0];
    const float* t2     = (const float*)d_in[1];
    const float* ft1    = (const float*)d_in[2];
    const float* flow   = (const float*)d_in[4];
    const float* feat_w = (const float*)d_in[5];
    const float* feat_b = (const float*)d_in[6];
    const float* mw1 = (const float*)d_in[7];  const float* mb1 = (const float*)d_in[8];
    const float* mw2 = (const float*)d_in[9];  const float* mb2 = (const float*)d_in[10];
    const float* mw3 = (const float*)d_in[11]; const float* mb3 = (const float*)d_in[12];
    const float* mw4 = (const float*)d_in[13]; const float* mb4 = (const float*)d_in[14];
    const float* mw5 = (const float*)d_in[15]; const float* mb5 = (const float*)d_in[16];
    const float* mw6 = (const float*)d_in[17]; const float* mb6 = (const float*)d_in[18];
    const float* dw1 = (const float*)d_in[19]; const float* db1 = (const float*)d_in[20];
    const float* dw2 = (const float*)d_in[21]; const float* db2 = (const float*)d_in[22];
    const float* sxw = (const float*)d_in[23]; const float* sxb = (const float*)d_in[24];
    const float* syw = (const float*)d_in[25]; const float* syb = (const float*)d_in[26];
    float* out = (float*)d_out;

    __half *px = nullptr, *pa = nullptr, *pb = nullptr;
    cudaGetSymbolAddress((void**)&px, g_x);
    cudaGetSymbolAddress((void**)&pa, g_a);
    cudaGetSymbolAddress((void**)&pb, g_b);

    // weight packing; bases (halfs):
    // L1: 9*9*16*128 = 165888  -> base 0
    // L2: 9*8*16*128 = 147456  -> base 165888
    // L3: 9*8*16*64  =  73728  -> base 313344
    // L4: 9*4*16*64  =  36864  -> base 387072
    // L5: 9*4*16*32  =  18432  -> base 423936
    // L6: 9*2*16*32  =   9216  -> base 442368   (total 451584 <= 460800)
    prep_w<<<(9*9*16*128+255)/256, 256>>>(mw1, 128, 131, 9, 0);
    prep_w<<<(9*8*16*128+255)/256, 256>>>(mw2, 128, 128, 8, 165888);
    prep_w<<<(9*8*16*64 +255)/256, 256>>>(mw3,  64, 128, 8, 313344);
    prep_w<<<(9*4*16*64 +255)/256, 256>>>(mw4,  64,  64, 4, 387072);
    prep_w<<<(9*4*16*32 +255)/256, 256>>>(mw5,  32,  64, 4, 423936);
    prep_w<<<(9*2*16*32 +255)/256, 256>>>(mw6,  32,  32, 2, 442368);

    flow_mean_kernel<<<8, 256>>>(flow);
    assemble_kernel<<<(BB*HWSZ + 255)/256, 256>>>(t1, t2, flow);
    feat_kernel<<<dim3(HWSZ/512, 1, 16), 256>>>(ft1, feat_w, feat_b);

    dim3 cgrid(4, HH, BB);
    conv3x3_mma<128><<<cgrid, 256>>>(px, 131, 9, mb1, pa, 0);
    conv3x3_mma<128><<<cgrid, 256>>>(pa, 128, 8, mb2, pb, 165888);
    conv3x3_mma< 64><<<cgrid, 256>>>(pb, 128, 8, mb3, pa, 313344);
    conv3x3_mma< 64><<<cgrid, 256>>>(pa,  64, 4, mb4, pb, 387072);
    conv3x3_mma< 32><<<cgrid, 256>>>(pb,  64, 4, mb5, pa, 423936);
    conv3x3_mma< 32><<<cgrid, 256>>>(pa,  32, 2, mb6, pb, 442368);

    dist1_kernel<<<(BB*HWSZ)/256, 256>>>(pb, dw1, db1);
    final_kernel<<<BB*HH*2, 224>>>(dw2, db2, flow, sxw, sxb, syw, syb, out);
}

// round 6
// speedup vs baseline: 9.6983x; 1.3746x over previous
#include <cuda_runtime.h>
#include <cuda_fp16.h>
#include <math.h>
#include <stdint.h>

#define HH 192
#define WW 448
#define HWSZ (HH*WW)
#define BB 4

// ---------------- scratch (__device__ globals; no allocation) ----------------
// NHWC activations. g_x: 144 ch (0..127 feat, 128 diff, 129/130 flow, 131..143 zero)
__device__ __half g_x[BB*HWSZ*144];
__device__ __half g_a[BB*HWSZ*128];   // ping
__device__ __half g_b[BB*HWSZ*128];   // pong
__device__ float  g_d1[BB*25*HWSZ];   // dist after 5x1 conv (CHW)
__device__ float  g_mean[8];
// packed fp16 weights: per layer, [ky][kc][kx][16][BN]
#define WP_TOTAL 460800
__device__ __align__(16) __half g_wp[WP_TOTAL];

__device__ __forceinline__ float lrelu(float v){ return v >= 0.f ? v : 0.1f*v; }

__device__ __forceinline__ uint32_t smem_u32(const void* p){
    uint32_t a;
    asm("{ .reg .u64 t; cvta.to.shared.u64 t, %1; cvt.u32.u64 %0, t; }" : "=r"(a) : "l"(p));
    return a;
}
__device__ __forceinline__ void cp16(uint32_t dst, const void* src, int srcsz){
    asm volatile("cp.async.ca.shared.global [%0], [%1], 16, %2;"
        :: "r"(dst), "l"(src), "r"(srcsz) : "memory");
}
#define CP_COMMIT() asm volatile("cp.async.commit_group;" ::: "memory")
#define CP_WAIT1()  asm volatile("cp.async.wait_group 1;"  ::: "memory")
#define CP_WAIT0()  asm volatile("cp.async.wait_group 0;"  ::: "memory")

__device__ __forceinline__ void ldsm_x4(uint32_t* r, uint32_t a){
    asm volatile("ldmatrix.sync.aligned.m8n8.x4.shared.b16 {%0,%1,%2,%3}, [%4];"
        : "=r"(r[0]),"=r"(r[1]),"=r"(r[2]),"=r"(r[3]) : "r"(a));
}
__device__ __forceinline__ void ldsm_x4t(uint32_t* r, uint32_t a){
    asm volatile("ldmatrix.sync.aligned.m8n8.x4.trans.shared.b16 {%0,%1,%2,%3}, [%4];"
        : "=r"(r[0]),"=r"(r[1]),"=r"(r[2]),"=r"(r[3]) : "r"(a));
}
__device__ __forceinline__ void mma16816(float* c, const uint32_t* a, const uint32_t* b){
    asm volatile("mma.sync.aligned.m16n8k16.row.col.f32.f16.f16.f32 "
        "{%0,%1,%2,%3}, {%4,%5,%6,%7}, {%8,%9}, {%0,%1,%2,%3};"
        : "+f"(c[0]),"+f"(c[1]),"+f"(c[2]),"+f"(c[3])
        : "r"(a[0]),"r"(a[1]),"r"(a[2]),"r"(a[3]), "r"(b[0]),"r"(b[1]));
}

// ---------------- weight prep: fp32 [Cout][Cin][9] -> [ky][kc][kx][16][BN] fp16 ----------------
__global__ void prep_w(const float* __restrict__ w, int BN, int Cin, int KC, int base, int permL1){
    int idx = blockIdx.x*256 + threadIdx.x;
    int total = 9*KC*16*BN;
    if (idx >= total) return;
    int co = idx % BN; int r = idx / BN;
    int krow = r % 16; r /= 16;
    int kx = r % 3; r /= 3;
    int kc = r % KC; int ky = r / KC;
    int ci = kc*16 + krow;
    int tap = ky*3 + kx;
    float v = 0.f;
    if (ci < Cin){
        int srcci = permL1 ? (ci < 128 ? ci + 3 : ci - 128) : ci;
        v = w[(co*Cin + srcci)*9 + tap];
    }
    g_wp[base + (((ky*KC + kc)*3 + kx)*16 + krow)*BN + co] = __float2half(v);
}

// ---------------- flow mean ----------------
__global__ void flow_mean_kernel(const float* __restrict__ flow){
    int bc = blockIdx.x;
    const float* p = flow + bc*HWSZ;
    float s = 0.f;
    for (int i = threadIdx.x; i < HWSZ; i += 256) s += p[i];
    __shared__ float red[256];
    red[threadIdx.x] = s; __syncthreads();
    for (int o = 128; o > 0; o >>= 1){
        if (threadIdx.x < o) red[threadIdx.x] += red[threadIdx.x+o];
        __syncthreads();
    }
    if (threadIdx.x == 0) g_mean[bc] = red[0] / (float)HWSZ;
}

// ---------------- backwarp diff + centered flow -> g_x ch 128..143 (NHWC fp16) ----------------
__global__ void assemble_kernel(const float* __restrict__ t1,
                                const float* __restrict__ t2,
                                const float* __restrict__ flow){
    int idx = blockIdx.x*256 + threadIdx.x;
    if (idx >= BB*HWSZ) return;
    int b = idx / HWSZ, p = idx % HWSZ;
    int h = p / WW, w = p % WW;
    float f0 = flow[(b*2+0)*HWSZ + p];
    float f1 = flow[(b*2+1)*HWSZ + p];
    float x = (float)w + f0*5.0f;
    float y = (float)h + f1*5.0f;
    float x0f = floorf(x), y0f = floorf(y);
    int x0 = (int)x0f, y0 = (int)y0f;
    float wx1 = x - x0f, wy1 = y - y0f;
    float wx0 = 1.f - wx1, wy0 = 1.f - wy1;
    float d2 = 0.f;
    #pragma unroll
    for (int c = 0; c < 3; c++){
        const float* img = t2 + (b*3+c)*HWSZ;
        float v00 = (y0   >= 0 && y0   < HH && x0   >= 0 && x0   < WW) ? img[y0*WW + x0]       : 0.f;
        float v01 = (y0   >= 0 && y0   < HH && x0+1 >= 0 && x0+1 < WW) ? img[y0*WW + x0+1]     : 0.f;
        float v10 = (y0+1 >= 0 && y0+1 < HH && x0   >= 0 && x0   < WW) ? img[(y0+1)*WW + x0]   : 0.f;
        float v11 = (y0+1 >= 0 && y0+1 < HH && x0+1 >= 0 && x0+1 < WW) ? img[(y0+1)*WW + x0+1] : 0.f;
        float warp = v00*(wy0*wx0) + v01*(wy0*wx1) + v10*(wy1*wx0) + v11*(wy1*wx1);
        float dv = t1[(b*3+c)*HWSZ + p] - warp;
        d2 += dv*dv;
    }
    __half hv[16];
    hv[0] = __float2half(sqrtf(d2));
    hv[1] = __float2half(f0 - g_mean[b*2+0]);
    hv[2] = __float2half(f1 - g_mean[b*2+1]);
    #pragma unroll
    for (int i = 3; i < 16; i++) hv[i] = __float2half(0.f);
    uint4* dst = reinterpret_cast<uint4*>(g_x + ((size_t)idx)*144 + 128);
    const uint4* srcv = reinterpret_cast<const uint4*>(hv);
    dst[0] = srcv[0]; dst[1] = srcv[1];
}

// ---------------- feat: 1x1 conv 64->128 + lrelu -> g_x ch 0..127 (NHWC) ----------------
__global__ void __launch_bounds__(256) feat_kernel(const float* __restrict__ fin,
                                                   const float* __restrict__ fw,
                                                   const float* __restrict__ fb){
    int b   = blockIdx.z >> 2;
    int co0 = (blockIdx.z & 3) * 32;
    __shared__ float sw[64][32];
    for (int i = threadIdx.x; i < 64*32; i += 256){
        int ci = i >> 5, co = i & 31;
        sw[ci][co] = fw[(co0+co)*64 + ci];
    }
    __syncthreads();
    int p0 = blockIdx.x*512 + threadIdx.x;
    int p1 = p0 + 256;
    float acc0[32], acc1[32];
    #pragma unroll
    for (int co = 0; co < 32; co++){ acc0[co] = 0.f; acc1[co] = 0.f; }
    const float* base = fin + b*64*HWSZ;
    for (int ci = 0; ci < 64; ci++){
        float v0 = base[ci*HWSZ + p0];
        float v1 = base[ci*HWSZ + p1];
        #pragma unroll
        for (int co = 0; co < 32; co++){
            float wv = sw[ci][co];
            acc0[co] = fmaf(v0, wv, acc0[co]);
            acc1[co] = fmaf(v1, wv, acc1[co]);
        }
    }
    __half o0[32], o1[32];
    #pragma unroll
    for (int co = 0; co < 32; co++){
        float bv = fb[co0+co];
        o0[co] = __float2half(lrelu(acc0[co] + bv));
        o1[co] = __float2half(lrelu(acc1[co] + bv));
    }
    uint4* d0 = reinterpret_cast<uint4*>(g_x + ((size_t)b*HWSZ + p0)*144 + co0);
    uint4* d1 = reinterpret_cast<uint4*>(g_x + ((size_t)b*HWSZ + p1)*144 + co0);
    const uint4* s0 = reinterpret_cast<const uint4*>(o0);
    const uint4* s1 = reinterpret_cast<const uint4*>(o1);
    #pragma unroll
    for (int q = 0; q < 4; q++){ d0[q] = s0[q]; d1[q] = s1[q]; }
}

// ---------------- NHWC implicit-GEMM 3x3 conv via mma.sync + cp.async pipeline ----------------
// CTA: 128-px x-strip (M=128) x BN=Cout. 8 warps: 4(m) x 2(n).
// Per iter: stage A[130 px][16 k] (reused by 3 kx taps) + B[3 kx][16][BN]; 3*2*NT mma/warp.
template<int BN>
__global__ void __launch_bounds__(256) conv3x3_nhwc(
        const __half* __restrict__ act, int CX, int KC,
        const float* __restrict__ bias, __half* __restrict__ out, int wp_base){
    constexpr int NT  = BN/16;          // n8 tiles per warp (WN=BN/2)
    constexpr int SBS = BN + 8;         // sB row stride (halfs)
    constexpr int ABUF = 130*48;        // bytes per A buffer (row stride 48B)
    constexpr int BBUF = 48*SBS*2;      // bytes per B buffer
    __shared__ __align__(16) __half sA[2*130*24];
    __shared__ __align__(16) __half sB[2*48*SBS];

    int tid = threadIdx.x, wid = tid >> 5, lane = tid & 31;
    int b = blockIdx.z, y = blockIdx.y;
    int x0 = blockIdx.x * 128; if (x0 > WW-128) x0 = WW-128;
    int warp_m = wid & 3, warp_n = wid >> 2;
    int m_off = warp_m * 32, n_off = warp_n * (BN/2);

    uint32_t sAu = smem_u32(sA), sBu = smem_u32(sB);

    // valid ky list
    int gylist[3]; int nky = 0;
    #pragma unroll
    for (int ky = 0; ky < 3; ky++){
        int gy = y + ky - 1;
        if (gy >= 0 && gy < HH){ gylist[nky] = (ky << 16) | gy; nky++; }
    }
    int N = nky * KC;

    float acc[2][NT][4];
    #pragma unroll
    for (int mt = 0; mt < 2; mt++)
        #pragma unroll
        for (int nt = 0; nt < NT; nt++)
            #pragma unroll
            for (int r = 0; r < 4; r++) acc[mt][nt][r] = 0.f;

    const size_t brow = (size_t)b * HH;

    // ---- staging lambda (by index) ----
    auto stage = [&](int it){
        int buf = it & 1;
        int kykey = gylist[it / KC];
        int ky = kykey >> 16, gy = kykey & 0xffff;
        int kc = it % KC;
        // A: 130 px rows x 16 halfs (32B) each -> 260 x 16B chunks
        const __half* arowb = act + ((brow + gy)*WW)*CX + kc*16;
        uint32_t adst = sAu + buf*ABUF;
        for (int c = tid; c < 260; c += 256){
            int r = c >> 1, hf = c & 1;
            int gx = x0 - 1 + r;
            int ok = (gx >= 0 && gx < WW) ? 16 : 0;
            int gxc = gx < 0 ? 0 : (gx >= WW ? WW-1 : gx);
            cp16(adst + r*48 + hf*16, arowb + (size_t)gxc*CX + hf*8, ok);
        }
        // B: rows = kx*16+krow (48 rows) x BN halfs
        const __half* wsrc = g_wp + wp_base + (size_t)((ky*KC + kc)*48) * BN;
        uint32_t bdst = sBu + buf*BBUF;
        constexpr int CPR = BN/8;            // 16B chunks per row
        for (int c = tid; c < 48*CPR; c += 256){
            int r = c / CPR, cu = c % CPR;
            cp16(bdst + (r*SBS + cu*8)*2, wsrc + (size_t)r*BN + cu*8, 16);
        }
        CP_COMMIT();
    };

    stage(0);
    for (int it = 0; it < N; it++){
        if (it + 1 < N){ stage(it+1); CP_WAIT1(); }
        else           { CP_WAIT0(); }
        __syncthreads();
        int buf = it & 1;
        uint32_t aBase = sAu + buf*ABUF + ((lane & 15)*48) + ((lane >> 4)*16);
        uint32_t bBase = sBu + buf*BBUF + ((lane & 15)*SBS + n_off)*2 + ((lane >> 4)*16);
        #pragma unroll
        for (int kx = 0; kx < 3; kx++){
            uint32_t afr[2][4];
            ldsm_x4(afr[0], aBase + (m_off + kx)*48);
            ldsm_x4(afr[1], aBase + (m_off + kx + 16)*48);
            uint32_t bfr[NT][2];
            #pragma unroll
            for (int np = 0; np < NT/2; np++){
                uint32_t r4[4];
                ldsm_x4t(r4, bBase + (kx*16)*SBS*2 + np*16*2);
                bfr[2*np][0] = r4[0]; bfr[2*np][1] = r4[1];
                bfr[2*np+1][0] = r4[2]; bfr[2*np+1][1] = r4[3];
            }
            #pragma unroll
            for (int mt = 0; mt < 2; mt++)
                #pragma unroll
                for (int nt = 0; nt < NT; nt++)
                    mma16816(acc[mt][nt], afr[mt], bfr[nt]);
        }
        __syncthreads();
    }

    // ---- epilogue: bias + lrelu -> fp16 NHWC ----
    int row = lane >> 2, col = (lane & 3)*2;
    __half* obase = out + ((brow + y)*WW + x0) * BN;
    #pragma unroll
    for (int mt = 0; mt < 2; mt++){
        int m0 = m_off + mt*16 + row;
        #pragma unroll
        for (int nt = 0; nt < NT; nt++){
            int n0 = n_off + nt*8 + col;
            float bv0 = bias[n0], bv1 = bias[n0+1];
            __half2 v0 = __halves2half2(__float2half(lrelu(acc[mt][nt][0] + bv0)),
                                        __float2half(lrelu(acc[mt][nt][1] + bv1)));
            __half2 v1 = __halves2half2(__float2half(lrelu(acc[mt][nt][2] + bv0)),
                                        __float2half(lrelu(acc[mt][nt][3] + bv1)));
            *reinterpret_cast<__half2*>(obase + (size_t)m0*BN + n0)       = v0;
            *reinterpret_cast<__half2*>(obase + (size_t)(m0+8)*BN + n0)   = v1;
        }
    }
}

// ---------------- dist1: 5x1 conv 32->25 (NHWC fp16 in, CHW fp32 out) ----------------
__global__ void __launch_bounds__(256) dist1_kernel(const __half* __restrict__ in,
                                                    const float* __restrict__ w1,
                                                    const float* __restrict__ b1){
    __shared__ float sw[25*32*5];
    for (int i = threadIdx.x; i < 25*32*5; i += 256) sw[i] = w1[i];
    __syncthreads();
    int idx = blockIdx.x*256 + threadIdx.x;
    int b = idx / HWSZ, p = idx % HWSZ;
    int h = p / WW, w = p % WW;
    float acc[25];
    #pragma unroll
    for (int co = 0; co < 25; co++) acc[co] = 0.f;
    #pragma unroll
    for (int kh = 0; kh < 5; kh++){
        int gy = h + kh - 2;
        if (gy < 0 || gy >= HH) continue;
        const __half2* rowp = reinterpret_cast<const __half2*>(
            in + ((size_t)(b*HH + gy)*WW + w)*32);
        #pragma unroll
        for (int q = 0; q < 16; q++){
            float2 fv = __half22float2(rowp[q]);
            #pragma unroll
            for (int co = 0; co < 25; co++){
                acc[co] = fmaf(fv.x, sw[(co*32 + 2*q  )*5 + kh], acc[co]);
                acc[co] = fmaf(fv.y, sw[(co*32 + 2*q+1)*5 + kh], acc[co]);
            }
        }
    }
    for (int co = 0; co < 25; co++)
        g_d1[(b*25+co)*HWSZ + p] = acc[co] + b1[co];
}

// ---------------- dist2 (1x5) + softmax + unfold-weighted flow avg ----------------
__global__ void __launch_bounds__(224) final_kernel(
        const float* __restrict__ w2, const float* __restrict__ b2,
        const float* __restrict__ flow,
        const float* __restrict__ sxw, const float* __restrict__ sxb,
        const float* __restrict__ syw, const float* __restrict__ syb,
        float* __restrict__ out){
    int blk  = blockIdx.x;
    int half = blk & 1;
    int bh   = blk >> 1;
    int b = bh / HH, h = bh % HH;
    int x0 = half * 224;

    __shared__ float sd[25][228];
    __shared__ float sw2[25*25*5];
    for (int i = threadIdx.x; i < 25*228; i += 224){
        int ci = i / 228, xx = i % 228;
        int gx = x0 + xx - 2;
        sd[ci][xx] = (gx >= 0 && gx < WW) ? g_d1[(b*25+ci)*HWSZ + h*WW + gx] : 0.f;
    }
    for (int i = threadIdx.x; i < 25*25*5; i += 224) sw2[i] = w2[i];
    __syncthreads();

    int lx = threadIdx.x;
    int x  = x0 + lx;
    float acc[25];
    #pragma unroll
    for (int co = 0; co < 25; co++) acc[co] = 0.f;
    for (int ci = 0; ci < 25; ci++){
        #pragma unroll
        for (int kw = 0; kw < 5; kw++){
            float v = sd[ci][lx + kw];
            #pragma unroll
            for (int co = 0; co < 25; co++)
                acc[co] = fmaf(v, sw2[(co*25+ci)*5 + kw], acc[co]);
        }
    }
    float m = -1e30f;
    #pragma unroll
    for (int co = 0; co < 25; co++){
        float d = acc[co] + b2[co];
        d = -(d*d);
        acc[co] = d;
        m = fmaxf(m, d);
    }
    float s = 0.f;
    #pragma unroll
    for (int co = 0; co < 25; co++){ acc[co] = expf(acc[co] - m); s += acc[co]; }
    float dv = 1.f / s;

    const float* f0 = flow + (b*2+0)*HWSZ;
    const float* f1 = flow + (b*2+1)*HWSZ;
    float sx = sxb[0], sy = syb[0];
    #pragma unroll
    for (int k = 0; k < 25; k++){
        int kh = k / 5, kw = k % 5;
        int gy = h + kh - 2, gx = x + kw - 2;
        float u1 = 0.f, u2 = 0.f;
        if (gy >= 0 && gy < HH && gx >= 0 && gx < WW){
            u1 = f0[gy*WW + gx];
            u2 = f1[gy*WW + gx];
        }
        sx = fmaf(sxw[k], acc[k]*u1, sx);
        sy = fmaf(syw[k], acc[k]*u2, sy);
    }
    out[(b*2+0)*HWSZ + h*WW + x] = sx * dv;
    out[(b*2+1)*HWSZ + h*WW + x] = sy * dv;
}

extern "C" void kernel_launch(void* const* d_in, const int* in_sizes, int n_in,
                              void* d_out, int out_size){
    const float* t1     = (const float*)d_in[0];
    const float* t2     = (const float*)d_in[1];
    const float* ft1    = (const float*)d_in[2];
    const float* flow   = (const float*)d_in[4];
    const float* feat_w = (const float*)d_in[5];
    const float* feat_b = (const float*)d_in[6];
    const float* mw1 = (const float*)d_in[7];  const float* mb1 = (const float*)d_in[8];
    const float* mw2 = (const float*)d_in[9];  const float* mb2 = (const float*)d_in[10];
    const float* mw3 = (const float*)d_in[11]; const float* mb3 = (const float*)d_in[12];
    const float* mw4 = (const float*)d_in[13]; const float* mb4 = (const float*)d_in[14];
    const float* mw5 = (const float*)d_in[15]; const float* mb5 = (const float*)d_in[16];
    const float* mw6 = (const float*)d_in[17]; const float* mb6 = (const float*)d_in[18];
    const float* dw1 = (const float*)d_in[19]; const float* db1 = (const float*)d_in[20];
    const float* dw2 = (const float*)d_in[21]; const float* db2 = (const float*)d_in[22];
    const float* sxw = (const float*)d_in[23]; const float* sxb = (const float*)d_in[24];
    const float* syw = (const float*)d_in[25]; const float* syb = (const float*)d_in[26];
    float* out = (float*)d_out;

    __half *px = nullptr, *pa = nullptr, *pb = nullptr;
    cudaGetSymbolAddress((void**)&px, g_x);
    cudaGetSymbolAddress((void**)&pa, g_a);
    cudaGetSymbolAddress((void**)&pb, g_b);

    // weight packing; bases (halfs):
    // L1: 9*9*16*128 = 165888  -> base 0      (Cin=131 with L1 channel perm, CX=144)
    // L2: 9*8*16*128 = 147456  -> base 165888
    // L3: 9*8*16*64  =  73728  -> base 313344
    // L4: 9*4*16*64  =  36864  -> base 387072
    // L5: 9*4*16*32  =  18432  -> base 423936
    // L6: 9*2*16*32  =   9216  -> base 442368
    prep_w<<<(9*9*16*128+255)/256, 256>>>(mw1, 128, 131, 9, 0,      1);
    prep_w<<<(9*8*16*128+255)/256, 256>>>(mw2, 128, 128, 8, 165888, 0);
    prep_w<<<(9*8*16*64 +255)/256, 256>>>(mw3,  64, 128, 8, 313344, 0);
    prep_w<<<(9*4*16*64 +255)/256, 256>>>(mw4,  64,  64, 4, 387072, 0);
    prep_w<<<(9*4*16*32 +255)/256, 256>>>(mw5,  32,  64, 4, 423936, 0);
    prep_w<<<(9*2*16*32 +255)/256, 256>>>(mw6,  32,  32, 2, 442368, 0);

    flow_mean_kernel<<<8, 256>>>(flow);
    assemble_kernel<<<(BB*HWSZ + 255)/256, 256>>>(t1, t2, flow);
    feat_kernel<<<dim3(HWSZ/512, 1, 16), 256>>>(ft1, feat_w, feat_b);

    dim3 cgrid(4, HH, BB);
    conv3x3_nhwc<128><<<cgrid, 256>>>(px, 144, 9, mb1, pa, 0);
    conv3x3_nhwc<128><<<cgrid, 256>>>(pa, 128, 8, mb2, pb, 165888);
    conv3x3_nhwc< 64><<<cgrid, 256>>>(pb, 128, 8, mb3, pa, 313344);
    conv3x3_nhwc< 64><<<cgrid, 256>>>(pa,  64, 4, mb4, pb, 387072);
    conv3x3_nhwc< 32><<<cgrid, 256>>>(pb,  64, 4, mb5, pa, 423936);
    conv3x3_nhwc< 32><<<cgrid, 256>>>(pa,  32, 2, mb6, pb, 442368);

    dist1_kernel<<<(BB*HWSZ)/256, 256>>>(pb, dw1, db1);
    final_kernel<<<BB*HH*2, 224>>>(dw2, db2, flow, sxw, sxb, syw, syb, out);
}

// round 7
// speedup vs baseline: 11.2517x; 1.1602x over previous
#include <cuda_runtime.h>
#include <cuda_fp16.h>
#include <math.h>
#include <stdint.h>

#define HH 192
#define WW 448
#define HWSZ (HH*WW)
#define BB 4

// ---------------- scratch (__device__ globals; no allocation) ----------------
// NHWC activations. g_x: 144 ch (0..127 feat, 128 diff, 129/130 flow, 131..143 zero)
__device__ __half g_x[BB*HWSZ*144];
__device__ __half g_a[BB*HWSZ*128];   // ping
__device__ __half g_b[BB*HWSZ*128];   // pong
__device__ float  g_d1[BB*HWSZ*32];   // dist after 5x1 conv (NHWC fp32, ch 0..24 valid)
__device__ float  g_mean[8];
// packed fp16 weights: conv layers [ky][kc][kx][16][BN]
#define WP_TOTAL 460800
__device__ __align__(16) __half g_wp[WP_TOTAL];
__device__ __align__(16) __half g_wpf[64*128];       // feat 1x1 weights [ci][co]
__device__ __align__(16) __half g_wpd[5*2*16*32];    // dist1 weights [ky][kc][krow][co32]

__device__ __forceinline__ float lrelu(float v){ return v >= 0.f ? v : 0.1f*v; }

__device__ __forceinline__ uint32_t smem_u32(const void* p){
    uint32_t a;
    asm("{ .reg .u64 t; cvta.to.shared.u64 t, %1; cvt.u32.u64 %0, t; }" : "=r"(a) : "l"(p));
    return a;
}
__device__ __forceinline__ void cp16(uint32_t dst, const void* src, int srcsz){
    asm volatile("cp.async.ca.shared.global [%0], [%1], 16, %2;"
        :: "r"(dst), "l"(src), "r"(srcsz) : "memory");
}
#define CP_COMMIT() asm volatile("cp.async.commit_group;" ::: "memory")
#define CP_WAIT1()  asm volatile("cp.async.wait_group 1;"  ::: "memory")
#define CP_WAIT0()  asm volatile("cp.async.wait_group 0;"  ::: "memory")

__device__ __forceinline__ void ldsm_x4(uint32_t* r, uint32_t a){
    asm volatile("ldmatrix.sync.aligned.m8n8.x4.shared.b16 {%0,%1,%2,%3}, [%4];"
        : "=r"(r[0]),"=r"(r[1]),"=r"(r[2]),"=r"(r[3]) : "r"(a));
}
__device__ __forceinline__ void ldsm_x4t(uint32_t* r, uint32_t a){
    asm volatile("ldmatrix.sync.aligned.m8n8.x4.trans.shared.b16 {%0,%1,%2,%3}, [%4];"
        : "=r"(r[0]),"=r"(r[1]),"=r"(r[2]),"=r"(r[3]) : "r"(a));
}
__device__ __forceinline__ void mma16816(float* c, const uint32_t* a, const uint32_t* b){
    asm volatile("mma.sync.aligned.m16n8k16.row.col.f32.f16.f16.f32 "
        "{%0,%1,%2,%3}, {%4,%5,%6,%7}, {%8,%9}, {%0,%1,%2,%3};"
        : "+f"(c[0]),"+f"(c[1]),"+f"(c[2]),"+f"(c[3])
        : "r"(a[0]),"r"(a[1]),"r"(a[2]),"r"(a[3]), "r"(b[0]),"r"(b[1]));
}

// ---------------- weight preps ----------------
__global__ void prep_w(const float* __restrict__ w, int BN, int Cin, int KC, int base, int permL1){
    int idx = blockIdx.x*256 + threadIdx.x;
    int total = 9*KC*16*BN;
    if (idx >= total) return;
    int co = idx % BN; int r = idx / BN;
    int krow = r % 16; r /= 16;
    int kx = r % 3; r /= 3;
    int kc = r % KC; int ky = r / KC;
    int ci = kc*16 + krow;
    int tap = ky*3 + kx;
    float v = 0.f;
    if (ci < Cin){
        int srcci = permL1 ? (ci < 128 ? ci + 3 : ci - 128) : ci;
        v = w[(co*Cin + srcci)*9 + tap];
    }
    g_wp[base + (((ky*KC + kc)*3 + kx)*16 + krow)*BN + co] = __float2half(v);
}
__global__ void prep_w_feat(const float* __restrict__ w){
    int idx = blockIdx.x*256 + threadIdx.x;
    if (idx >= 64*128) return;
    int ci = idx >> 7, co = idx & 127;
    g_wpf[ci*128 + co] = __float2half(w[co*64 + ci]);
}
__global__ void prep_w_dist1(const float* __restrict__ w){
    int idx = blockIdx.x*256 + threadIdx.x;
    if (idx >= 5*2*16*32) return;
    int co = idx & 31; int r = idx >> 5;
    int krow = r % 16; r /= 16;
    int kc = r & 1; int ky = r >> 1;
    int ci = kc*16 + krow;
    float v = (co < 25) ? w[(co*32 + ci)*5 + ky] : 0.f;
    g_wpd[idx] = __float2half(v);
}

// ---------------- flow mean ----------------
__global__ void flow_mean_kernel(const float* __restrict__ flow){
    int bc = blockIdx.x;
    const float* p = flow + bc*HWSZ;
    float s = 0.f;
    for (int i = threadIdx.x; i < HWSZ; i += 256) s += p[i];
    __shared__ float red[256];
    red[threadIdx.x] = s; __syncthreads();
    for (int o = 128; o > 0; o >>= 1){
        if (threadIdx.x < o) red[threadIdx.x] += red[threadIdx.x+o];
        __syncthreads();
    }
    if (threadIdx.x == 0) g_mean[bc] = red[0] / (float)HWSZ;
}

// ---------------- backwarp diff + centered flow -> g_x ch 128..143 (NHWC fp16) ----------------
__global__ void assemble_kernel(const float* __restrict__ t1,
                                const float* __restrict__ t2,
                                const float* __restrict__ flow){
    int idx = blockIdx.x*256 + threadIdx.x;
    if (idx >= BB*HWSZ) return;
    int b = idx / HWSZ, p = idx % HWSZ;
    int h = p / WW, w = p % WW;
    float f0 = flow[(b*2+0)*HWSZ + p];
    float f1 = flow[(b*2+1)*HWSZ + p];
    float x = (float)w + f0*5.0f;
    float y = (float)h + f1*5.0f;
    float x0f = floorf(x), y0f = floorf(y);
    int x0 = (int)x0f, y0 = (int)y0f;
    float wx1 = x - x0f, wy1 = y - y0f;
    float wx0 = 1.f - wx1, wy0 = 1.f - wy1;
    float d2 = 0.f;
    #pragma unroll
    for (int c = 0; c < 3; c++){
        const float* img = t2 + (b*3+c)*HWSZ;
        float v00 = (y0   >= 0 && y0   < HH && x0   >= 0 && x0   < WW) ? img[y0*WW + x0]       : 0.f;
        float v01 = (y0   >= 0 && y0   < HH && x0+1 >= 0 && x0+1 < WW) ? img[y0*WW + x0+1]     : 0.f;
        float v10 = (y0+1 >= 0 && y0+1 < HH && x0   >= 0 && x0   < WW) ? img[(y0+1)*WW + x0]   : 0.f;
        float v11 = (y0+1 >= 0 && y0+1 < HH && x0+1 >= 0 && x0+1 < WW) ? img[(y0+1)*WW + x0+1] : 0.f;
        float warp = v00*(wy0*wx0) + v01*(wy0*wx1) + v10*(wy1*wx0) + v11*(wy1*wx1);
        float dv = t1[(b*3+c)*HWSZ + p] - warp;
        d2 += dv*dv;
    }
    __half hv[16];
    hv[0] = __float2half(sqrtf(d2));
    hv[1] = __float2half(f0 - g_mean[b*2+0]);
    hv[2] = __float2half(f1 - g_mean[b*2+1]);
    #pragma unroll
    for (int i = 3; i < 16; i++) hv[i] = __float2half(0.f);
    uint4* dst = reinterpret_cast<uint4*>(g_x + ((size_t)idx)*144 + 128);
    const uint4* srcv = reinterpret_cast<const uint4*>(hv);
    dst[0] = srcv[0]; dst[1] = srcv[1];
}

// ---------------- feat: 1x1 conv 64->128 via mma -> g_x ch 0..127 (NHWC) ----------------
// CTA: 224 px of one row, 448 threads, warps 7(m) x 2(n)
__global__ void __launch_bounds__(448) feat_mma(const float* __restrict__ fin,
                                                const float* __restrict__ fb){
    __shared__ __align__(16) __half sA[224*40];   // px-major, stride 40 halfs (80B)
    __shared__ __align__(16) __half sB[32*136];   // rows kci*16+krow, stride 136

    int tid = threadIdx.x, wid = tid >> 5, lane = tid & 31;
    int b = blockIdx.z, y = blockIdx.y;
    int x0 = blockIdx.x * 224;
    int warp_m = wid % 7, warp_n = wid / 7;
    int m_off = warp_m * 32, n_off = warp_n * 64;

    uint32_t sAu = smem_u32(sA), sBu = smem_u32(sB);
    uint32_t aBase = sAu + (lane & 15)*80 + (lane >> 4)*16;
    uint32_t bBase = sBu + ((lane & 15)*136 + n_off)*2 + (lane >> 4)*16;

    float acc[2][8][4];
    #pragma unroll
    for (int mt = 0; mt < 2; mt++)
        #pragma unroll
        for (int nt = 0; nt < 8; nt++)
            #pragma unroll
            for (int r = 0; r < 4; r++) acc[mt][nt][r] = 0.f;

    const float* fbase = fin + (size_t)b*64*HWSZ + (size_t)y*WW + x0;

    for (int kc2 = 0; kc2 < 2; kc2++){
        if (kc2) __syncthreads();
        // stage A[224 px][32 ch] from CHW fp32 (coalesced over px)
        for (int i = tid; i < 224*32; i += 448){
            int px = i % 224, ci = i / 224;
            sA[px*40 + ci] = __float2half(fbase[(size_t)(kc2*32 + ci)*HWSZ + px]);
        }
        // stage B[32][128]
        for (int c = tid; c < 32*16; c += 448){
            int r = c >> 4, cu = c & 15;
            const uint4* src = reinterpret_cast<const uint4*>(g_wpf + (kc2*32 + r)*128 + cu*8);
            *reinterpret_cast<uint4*>(sB + r*136 + cu*8) = *src;
        }
        __syncthreads();
        #pragma unroll
        for (int kci = 0; kci < 2; kci++){
            uint32_t afr[2][4];
            ldsm_x4(afr[0], aBase + m_off*80 + kci*32);
            ldsm_x4(afr[1], aBase + (m_off + 16)*80 + kci*32);
            uint32_t bfr[8][2];
            #pragma unroll
            for (int np = 0; np < 4; np++){
                uint32_t r4[4];
                ldsm_x4t(r4, bBase + kci*16*136*2 + np*16*2);
                bfr[2*np][0] = r4[0]; bfr[2*np][1] = r4[1];
                bfr[2*np+1][0] = r4[2]; bfr[2*np+1][1] = r4[3];
            }
            #pragma unroll
            for (int mt = 0; mt < 2; mt++)
                #pragma unroll
                for (int nt = 0; nt < 8; nt++)
                    mma16816(acc[mt][nt], afr[mt], bfr[nt]);
        }
    }
    // epilogue -> g_x NHWC (CX=144), ch 0..127
    int row = lane >> 2, col = (lane & 3)*2;
    __half* obase = g_x + ((size_t)(b*HH + y)*WW + x0)*144;
    #pragma unroll
    for (int mt = 0; mt < 2; mt++){
        int m0 = m_off + mt*16 + row;
        #pragma unroll
        for (int nt = 0; nt < 8; nt++){
            int n0 = n_off + nt*8 + col;
            float bv0 = fb[n0], bv1 = fb[n0+1];
            __half2 v0 = __halves2half2(__float2half(lrelu(acc[mt][nt][0] + bv0)),
                                        __float2half(lrelu(acc[mt][nt][1] + bv1)));
            __half2 v1 = __halves2half2(__float2half(lrelu(acc[mt][nt][2] + bv0)),
                                        __float2half(lrelu(acc[mt][nt][3] + bv1)));
            *reinterpret_cast<__half2*>(obase + (size_t)m0*144 + n0)     = v0;
            *reinterpret_cast<__half2*>(obase + (size_t)(m0+8)*144 + n0) = v1;
        }
    }
}

// ---------------- NHWC implicit-GEMM 3x3 conv, M=224, 448 threads ----------------
template<int BN>
__global__ void __launch_bounds__(448) conv3x3_nhwc(
        const __half* __restrict__ act, int CX, int KC,
        const float* __restrict__ bias, __half* __restrict__ out, int wp_base){
    constexpr int NT  = BN/16;
    constexpr int SBS = BN + 8;
    constexpr int ABUF = 226*48;        // bytes per A buffer (row stride 48B)
    constexpr int BBUF = 48*SBS*2;
    __shared__ __align__(16) __half sA[2*226*24];
    __shared__ __align__(16) __half sB[2*48*SBS];

    int tid = threadIdx.x, wid = tid >> 5, lane = tid & 31;
    int b = blockIdx.z, y = blockIdx.y;
    int x0 = blockIdx.x * 224;
    int warp_m = wid % 7, warp_n = wid / 7;
    int m_off = warp_m * 32, n_off = warp_n * (BN/2);

    uint32_t sAu = smem_u32(sA), sBu = smem_u32(sB);

    int gylist[3]; int nky = 0;
    #pragma unroll
    for (int ky = 0; ky < 3; ky++){
        int gy = y + ky - 1;
        if (gy >= 0 && gy < HH){ gylist[nky] = (ky << 16) | gy; nky++; }
    }
    int N = nky * KC;

    float acc[2][NT][4];
    #pragma unroll
    for (int mt = 0; mt < 2; mt++)
        #pragma unroll
        for (int nt = 0; nt < NT; nt++)
            #pragma unroll
            for (int r = 0; r < 4; r++) acc[mt][nt][r] = 0.f;

    const size_t brow = (size_t)b * HH;

    auto stage = [&](int it){
        int buf = it & 1;
        int kykey = gylist[it / KC];
        int ky = kykey >> 16, gy = kykey & 0xffff;
        int kc = it % KC;
        const __half* arowb = act + ((brow + gy)*WW)*CX + kc*16;
        uint32_t adst = sAu + buf*ABUF;
        for (int c = tid; c < 452; c += 448){
            int r = c >> 1, hf = c & 1;
            int gx = x0 - 1 + r;
            int ok = (gx >= 0 && gx < WW) ? 16 : 0;
            int gxc = gx < 0 ? 0 : (gx >= WW ? WW-1 : gx);
            cp16(adst + r*48 + hf*16, arowb + (size_t)gxc*CX + hf*8, ok);
        }
        const __half* wsrc = g_wp + wp_base + (size_t)((ky*KC + kc)*48) * BN;
        uint32_t bdst = sBu + buf*BBUF;
        constexpr int CPR = BN/8;
        for (int c = tid; c < 48*CPR; c += 448){
            int r = c / CPR, cu = c % CPR;
            cp16(bdst + (r*SBS + cu*8)*2, wsrc + (size_t)r*BN + cu*8, 16);
        }
        CP_COMMIT();
    };

    stage(0);
    for (int it = 0; it < N; it++){
        if (it + 1 < N){ stage(it+1); CP_WAIT1(); }
        else           { CP_WAIT0(); }
        __syncthreads();
        int buf = it & 1;
        uint32_t aBase = sAu + buf*ABUF + ((lane & 15)*48) + ((lane >> 4)*16);
        uint32_t bBase = sBu + buf*BBUF + ((lane & 15)*SBS + n_off)*2 + ((lane >> 4)*16);
        #pragma unroll
        for (int kx = 0; kx < 3; kx++){
            uint32_t afr[2][4];
            ldsm_x4(afr[0], aBase + (m_off + kx)*48);
            ldsm_x4(afr[1], aBase + (m_off + kx + 16)*48);
            uint32_t bfr[NT][2];
            #pragma unroll
            for (int np = 0; np < NT/2; np++){
                uint32_t r4[4];
                ldsm_x4t(r4, bBase + (kx*16)*SBS*2 + np*16*2);
                bfr[2*np][0] = r4[0]; bfr[2*np][1] = r4[1];
                bfr[2*np+1][0] = r4[2]; bfr[2*np+1][1] = r4[3];
            }
            #pragma unroll
            for (int mt = 0; mt < 2; mt++)
                #pragma unroll
                for (int nt = 0; nt < NT; nt++)
                    mma16816(acc[mt][nt], afr[mt], bfr[nt]);
        }
        __syncthreads();
    }

    int row = lane >> 2, col = (lane & 3)*2;
    __half* obase = out + ((brow + y)*WW + x0) * BN;
    #pragma unroll
    for (int mt = 0; mt < 2; mt++){
        int m0 = m_off + mt*16 + row;
        #pragma unroll
        for (int nt = 0; nt < NT; nt++){
            int n0 = n_off + nt*8 + col;
            float bv0 = bias[n0], bv1 = bias[n0+1];
            __half2 v0 = __halves2half2(__float2half(lrelu(acc[mt][nt][0] + bv0)),
                                        __float2half(lrelu(acc[mt][nt][1] + bv1)));
            __half2 v1 = __halves2half2(__float2half(lrelu(acc[mt][nt][2] + bv0)),
                                        __float2half(lrelu(acc[mt][nt][3] + bv1)));
            *reinterpret_cast<__half2*>(obase + (size_t)m0*BN + n0)       = v0;
            *reinterpret_cast<__half2*>(obase + (size_t)(m0+8)*BN + n0)   = v1;
        }
    }
}

// ---------------- dist1: 5x1 conv 32->25(pad32) via mma -> g_d1 NHWC fp32 ----------------
__global__ void __launch_bounds__(448) dist1_mma(const __half* __restrict__ act,
                                                 const float* __restrict__ b1){
    constexpr int SBS = 40;
    constexpr int ABUF = 224*48;       // bytes
    constexpr int BBUF = 16*SBS*2;
    __shared__ __align__(16) __half sA[2*224*24];
    __shared__ __align__(16) __half sB[2*16*SBS];

    int tid = threadIdx.x, wid = tid >> 5, lane = tid & 31;
    int b = blockIdx.z, y = blockIdx.y;
    int x0 = blockIdx.x * 224;
    int warp_m = wid % 7, warp_n = wid / 7;
    int m_off = warp_m * 32, n_off = warp_n * 16;

    uint32_t sAu = smem_u32(sA), sBu = smem_u32(sB);

    int gylist[5]; int nky = 0;
    #pragma unroll
    for (int ky = 0; ky < 5; ky++){
        int gy = y + ky - 2;
        if (gy >= 0 && gy < HH){ gylist[nky] = (ky << 16) | gy; nky++; }
    }
    int N = nky * 2;

    float acc[2][2][4];
    #pragma unroll
    for (int mt = 0; mt < 2; mt++)
        #pragma unroll
        for (int nt = 0; nt < 2; nt++)
            #pragma unroll
            for (int r = 0; r < 4; r++) acc[mt][nt][r] = 0.f;

    const size_t brow = (size_t)b * HH;

    auto stage = [&](int it){
        int buf = it & 1;
        int kykey = gylist[it >> 1];
        int ky = kykey >> 16, gy = kykey & 0xffff;
        int kc = it & 1;
        const __half* arowb = act + ((brow + gy)*WW + x0)*32 + kc*16;
        uint32_t adst = sAu + buf*ABUF;
        {
            int c = tid;  // 448 chunks exactly
            int r = c >> 1, hf = c & 1;
            cp16(adst + r*48 + hf*16, arowb + (size_t)r*32 + hf*8, 16);
        }
        const __half* wsrc = g_wpd + ((ky*2 + kc)*16) * 32;
        uint32_t bdst = sBu + buf*BBUF;
        if (tid < 64){
            int r = tid >> 2, cu = tid & 3;
            cp16(bdst + (r*SBS + cu*8)*2, wsrc + r*32 + cu*8, 16);
        }
        CP_COMMIT();
    };

    stage(0);
    for (int it = 0; it < N; it++){
        if (it + 1 < N){ stage(it+1); CP_WAIT1(); }
        else           { CP_WAIT0(); }
        __syncthreads();
        int buf = it & 1;
        uint32_t aBase = sAu + buf*ABUF + ((lane & 15)*48) + ((lane >> 4)*16);
        uint32_t bBase = sBu + buf*BBUF + ((lane & 15)*SBS + n_off)*2 + ((lane >> 4)*16);
        uint32_t afr[2][4];
        ldsm_x4(afr[0], aBase + m_off*48);
        ldsm_x4(afr[1], aBase + (m_off + 16)*48);
        uint32_t r4[4];
        ldsm_x4t(r4, bBase);
        uint32_t bfr[2][2];
        bfr[0][0] = r4[0]; bfr[0][1] = r4[1];
        bfr[1][0] = r4[2]; bfr[1][1] = r4[3];
        #pragma unroll
        for (int mt = 0; mt < 2; mt++)
            #pragma unroll
            for (int nt = 0; nt < 2; nt++)
                mma16816(acc[mt][nt], afr[mt], bfr[nt]);
        __syncthreads();
    }

    int row = lane >> 2, col = (lane & 3)*2;
    float* obase = g_d1 + ((brow + y)*WW + x0) * 32;
    #pragma unroll
    for (int mt = 0; mt < 2; mt++){
        int m0 = m_off + mt*16 + row;
        #pragma unroll
        for (int nt = 0; nt < 2; nt++){
            int n0 = n_off + nt*8 + col;
            float bv0 = (n0   < 25) ? b1[n0]   : 0.f;
            float bv1 = (n0+1 < 25) ? b1[n0+1] : 0.f;
            float2 v0 = make_float2(acc[mt][nt][0] + bv0, acc[mt][nt][1] + bv1);
            float2 v1 = make_float2(acc[mt][nt][2] + bv0, acc[mt][nt][3] + bv1);
            *reinterpret_cast<float2*>(obase + (size_t)m0*32 + n0)     = v0;
            *reinterpret_cast<float2*>(obase + (size_t)(m0+8)*32 + n0) = v1;
        }
    }
}

// ---------------- dist2 (1x5) + softmax + unfold-weighted flow avg ----------------
__global__ void __launch_bounds__(224) final_kernel(
        const float* __restrict__ w2, const float* __restrict__ b2,
        const float* __restrict__ flow,
        const float* __restrict__ sxw, const float* __restrict__ sxb,
        const float* __restrict__ syw, const float* __restrict__ syb,
        float* __restrict__ out){
    int blk  = blockIdx.x;
    int half = blk & 1;
    int bh   = blk >> 1;
    int b = bh / HH, h = bh % HH;
    int x0 = half * 224;

    __shared__ float sd[25][228];
    __shared__ float sw2[25*25*5];
    for (int i = threadIdx.x; i < 25*228; i += 224){
        int ci = i / 228, xx = i % 228;
        int gx = x0 + xx - 2;
        sd[ci][xx] = (gx >= 0 && gx < WW) ?
            g_d1[((size_t)(b*HH + h)*WW + gx)*32 + ci] : 0.f;
    }
    for (int i = threadIdx.x; i < 25*25*5; i += 224) sw2[i] = w2[i];
    __syncthreads();

    int lx = threadIdx.x;
    int x  = x0 + lx;
    float acc[25];
    #pragma unroll
    for (int co = 0; co < 25; co++) acc[co] = 0.f;
    for (int ci = 0; ci < 25; ci++){
        #pragma unroll
        for (int kw = 0; kw < 5; kw++){
            float v = sd[ci][lx + kw];
            #pragma unroll
            for (int co = 0; co < 25; co++)
                acc[co] = fmaf(v, sw2[(co*25+ci)*5 + kw], acc[co]);
        }
    }
    float m = -1e30f;
    #pragma unroll
    for (int co = 0; co < 25; co++){
        float d = acc[co] + b2[co];
        d = -(d*d);
        acc[co] = d;
        m = fmaxf(m, d);
    }
    float s = 0.f;
    #pragma unroll
    for (int co = 0; co < 25; co++){ acc[co] = expf(acc[co] - m); s += acc[co]; }
    float dv = 1.f / s;

    const float* f0 = flow + (b*2+0)*HWSZ;
    const float* f1 = flow + (b*2+1)*HWSZ;
    float sx = sxb[0], sy = syb[0];
    #pragma unroll
    for (int k = 0; k < 25; k++){
        int kh = k / 5, kw = k % 5;
        int gy = h + kh - 2, gx = x + kw - 2;
        float u1 = 0.f, u2 = 0.f;
        if (gy >= 0 && gy < HH && gx >= 0 && gx < WW){
            u1 = f0[gy*WW + gx];
            u2 = f1[gy*WW + gx];
        }
        sx = fmaf(sxw[k], acc[k]*u1, sx);
        sy = fmaf(syw[k], acc[k]*u2, sy);
    }
    out[(b*2+0)*HWSZ + h*WW + x] = sx * dv;
    out[(b*2+1)*HWSZ + h*WW + x] = sy * dv;
}

extern "C" void kernel_launch(void* const* d_in, const int* in_sizes, int n_in,
                              void* d_out, int out_size){
    const float* t1     = (const float*)d_in[0];
    const float* t2     = (const float*)d_in[1];
    const float* ft1    = (const float*)d_in[2];
    const float* flow   = (const float*)d_in[4];
    const float* feat_w = (const float*)d_in[5];
    const float* feat_b = (const float*)d_in[6];
    const float* mw1 = (const float*)d_in[7];  const float* mb1 = (const float*)d_in[8];
    const float* mw2 = (const float*)d_in[9];  const float* mb2 = (const float*)d_in[10];
    const float* mw3 = (const float*)d_in[11]; const float* mb3 = (const float*)d_in[12];
    const float* mw4 = (const float*)d_in[13]; const float* mb4 = (const float*)d_in[14];
    const float* mw5 = (const float*)d_in[15]; const float* mb5 = (const float*)d_in[16];
    const float* mw6 = (const float*)d_in[17]; const float* mb6 = (const float*)d_in[18];
    const float* dw1 = (const float*)d_in[19]; const float* db1 = (const float*)d_in[20];
    const float* dw2 = (const float*)d_in[21]; const float* db2 = (const float*)d_in[22];
    const float* sxw = (const float*)d_in[23]; const float* sxb = (const float*)d_in[24];
    const float* syw = (const float*)d_in[25]; const float* syb = (const float*)d_in[26];
    float* out = (float*)d_out;

    __half *px = nullptr, *pa = nullptr, *pb = nullptr;
    cudaGetSymbolAddress((void**)&px, g_x);
    cudaGetSymbolAddress((void**)&pa, g_a);
    cudaGetSymbolAddress((void**)&pb, g_b);

    prep_w<<<(9*9*16*128+255)/256, 256>>>(mw1, 128, 131, 9, 0,      1);
    prep_w<<<(9*8*16*128+255)/256, 256>>>(mw2, 128, 128, 8, 165888, 0);
    prep_w<<<(9*8*16*64 +255)/256, 256>>>(mw3,  64, 128, 8, 313344, 0);
    prep_w<<<(9*4*16*64 +255)/256, 256>>>(mw4,  64,  64, 4, 387072, 0);
    prep_w<<<(9*4*16*32 +255)/256, 256>>>(mw5,  32,  64, 4, 423936, 0);
    prep_w<<<(9*2*16*32 +255)/256, 256>>>(mw6,  32,  32, 2, 442368, 0);
    prep_w_feat<<<(64*128+255)/256, 256>>>(feat_w);
    prep_w_dist1<<<(5*2*16*32+255)/256, 256>>>(dw1);

    flow_mean_kernel<<<8, 256>>>(flow);
    assemble_kernel<<<(BB*HWSZ + 255)/256, 256>>>(t1, t2, flow);

    dim3 cgrid(2, HH, BB);
    feat_mma<<<cgrid, 448>>>(ft1, feat_b);

    conv3x3_nhwc<128><<<cgrid, 448>>>(px, 144, 9, mb1, pa, 0);
    conv3x3_nhwc<128><<<cgrid, 448>>>(pa, 128, 8, mb2, pb, 165888);
    conv3x3_nhwc< 64><<<cgrid, 448>>>(pb, 128, 8, mb3, pa, 313344);
    conv3x3_nhwc< 64><<<cgrid, 448>>>(pa,  64, 4, mb4, pb, 387072);
    conv3x3_nhwc< 32><<<cgrid, 448>>>(pb,  64, 4, mb5, pa, 423936);
    conv3x3_nhwc< 32><<<cgrid, 448>>>(pa,  32, 2, mb6, pb, 442368);

    dist1_mma<<<cgrid, 448>>>(pb, db1);
    final_kernel<<<BB*HH*2, 224>>>(dw2, db2, flow, sxw, sxb, syw, syb, out);
}

// round 8
// speedup vs baseline: 11.2809x; 1.0026x over previous
#include <cuda_runtime.h>
#include <cuda_fp16.h>
#include <math.h>
#include <stdint.h>

#define HH 192
#define WW 448
#define HWSZ (HH*WW)
#define BB 4

// ---------------- scratch (__device__ globals; no allocation) ----------------
// NHWC activations. g_x: 144 ch (0..127 feat, 128 diff, 129/130 flow, 131..143 zero)
__device__ __half g_x[BB*HWSZ*144];
__device__ __half g_a[BB*HWSZ*128];   // ping
__device__ __half g_b[BB*HWSZ*128];   // pong
__device__ float  g_d1[BB*HWSZ*32];   // dist after 5x1 conv (NHWC fp32, ch 0..24 valid)
__device__ float  g_mean[8];
// packed fp16 weights: conv layers [ky][kc][kx][16][BN]
#define WP_TOTAL 460800
__device__ __align__(16) __half g_wp[WP_TOTAL];
__device__ __align__(16) __half g_wpf[64*128];       // feat 1x1 weights [ci][co]
__device__ __align__(16) __half g_wpd[5*2*16*32];    // dist1 weights [ky][kc][krow][co32]

__device__ __forceinline__ float lrelu(float v){ return v >= 0.f ? v : 0.1f*v; }

__device__ __forceinline__ uint32_t smem_u32(const void* p){
    uint32_t a;
    asm("{ .reg .u64 t; cvta.to.shared.u64 t, %1; cvt.u32.u64 %0, t; }" : "=r"(a) : "l"(p));
    return a;
}
__device__ __forceinline__ void cp16(uint32_t dst, const void* src, int srcsz){
    asm volatile("cp.async.ca.shared.global [%0], [%1], 16, %2;"
        :: "r"(dst), "l"(src), "r"(srcsz) : "memory");
}
#define CP_COMMIT() asm volatile("cp.async.commit_group;" ::: "memory")
#define CP_WAIT0()  asm volatile("cp.async.wait_group 0;"  ::: "memory")

__device__ __forceinline__ void ldsm_x4(uint32_t* r, uint32_t a){
    asm volatile("ldmatrix.sync.aligned.m8n8.x4.shared.b16 {%0,%1,%2,%3}, [%4];"
        : "=r"(r[0]),"=r"(r[1]),"=r"(r[2]),"=r"(r[3]) : "r"(a));
}
__device__ __forceinline__ void ldsm_x4t(uint32_t* r, uint32_t a){
    asm volatile("ldmatrix.sync.aligned.m8n8.x4.trans.shared.b16 {%0,%1,%2,%3}, [%4];"
        : "=r"(r[0]),"=r"(r[1]),"=r"(r[2]),"=r"(r[3]) : "r"(a));
}
__device__ __forceinline__ void mma16816(float* c, const uint32_t* a, const uint32_t* b){
    asm volatile("mma.sync.aligned.m16n8k16.row.col.f32.f16.f16.f32 "
        "{%0,%1,%2,%3}, {%4,%5,%6,%7}, {%8,%9}, {%0,%1,%2,%3};"
        : "+f"(c[0]),"+f"(c[1]),"+f"(c[2]),"+f"(c[3])
        : "r"(a[0]),"r"(a[1]),"r"(a[2]),"r"(a[3]), "r"(b[0]),"r"(b[1]));
}

// ---------------- fused weight prep ----------------
__device__ __forceinline__ void prep_conv_one(const float* w, int idx,
        int BN, int Cin, int KC, int base, int permL1){
    int co = idx % BN; int r = idx / BN;
    int krow = r % 16; r /= 16;
    int kx = r % 3; r /= 3;
    int kc = r % KC; int ky = r / KC;
    int ci = kc*16 + krow;
    int tap = ky*3 + kx;
    float v = 0.f;
    if (ci < Cin){
        int srcci = permL1 ? (ci < 128 ? ci + 3 : ci - 128) : ci;
        v = w[(co*Cin + srcci)*9 + tap];
    }
    g_wp[base + (((ky*KC + kc)*3 + kx)*16 + krow)*BN + co] = __float2half(v);
}

__global__ void prep_all(const float* __restrict__ mw1, const float* __restrict__ mw2,
                         const float* __restrict__ mw3, const float* __restrict__ mw4,
                         const float* __restrict__ mw5, const float* __restrict__ mw6,
                         const float* __restrict__ fw,  const float* __restrict__ dw1){
    int idx = blockIdx.x*256 + threadIdx.x;
    if (idx < 165888){ prep_conv_one(mw1, idx, 128, 131, 9, 0, 1); return; }
    idx -= 165888;
    if (idx < 147456){ prep_conv_one(mw2, idx, 128, 128, 8, 165888, 0); return; }
    idx -= 147456;
    if (idx < 73728){ prep_conv_one(mw3, idx, 64, 128, 8, 313344, 0); return; }
    idx -= 73728;
    if (idx < 36864){ prep_conv_one(mw4, idx, 64, 64, 4, 387072, 0); return; }
    idx -= 36864;
    if (idx < 18432){ prep_conv_one(mw5, idx, 32, 64, 4, 423936, 0); return; }
    idx -= 18432;
    if (idx < 9216){ prep_conv_one(mw6, idx, 32, 32, 2, 442368, 0); return; }
    idx -= 9216;
    if (idx < 64*128){
        int ci = idx >> 7, co = idx & 127;
        g_wpf[ci*128 + co] = __float2half(fw[co*64 + ci]);
        return;
    }
    idx -= 64*128;
    if (idx < 5*2*16*32){
        int co = idx & 31; int r = idx >> 5;
        int krow = r % 16; r /= 16;
        int kc = r & 1; int ky = r >> 1;
        int ci = kc*16 + krow;
        float v = (co < 25) ? dw1[(co*32 + ci)*5 + ky] : 0.f;
        g_wpd[idx] = __float2half(v);
    }
}
#define PREP_TOTAL (165888+147456+73728+36864+18432+9216+8192+5120)

// ---------------- flow mean ----------------
__global__ void flow_mean_kernel(const float* __restrict__ flow){
    int bc = blockIdx.x;
    const float* p = flow + bc*HWSZ;
    float s = 0.f;
    for (int i = threadIdx.x; i < HWSZ; i += 256) s += p[i];
    __shared__ float red[256];
    red[threadIdx.x] = s; __syncthreads();
    for (int o = 128; o > 0; o >>= 1){
        if (threadIdx.x < o) red[threadIdx.x] += red[threadIdx.x+o];
        __syncthreads();
    }
    if (threadIdx.x == 0) g_mean[bc] = red[0] / (float)HWSZ;
}

// ---------------- backwarp diff + centered flow -> g_x ch 128..143 (NHWC fp16) ----------------
__global__ void assemble_kernel(const float* __restrict__ t1,
                                const float* __restrict__ t2,
                                const float* __restrict__ flow){
    int idx = blockIdx.x*256 + threadIdx.x;
    if (idx >= BB*HWSZ) return;
    int b = idx / HWSZ, p = idx % HWSZ;
    int h = p / WW, w = p % WW;
    float f0 = flow[(b*2+0)*HWSZ + p];
    float f1 = flow[(b*2+1)*HWSZ + p];
    float x = (float)w + f0*5.0f;
    float y = (float)h + f1*5.0f;
    float x0f = floorf(x), y0f = floorf(y);
    int x0 = (int)x0f, y0 = (int)y0f;
    float wx1 = x - x0f, wy1 = y - y0f;
    float wx0 = 1.f - wx1, wy0 = 1.f - wy1;
    float d2 = 0.f;
    #pragma unroll
    for (int c = 0; c < 3; c++){
        const float* img = t2 + (b*3+c)*HWSZ;
        float v00 = (y0   >= 0 && y0   < HH && x0   >= 0 && x0   < WW) ? img[y0*WW + x0]       : 0.f;
        float v01 = (y0   >= 0 && y0   < HH && x0+1 >= 0 && x0+1 < WW) ? img[y0*WW + x0+1]     : 0.f;
        float v10 = (y0+1 >= 0 && y0+1 < HH && x0   >= 0 && x0   < WW) ? img[(y0+1)*WW + x0]   : 0.f;
        float v11 = (y0+1 >= 0 && y0+1 < HH && x0+1 >= 0 && x0+1 < WW) ? img[(y0+1)*WW + x0+1] : 0.f;
        float warp = v00*(wy0*wx0) + v01*(wy0*wx1) + v10*(wy1*wx0) + v11*(wy1*wx1);
        float dv = t1[(b*3+c)*HWSZ + p] - warp;
        d2 += dv*dv;
    }
    __half hv[16];
    hv[0] = __float2half(sqrtf(d2));
    hv[1] = __float2half(f0 - g_mean[b*2+0]);
    hv[2] = __float2half(f1 - g_mean[b*2+1]);
    #pragma unroll
    for (int i = 3; i < 16; i++) hv[i] = __float2half(0.f);
    uint4* dst = reinterpret_cast<uint4*>(g_x + ((size_t)idx)*144 + 128);
    const uint4* srcv = reinterpret_cast<const uint4*>(hv);
    dst[0] = srcv[0]; dst[1] = srcv[1];
}

// ---------------- feat: 1x1 conv 64->128 via mma -> g_x ch 0..127 (NHWC) ----------------
__global__ void __launch_bounds__(448) feat_mma(const float* __restrict__ fin,
                                                const float* __restrict__ fb){
    __shared__ __align__(16) __half sA[224*40];
    __shared__ __align__(16) __half sB[32*136];

    int tid = threadIdx.x, wid = tid >> 5, lane = tid & 31;
    int b = blockIdx.z, y = blockIdx.y;
    int x0 = blockIdx.x * 224;
    int warp_m = wid % 7, warp_n = wid / 7;
    int m_off = warp_m * 32, n_off = warp_n * 64;

    uint32_t sAu = smem_u32(sA), sBu = smem_u32(sB);
    uint32_t aBase = sAu + (lane & 15)*80 + (lane >> 4)*16;
    uint32_t bBase = sBu + ((lane & 15)*136 + n_off)*2 + (lane >> 4)*16;

    float acc[2][8][4];
    #pragma unroll
    for (int mt = 0; mt < 2; mt++)
        #pragma unroll
        for (int nt = 0; nt < 8; nt++)
            #pragma unroll
            for (int r = 0; r < 4; r++) acc[mt][nt][r] = 0.f;

    const float* fbase = fin + (size_t)b*64*HWSZ + (size_t)y*WW + x0;

    for (int kc2 = 0; kc2 < 2; kc2++){
        if (kc2) __syncthreads();
        for (int i = tid; i < 224*32; i += 448){
            int px = i % 224, ci = i / 224;
            sA[px*40 + ci] = __float2half(fbase[(size_t)(kc2*32 + ci)*HWSZ + px]);
        }
        for (int c = tid; c < 32*16; c += 448){
            int r = c >> 4, cu = c & 15;
            const uint4* src = reinterpret_cast<const uint4*>(g_wpf + (kc2*32 + r)*128 + cu*8);
            *reinterpret_cast<uint4*>(sB + r*136 + cu*8) = *src;
        }
        __syncthreads();
        #pragma unroll
        for (int kci = 0; kci < 2; kci++){
            uint32_t afr[2][4];
            ldsm_x4(afr[0], aBase + m_off*80 + kci*32);
            ldsm_x4(afr[1], aBase + (m_off + 16)*80 + kci*32);
            uint32_t bfr[8][2];
            #pragma unroll
            for (int np = 0; np < 4; np++){
                uint32_t r4[4];
                ldsm_x4t(r4, bBase + kci*16*136*2 + np*16*2);
                bfr[2*np][0] = r4[0]; bfr[2*np][1] = r4[1];
                bfr[2*np+1][0] = r4[2]; bfr[2*np+1][1] = r4[3];
            }
            #pragma unroll
            for (int mt = 0; mt < 2; mt++)
                #pragma unroll
                for (int nt = 0; nt < 8; nt++)
                    mma16816(acc[mt][nt], afr[mt], bfr[nt]);
        }
    }
    int row = lane >> 2, col = (lane & 3)*2;
    __half* obase = g_x + ((size_t)(b*HH + y)*WW + x0)*144;
    #pragma unroll
    for (int mt = 0; mt < 2; mt++){
        int m0 = m_off + mt*16 + row;
        #pragma unroll
        for (int nt = 0; nt < 8; nt++){
            int n0 = n_off + nt*8 + col;
            float bv0 = fb[n0], bv1 = fb[n0+1];
            __half2 v0 = __halves2half2(__float2half(lrelu(acc[mt][nt][0] + bv0)),
                                        __float2half(lrelu(acc[mt][nt][1] + bv1)));
            __half2 v1 = __halves2half2(__float2half(lrelu(acc[mt][nt][2] + bv0)),
                                        __float2half(lrelu(acc[mt][nt][3] + bv1)));
            *reinterpret_cast<__half2*>(obase + (size_t)m0*144 + n0)     = v0;
            *reinterpret_cast<__half2*>(obase + (size_t)(m0+8)*144 + n0) = v1;
        }
    }
}

// ---------------- NHWC implicit-GEMM 3x3 conv, M=224, 448 threads ----------------
// Pipeline: wait -> sync -> stage(it+1) -> mma(it). Single sync per iter.
template<int BN>
__global__ void __launch_bounds__(448) conv3x3_nhwc(
        const __half* __restrict__ act, int CX, int KC,
        const float* __restrict__ bias, __half* __restrict__ out, int wp_base){
    constexpr int NT  = BN/16;
    constexpr int SBS = BN + 8;
    constexpr int ABUF = 226*48;        // bytes per A buffer (row stride 48B)
    constexpr int BBUF = 48*SBS*2;
    __shared__ __align__(16) __half sA[2*226*24];
    __shared__ __align__(16) __half sB[2*48*SBS];

    int tid = threadIdx.x, wid = tid >> 5, lane = tid & 31;
    int b = blockIdx.z, y = blockIdx.y;
    int x0 = blockIdx.x * 224;
    int warp_m = wid % 7, warp_n = wid / 7;
    int m_off = warp_m * 32, n_off = warp_n * (BN/2);

    uint32_t sAu = smem_u32(sA), sBu = smem_u32(sB);

    int gylist[3]; int nky = 0;
    #pragma unroll
    for (int ky = 0; ky < 3; ky++){
        int gy = y + ky - 1;
        if (gy >= 0 && gy < HH){ gylist[nky] = (ky << 16) | gy; nky++; }
    }
    int N = nky * KC;

    float acc[2][NT][4];
    #pragma unroll
    for (int mt = 0; mt < 2; mt++)
        #pragma unroll
        for (int nt = 0; nt < NT; nt++)
            #pragma unroll
            for (int r = 0; r < 4; r++) acc[mt][nt][r] = 0.f;

    const size_t brow = (size_t)b * HH;

    auto stage = [&](int it){
        int buf = it & 1;
        int kykey = gylist[it / KC];
        int ky = kykey >> 16, gy = kykey & 0xffff;
        int kc = it % KC;
        const __half* arowb = act + ((brow + gy)*WW)*CX + kc*16;
        uint32_t adst = sAu + buf*ABUF;
        for (int c = tid; c < 452; c += 448){
            int r = c >> 1, hf = c & 1;
            int gx = x0 - 1 + r;
            int ok = (gx >= 0 && gx < WW) ? 16 : 0;
            int gxc = gx < 0 ? 0 : (gx >= WW ? WW-1 : gx);
            cp16(adst + r*48 + hf*16, arowb + (size_t)gxc*CX + hf*8, ok);
        }
        const __half* wsrc = g_wp + wp_base + (size_t)((ky*KC + kc)*48) * BN;
        uint32_t bdst = sBu + buf*BBUF;
        constexpr int CPR = BN/8;
        for (int c = tid; c < 48*CPR; c += 448){
            int r = c / CPR, cu = c % CPR;
            cp16(bdst + (r*SBS + cu*8)*2, wsrc + (size_t)r*BN + cu*8, 16);
        }
        CP_COMMIT();
    };

    stage(0);
    for (int it = 0; it < N; it++){
        CP_WAIT0();
        __syncthreads();
        if (it + 1 < N) stage(it+1);
        int buf = it & 1;
        uint32_t aBase = sAu + buf*ABUF + ((lane & 15)*48) + ((lane >> 4)*16);
        uint32_t bBase = sBu + buf*BBUF + ((lane & 15)*SBS + n_off)*2 + ((lane >> 4)*16);
        #pragma unroll
        for (int kx = 0; kx < 3; kx++){
            uint32_t afr[2][4];
            ldsm_x4(afr[0], aBase + (m_off + kx)*48);
            ldsm_x4(afr[1], aBase + (m_off + kx + 16)*48);
            uint32_t bfr[NT][2];
            #pragma unroll
            for (int np = 0; np < NT/2; np++){
                uint32_t r4[4];
                ldsm_x4t(r4, bBase + (kx*16)*SBS*2 + np*16*2);
                bfr[2*np][0] = r4[0]; bfr[2*np][1] = r4[1];
                bfr[2*np+1][0] = r4[2]; bfr[2*np+1][1] = r4[3];
            }
            #pragma unroll
            for (int mt = 0; mt < 2; mt++)
                #pragma unroll
                for (int nt = 0; nt < NT; nt++)
                    mma16816(acc[mt][nt], afr[mt], bfr[nt]);
        }
    }

    int row = lane >> 2, col = (lane & 3)*2;
    __half* obase = out + ((brow + y)*WW + x0) * BN;
    #pragma unroll
    for (int mt = 0; mt < 2; mt++){
        int m0 = m_off + mt*16 + row;
        #pragma unroll
        for (int nt = 0; nt < NT; nt++){
            int n0 = n_off + nt*8 + col;
            float bv0 = bias[n0], bv1 = bias[n0+1];
            __half2 v0 = __halves2half2(__float2half(lrelu(acc[mt][nt][0] + bv0)),
                                        __float2half(lrelu(acc[mt][nt][1] + bv1)));
            __half2 v1 = __halves2half2(__float2half(lrelu(acc[mt][nt][2] + bv0)),
                                        __float2half(lrelu(acc[mt][nt][3] + bv1)));
            *reinterpret_cast<__half2*>(obase + (size_t)m0*BN + n0)       = v0;
            *reinterpret_cast<__half2*>(obase + (size_t)(m0+8)*BN + n0)   = v1;
        }
    }
}

// ---------------- dist1: 5x1 conv 32->25(pad32) via mma -> g_d1 NHWC fp32 ----------------
__global__ void __launch_bounds__(448) dist1_mma(const __half* __restrict__ act,
                                                 const float* __restrict__ b1){
    constexpr int SBS = 40;
    constexpr int ABUF = 224*48;
    constexpr int BBUF = 16*SBS*2;
    __shared__ __align__(16) __half sA[2*224*24];
    __shared__ __align__(16) __half sB[2*16*SBS];

    int tid = threadIdx.x, wid = tid >> 5, lane = tid & 31;
    int b = blockIdx.z, y = blockIdx.y;
    int x0 = blockIdx.x * 224;
    int warp_m = wid % 7, warp_n = wid / 7;
    int m_off = warp_m * 32, n_off = warp_n * 16;

    uint32_t sAu = smem_u32(sA), sBu = smem_u32(sB);

    int gylist[5]; int nky = 0;
    #pragma unroll
    for (int ky = 0; ky < 5; ky++){
        int gy = y + ky - 2;
        if (gy >= 0 && gy < HH){ gylist[nky] = (ky << 16) | gy; nky++; }
    }
    int N = nky * 2;

    float acc[2][2][4];
    #pragma unroll
    for (int mt = 0; mt < 2; mt++)
        #pragma unroll
        for (int nt = 0; nt < 2; nt++)
            #pragma unroll
            for (int r = 0; r < 4; r++) acc[mt][nt][r] = 0.f;

    const size_t brow = (size_t)b * HH;

    auto stage = [&](int it){
        int buf = it & 1;
        int kykey = gylist[it >> 1];
        int ky = kykey >> 16, gy = kykey & 0xffff;
        int kc = it & 1;
        const __half* arowb = act + ((brow + gy)*WW + x0)*32 + kc*16;
        uint32_t adst = sAu + buf*ABUF;
        {
            int c = tid;
            int r = c >> 1, hf = c & 1;
            cp16(adst + r*48 + hf*16, arowb + (size_t)r*32 + hf*8, 16);
        }
        const __half* wsrc = g_wpd + ((ky*2 + kc)*16) * 32;
        uint32_t bdst = sBu + buf*BBUF;
        if (tid < 64){
            int r = tid >> 2, cu = tid & 3;
            cp16(bdst + (r*SBS + cu*8)*2, wsrc + r*32 + cu*8, 16);
        }
        CP_COMMIT();
    };

    stage(0);
    for (int it = 0; it < N; it++){
        CP_WAIT0();
        __syncthreads();
        if (it + 1 < N) stage(it+1);
        int buf = it & 1;
        uint32_t aBase = sAu + buf*ABUF + ((lane & 15)*48) + ((lane >> 4)*16);
        uint32_t bBase = sBu + buf*BBUF + ((lane & 15)*SBS + n_off)*2 + ((lane >> 4)*16);
        uint32_t afr[2][4];
        ldsm_x4(afr[0], aBase + m_off*48);
        ldsm_x4(afr[1], aBase + (m_off + 16)*48);
        uint32_t r4[4];
        ldsm_x4t(r4, bBase);
        uint32_t bfr[2][2];
        bfr[0][0] = r4[0]; bfr[0][1] = r4[1];
        bfr[1][0] = r4[2]; bfr[1][1] = r4[3];
        #pragma unroll
        for (int mt = 0; mt < 2; mt++)
            #pragma unroll
            for (int nt = 0; nt < 2; nt++)
                mma16816(acc[mt][nt], afr[mt], bfr[nt]);
    }

    int row = lane >> 2, col = (lane & 3)*2;
    float* obase = g_d1 + ((brow + y)*WW + x0) * 32;
    #pragma unroll
    for (int mt = 0; mt < 2; mt++){
        int m0 = m_off + mt*16 + row;
        #pragma unroll
        for (int nt = 0; nt < 2; nt++){
            int n0 = n_off + nt*8 + col;
            float bv0 = (n0   < 25) ? b1[n0]   : 0.f;
            float bv1 = (n0+1 < 25) ? b1[n0+1] : 0.f;
            float2 v0 = make_float2(acc[mt][nt][0] + bv0, acc[mt][nt][1] + bv1);
            float2 v1 = make_float2(acc[mt][nt][2] + bv0, acc[mt][nt][3] + bv1);
            *reinterpret_cast<float2*>(obase + (size_t)m0*32 + n0)     = v0;
            *reinterpret_cast<float2*>(obase + (size_t)(m0+8)*32 + n0) = v1;
        }
    }
}

// ---------------- dist2 (1x5) + softmax + unfold-weighted flow avg ----------------
__global__ void __launch_bounds__(224) final_kernel(
        const float* __restrict__ w2, const float* __restrict__ b2,
        const float* __restrict__ flow,
        const float* __restrict__ sxw, const float* __restrict__ sxb,
        const float* __restrict__ syw, const float* __restrict__ syb,
        float* __restrict__ out){
    int blk  = blockIdx.x;
    int half = blk & 1;
    int bh   = blk >> 1;
    int b = bh / HH, h = bh % HH;
    int x0 = half * 224;

    __shared__ float sd[25][228];
    __shared__ float sw2[25*25*5];
    for (int i = threadIdx.x; i < 25*228; i += 224){
        int ci = i / 228, xx = i % 228;
        int gx = x0 + xx - 2;
        sd[ci][xx] = (gx >= 0 && gx < WW) ?
            g_d1[((size_t)(b*HH + h)*WW + gx)*32 + ci] : 0.f;
    }
    for (int i = threadIdx.x; i < 25*25*5; i += 224) sw2[i] = w2[i];
    __syncthreads();

    int lx = threadIdx.x;
    int x  = x0 + lx;
    float acc[25];
    #pragma unroll
    for (int co = 0; co < 25; co++) acc[co] = 0.f;
    for (int ci = 0; ci < 25; ci++){
        #pragma unroll
        for (int kw = 0; kw < 5; kw++){
            float v = sd[ci][lx + kw];
            #pragma unroll
            for (int co = 0; co < 25; co++)
                acc[co] = fmaf(v, sw2[(co*25+ci)*5 + kw], acc[co]);
        }
    }
    float m = -1e30f;
    #pragma unroll
    for (int co = 0; co < 25; co++){
        float d = acc[co] + b2[co];
        d = -(d*d);
        acc[co] = d;
        m = fmaxf(m, d);
    }
    float s = 0.f;
    #pragma unroll
    for (int co = 0; co < 25; co++){ acc[co] = expf(acc[co] - m); s += acc[co]; }
    float dv = 1.f / s;

    const float* f0 = flow + (b*2+0)*HWSZ;
    const float* f1 = flow + (b*2+1)*HWSZ;
    float sx = sxb[0], sy = syb[0];
    #pragma unroll
    for (int k = 0; k < 25; k++){
        int kh = k / 5, kw = k % 5;
        int gy = h + kh - 2, gx = x + kw - 2;
        float u1 = 0.f, u2 = 0.f;
        if (gy >= 0 && gy < HH && gx >= 0 && gx < WW){
            u1 = f0[gy*WW + gx];
            u2 = f1[gy*WW + gx];
        }
        sx = fmaf(sxw[k], acc[k]*u1, sx);
        sy = fmaf(syw[k], acc[k]*u2, sy);
    }
    out[(b*2+0)*HWSZ + h*WW + x] = sx * dv;
    out[(b*2+1)*HWSZ + h*WW + x] = sy * dv;
}

extern "C" void kernel_launch(void* const* d_in, const int* in_sizes, int n_in,
                              void* d_out, int out_size){
    const float* t1     = (const float*)d_in[0];
    const float* t2     = (const float*)d_in[1];
    const float* ft1    = (const float*)d_in[2];
    const float* flow   = (const float*)d_in[4];
    const float* feat_w = (const float*)d_in[5];
    const float* feat_b = (const float*)d_in[6];
    const float* mw1 = (const float*)d_in[7];  const float* mb1 = (const float*)d_in[8];
    const float* mw2 = (const float*)d_in[9];  const float* mb2 = (const float*)d_in[10];
    const float* mw3 = (const float*)d_in[11]; const float* mb3 = (const float*)d_in[12];
    const float* mw4 = (const float*)d_in[13]; const float* mb4 = (const float*)d_in[14];
    const float* mw5 = (const float*)d_in[15]; const float* mb5 = (const float*)d_in[16];
    const float* mw6 = (const float*)d_in[17]; const float* mb6 = (const float*)d_in[18];
    const float* dw1 = (const float*)d_in[19]; const float* db1 = (const float*)d_in[20];
    const float* dw2 = (const float*)d_in[21]; const float* db2 = (const float*)d_in[22];
    const float* sxw = (const float*)d_in[23]; const float* sxb = (const float*)d_in[24];
    const float* syw = (const float*)d_in[25]; const float* syb = (const float*)d_in[26];
    float* out = (float*)d_out;

    __half *px = nullptr, *pa = nullptr, *pb = nullptr;
    cudaGetSymbolAddress((void**)&px, g_x);
    cudaGetSymbolAddress((void**)&pa, g_a);
    cudaGetSymbolAddress((void**)&pb, g_b);

    // launch 1: fused weight prep
    prep_all<<<(PREP_TOTAL + 255)/256, 256>>>(mw1, mw2, mw3, mw4, mw5, mw6, feat_w, dw1);
    // launches 2-4
    flow_mean_kernel<<<8, 256>>>(flow);
    assemble_kernel<<<(BB*HWSZ + 255)/256, 256>>>(t1, t2, flow);
    dim3 cgrid(2, HH, BB);
    feat_mma<<<cgrid, 448>>>(ft1, feat_b);

    // launches 5-10: conv chain (launch #6 = conv layer 2 -> captured by ncu -s 5 -c 1)
    conv3x3_nhwc<128><<<cgrid, 448>>>(px, 144, 9, mb1, pa, 0);
    conv3x3_nhwc<128><<<cgrid, 448>>>(pa, 128, 8, mb2, pb, 165888);
    conv3x3_nhwc< 64><<<cgrid, 448>>>(pb, 128, 8, mb3, pa, 313344);
    conv3x3_nhwc< 64><<<cgrid, 448>>>(pa,  64, 4, mb4, pb, 387072);
    conv3x3_nhwc< 32><<<cgrid, 448>>>(pb,  64, 4, mb5, pa, 423936);
    conv3x3_nhwc< 32><<<cgrid, 448>>>(pa,  32, 2, mb6, pb, 442368);

    dist1_mma<<<cgrid, 448>>>(pb, db1);
    final_kernel<<<BB*HH*2, 224>>>(dw2, db2, flow, sxw, sxb, syw, syb, out);
}

// round 9
// speedup vs baseline: 11.9769x; 1.0617x over previous
#include <cuda_runtime.h>
#include <cuda_fp16.h>
#include <math.h>
#include <stdint.h>

#define HH 192
#define WW 448
#define HWSZ (HH*WW)
#define BB 4

// ---------------- scratch (__device__ globals; no allocation) ----------------
__device__ __half g_x[BB*HWSZ*144];
__device__ __half g_a[BB*HWSZ*128];   // ping
__device__ __half g_b[BB*HWSZ*128];   // pong
__device__ float  g_d1[BB*HWSZ*32];   // dist after 5x1 conv (NHWC fp32, ch 0..24 valid)
__device__ float  g_mean[8];
#define WP_TOTAL 460800
__device__ __align__(16) __half g_wp[WP_TOTAL];
__device__ __align__(16) __half g_wpf[64*128];       // feat 1x1 weights [ci][co]
__device__ __align__(16) __half g_wpd[5*2*16*32];    // dist1 weights [ky][kc][krow][co32]

__device__ __forceinline__ float lrelu(float v){ return v >= 0.f ? v : 0.1f*v; }

__device__ __forceinline__ uint32_t smem_u32(const void* p){
    uint32_t a;
    asm("{ .reg .u64 t; cvta.to.shared.u64 t, %1; cvt.u32.u64 %0, t; }" : "=r"(a) : "l"(p));
    return a;
}
__device__ __forceinline__ void cp16(uint32_t dst, const void* src, int srcsz){
    asm volatile("cp.async.ca.shared.global [%0], [%1], 16, %2;"
        :: "r"(dst), "l"(src), "r"(srcsz) : "memory");
}
#define CP_COMMIT() asm volatile("cp.async.commit_group;" ::: "memory")
#define CP_WAIT0()  asm volatile("cp.async.wait_group 0;"  ::: "memory")

__device__ __forceinline__ void ldsm_x4(uint32_t* r, uint32_t a){
    asm volatile("ldmatrix.sync.aligned.m8n8.x4.shared.b16 {%0,%1,%2,%3}, [%4];"
        : "=r"(r[0]),"=r"(r[1]),"=r"(r[2]),"=r"(r[3]) : "r"(a));
}
__device__ __forceinline__ void ldsm_x4t(uint32_t* r, uint32_t a){
    asm volatile("ldmatrix.sync.aligned.m8n8.x4.trans.shared.b16 {%0,%1,%2,%3}, [%4];"
        : "=r"(r[0]),"=r"(r[1]),"=r"(r[2]),"=r"(r[3]) : "r"(a));
}
__device__ __forceinline__ void mma16816(float* c, const uint32_t* a, const uint32_t* b){
    asm volatile("mma.sync.aligned.m16n8k16.row.col.f32.f16.f16.f32 "
        "{%0,%1,%2,%3}, {%4,%5,%6,%7}, {%8,%9}, {%0,%1,%2,%3};"
        : "+f"(c[0]),"+f"(c[1]),"+f"(c[2]),"+f"(c[3])
        : "r"(a[0]),"r"(a[1]),"r"(a[2]),"r"(a[3]), "r"(b[0]),"r"(b[1]));
}

// ---------------- fused weight prep ----------------
__device__ __forceinline__ void prep_conv_one(const float* w, int idx,
        int BN, int Cin, int KC, int base, int permL1){
    int co = idx % BN; int r = idx / BN;
    int krow = r % 16; r /= 16;
    int kx = r % 3; r /= 3;
    int kc = r % KC; int ky = r / KC;
    int ci = kc*16 + krow;
    int tap = ky*3 + kx;
    float v = 0.f;
    if (ci < Cin){
        int srcci = permL1 ? (ci < 128 ? ci + 3 : ci - 128) : ci;
        v = w[(co*Cin + srcci)*9 + tap];
    }
    g_wp[base + (((ky*KC + kc)*3 + kx)*16 + krow)*BN + co] = __float2half(v);
}

__global__ void prep_all(const float* __restrict__ mw1, const float* __restrict__ mw2,
                         const float* __restrict__ mw3, const float* __restrict__ mw4,
                         const float* __restrict__ mw5, const float* __restrict__ mw6,
                         const float* __restrict__ fw,  const float* __restrict__ dw1){
    int idx = blockIdx.x*256 + threadIdx.x;
    if (idx < 8) g_mean[idx] = 0.f;    // zeroed before flow_mean (same stream)
    if (idx < 165888){ prep_conv_one(mw1, idx, 128, 131, 9, 0, 1); return; }
    idx -= 165888;
    if (idx < 147456){ prep_conv_one(mw2, idx, 128, 128, 8, 165888, 0); return; }
    idx -= 147456;
    if (idx < 73728){ prep_conv_one(mw3, idx, 64, 128, 8, 313344, 0); return; }
    idx -= 73728;
    if (idx < 36864){ prep_conv_one(mw4, idx, 64, 64, 4, 387072, 0); return; }
    idx -= 36864;
    if (idx < 18432){ prep_conv_one(mw5, idx, 32, 64, 4, 423936, 0); return; }
    idx -= 18432;
    if (idx < 9216){ prep_conv_one(mw6, idx, 32, 32, 2, 442368, 0); return; }
    idx -= 9216;
    if (idx < 64*128){
        int ci = idx >> 7, co = idx & 127;
        g_wpf[ci*128 + co] = __float2half(fw[co*64 + ci]);
        return;
    }
    idx -= 64*128;
    if (idx < 5*2*16*32){
        int co = idx & 31; int r = idx >> 5;
        int krow = r % 16; r /= 16;
        int kc = r & 1; int ky = r >> 1;
        int ci = kc*16 + krow;
        float v = (co < 25) ? dw1[(co*32 + ci)*5 + ky] : 0.f;
        g_wpd[idx] = __float2half(v);
    }
}
#define PREP_TOTAL (165888+147456+73728+36864+18432+9216+8192+5120)

// ---------------- flow mean: 64 blocks, atomic accumulation ----------------
__global__ void flow_mean_kernel(const float* __restrict__ flow){
    int bc = blockIdx.x >> 3;          // 0..7
    int chunk = blockIdx.x & 7;        // 0..7
    const float* p = flow + bc*HWSZ + chunk*(HWSZ/8);
    float s = 0.f;
    for (int i = threadIdx.x; i < HWSZ/8; i += 256) s += p[i];
    __shared__ float red[256];
    red[threadIdx.x] = s; __syncthreads();
    for (int o = 128; o > 0; o >>= 1){
        if (threadIdx.x < o) red[threadIdx.x] += red[threadIdx.x+o];
        __syncthreads();
    }
    if (threadIdx.x == 0) atomicAdd(&g_mean[bc], red[0] / (float)HWSZ);
}

// ---------------- backwarp diff + centered flow -> g_x ch 128..143 ----------------
__global__ void assemble_kernel(const float* __restrict__ t1,
                                const float* __restrict__ t2,
                                const float* __restrict__ flow){
    int idx = blockIdx.x*256 + threadIdx.x;
    if (idx >= BB*HWSZ) return;
    int b = idx / HWSZ, p = idx % HWSZ;
    int h = p / WW, w = p % WW;
    float f0 = flow[(b*2+0)*HWSZ + p];
    float f1 = flow[(b*2+1)*HWSZ + p];
    float x = (float)w + f0*5.0f;
    float y = (float)h + f1*5.0f;
    float x0f = floorf(x), y0f = floorf(y);
    int x0 = (int)x0f, y0 = (int)y0f;
    float wx1 = x - x0f, wy1 = y - y0f;
    float wx0 = 1.f - wx1, wy0 = 1.f - wy1;
    float d2 = 0.f;
    #pragma unroll
    for (int c = 0; c < 3; c++){
        const float* img = t2 + (b*3+c)*HWSZ;
        float v00 = (y0   >= 0 && y0   < HH && x0   >= 0 && x0   < WW) ? img[y0*WW + x0]       : 0.f;
        float v01 = (y0   >= 0 && y0   < HH && x0+1 >= 0 && x0+1 < WW) ? img[y0*WW + x0+1]     : 0.f;
        float v10 = (y0+1 >= 0 && y0+1 < HH && x0   >= 0 && x0   < WW) ? img[(y0+1)*WW + x0]   : 0.f;
        float v11 = (y0+1 >= 0 && y0+1 < HH && x0+1 >= 0 && x0+1 < WW) ? img[(y0+1)*WW + x0+1] : 0.f;
        float warp = v00*(wy0*wx0) + v01*(wy0*wx1) + v10*(wy1*wx0) + v11*(wy1*wx1);
        float dv = t1[(b*3+c)*HWSZ + p] - warp;
        d2 += dv*dv;
    }
    __half hv[16];
    hv[0] = __float2half(sqrtf(d2));
    hv[1] = __float2half(f0 - g_mean[b*2+0]);
    hv[2] = __float2half(f1 - g_mean[b*2+1]);
    #pragma unroll
    for (int i = 3; i < 16; i++) hv[i] = __float2half(0.f);
    uint4* dst = reinterpret_cast<uint4*>(g_x + ((size_t)idx)*144 + 128);
    const uint4* srcv = reinterpret_cast<const uint4*>(hv);
    dst[0] = srcv[0]; dst[1] = srcv[1];
}

// ---------------- feat: 1x1 conv 64->128 via mma, high occupancy ----------------
// CTA: 64 px, 256 threads, warps 4(m)x2(n); warp tile 16px x 64co.
// A staged [k][m] fp16 (stride 72), loaded with ldmatrix.trans.
__global__ void __launch_bounds__(256) feat_mma(const float* __restrict__ fin,
                                                const float* __restrict__ fb){
    __shared__ __align__(16) __half sA[64*72];    // [ci][px], stride 72
    __shared__ __align__(16) __half sB[64*136];   // [ci][co], stride 136

    int tid = threadIdx.x, wid = tid >> 5, lane = tid & 31;
    int b = blockIdx.z, y = blockIdx.y;
    int x0 = blockIdx.x * 64;
    int warp_m = wid & 3, warp_n = wid >> 2;
    int m_off = warp_m * 16, n_off = warp_n * 64;

    uint32_t sAu = smem_u32(sA), sBu = smem_u32(sB);
    // A trans lane mapping: matrix0=(m0-7,k0-7) <- rows k0-7 col m0; m1 <- col m8; m2 <- rows k8-15...
    int a_krow = (lane & 7) + ((lane >> 4) << 3);
    int a_mcol = m_off + (((lane >> 3) & 1) << 3);
    uint32_t aBase = sAu + (uint32_t)((a_krow*72 + a_mcol) * 2);
    uint32_t bBase = sBu + (uint32_t)(((lane & 15)*136 + n_off) * 2) + ((lane >> 4) << 4);

    float acc[8][4];
    #pragma unroll
    for (int nt = 0; nt < 8; nt++)
        #pragma unroll
        for (int r = 0; r < 4; r++) acc[nt][r] = 0.f;

    const float* fbase = fin + (size_t)b*64*HWSZ + (size_t)y*WW + x0;

    // stage A: 64 ch x 64 px, float4 loads -> half2 stores (contiguous per ci row)
    #pragma unroll
    for (int k = 0; k < 4; k++){
        int c = tid + k*256;            // 1024 float4 total
        int row = c >> 4, q = c & 15;
        float4 v = *reinterpret_cast<const float4*>(fbase + (size_t)row*HWSZ + q*4);
        __half2 h0 = __floats2half2_rn(v.x, v.y);
        __half2 h1 = __floats2half2_rn(v.z, v.w);
        uint32_t dst = sAu + (uint32_t)((row*72 + q*4) * 2);
        asm volatile("st.shared.v2.b32 [%0], {%1, %2};"
            :: "r"(dst), "r"(*(uint32_t*)&h0), "r"(*(uint32_t*)&h1) : "memory");
    }
    // stage B: 64 x 128
    #pragma unroll
    for (int k = 0; k < 4; k++){
        int c = tid + k*256;            // 1024 uint4 total
        int r = c >> 4, cu = c & 15;
        *reinterpret_cast<uint4*>(sB + r*136 + cu*8) =
            *reinterpret_cast<const uint4*>(g_wpf + r*128 + cu*8);
    }
    __syncthreads();

    #pragma unroll
    for (int kci = 0; kci < 4; kci++){
        uint32_t afr[4];
        ldsm_x4t(afr, aBase + (uint32_t)(kci*16*72*2));
        uint32_t bfr[8][2];
        #pragma unroll
        for (int np = 0; np < 4; np++){
            uint32_t r4[4];
            ldsm_x4t(r4, bBase + (uint32_t)(kci*16*136*2 + np*16*2));
            bfr[2*np][0] = r4[0]; bfr[2*np][1] = r4[1];
            bfr[2*np+1][0] = r4[2]; bfr[2*np+1][1] = r4[3];
        }
        #pragma unroll
        for (int nt = 0; nt < 8; nt++)
            mma16816(acc[nt], afr, bfr[nt]);
    }

    int row = lane >> 2, col = (lane & 3)*2;
    __half* obase = g_x + ((size_t)(b*HH + y)*WW + x0)*144;
    int m0 = m_off + row;
    #pragma unroll
    for (int nt = 0; nt < 8; nt++){
        int n0 = n_off + nt*8 + col;
        float bv0 = fb[n0], bv1 = fb[n0+1];
        __half2 v0 = __halves2half2(__float2half(lrelu(acc[nt][0] + bv0)),
                                    __float2half(lrelu(acc[nt][1] + bv1)));
        __half2 v1 = __halves2half2(__float2half(lrelu(acc[nt][2] + bv0)),
                                    __float2half(lrelu(acc[nt][3] + bv1)));
        *reinterpret_cast<__half2*>(obase + (size_t)m0*144 + n0)     = v0;
        *reinterpret_cast<__half2*>(obase + (size_t)(m0+8)*144 + n0) = v1;
    }
}

// ---------------- NHWC implicit-GEMM 3x3 conv, M=224, 448 threads ----------------
template<int BN>
__global__ void __launch_bounds__(448) conv3x3_nhwc(
        const __half* __restrict__ act, int CX, int KC,
        const float* __restrict__ bias, __half* __restrict__ out, int wp_base){
    constexpr int NT  = BN/16;
    constexpr int SBS = BN + 8;
    constexpr int ABUF = 226*48;
    constexpr int BBUF = 48*SBS*2;
    __shared__ __align__(16) __half sA[2*226*24];
    __shared__ __align__(16) __half sB[2*48*SBS];

    int tid = threadIdx.x, wid = tid >> 5, lane = tid & 31;
    int b = blockIdx.z, y = blockIdx.y;
    int x0 = blockIdx.x * 224;
    int warp_m = wid % 7, warp_n = wid / 7;
    int m_off = warp_m * 32, n_off = warp_n * (BN/2);

    uint32_t sAu = smem_u32(sA), sBu = smem_u32(sB);

    int gylist[3]; int nky = 0;
    #pragma unroll
    for (int ky = 0; ky < 3; ky++){
        int gy = y + ky - 1;
        if (gy >= 0 && gy < HH){ gylist[nky] = (ky << 16) | gy; nky++; }
    }
    int N = nky * KC;

    float acc[2][NT][4];
    #pragma unroll
    for (int mt = 0; mt < 2; mt++)
        #pragma unroll
        for (int nt = 0; nt < NT; nt++)
            #pragma unroll
            for (int r = 0; r < 4; r++) acc[mt][nt][r] = 0.f;

    const size_t brow = (size_t)b * HH;

    auto stage = [&](int it){
        int buf = it & 1;
        int kykey = gylist[it / KC];
        int ky = kykey >> 16, gy = kykey & 0xffff;
        int kc = it % KC;
        const __half* arowb = act + ((brow + gy)*WW)*CX + kc*16;
        uint32_t adst = sAu + buf*ABUF;
        for (int c = tid; c < 452; c += 448){
            int r = c >> 1, hf = c & 1;
            int gx = x0 - 1 + r;
            int ok = (gx >= 0 && gx < WW) ? 16 : 0;
            int gxc = gx < 0 ? 0 : (gx >= WW ? WW-1 : gx);
            cp16(adst + r*48 + hf*16, arowb + (size_t)gxc*CX + hf*8, ok);
        }
        const __half* wsrc = g_wp + wp_base + (size_t)((ky*KC + kc)*48) * BN;
        uint32_t bdst = sBu + buf*BBUF;
        constexpr int CPR = BN/8;
        for (int c = tid; c < 48*CPR; c += 448){
            int r = c / CPR, cu = c % CPR;
            cp16(bdst + (r*SBS + cu*8)*2, wsrc + (size_t)r*BN + cu*8, 16);
        }
        CP_COMMIT();
    };

    stage(0);
    for (int it = 0; it < N; it++){
        CP_WAIT0();
        __syncthreads();
        if (it + 1 < N) stage(it+1);
        int buf = it & 1;
        uint32_t aBase = sAu + buf*ABUF + ((lane & 15)*48) + ((lane >> 4)*16);
        uint32_t bBase = sBu + buf*BBUF + ((lane & 15)*SBS + n_off)*2 + ((lane >> 4)*16);
        #pragma unroll
        for (int kx = 0; kx < 3; kx++){
            uint32_t afr[2][4];
            ldsm_x4(afr[0], aBase + (m_off + kx)*48);
            ldsm_x4(afr[1], aBase + (m_off + kx + 16)*48);
            uint32_t bfr[NT][2];
            #pragma unroll
            for (int np = 0; np < NT/2; np++){
                uint32_t r4[4];
                ldsm_x4t(r4, bBase + (kx*16)*SBS*2 + np*16*2);
                bfr[2*np][0] = r4[0]; bfr[2*np][1] = r4[1];
                bfr[2*np+1][0] = r4[2]; bfr[2*np+1][1] = r4[3];
            }
            #pragma unroll
            for (int mt = 0; mt < 2; mt++)
                #pragma unroll
                for (int nt = 0; nt < NT; nt++)
                    mma16816(acc[mt][nt], afr[mt], bfr[nt]);
        }
    }

    int row = lane >> 2, col = (lane & 3)*2;
    __half* obase = out + ((brow + y)*WW + x0) * BN;
    #pragma unroll
    for (int mt = 0; mt < 2; mt++){
        int m0 = m_off + mt*16 + row;
        #pragma unroll
        for (int nt = 0; nt < NT; nt++){
            int n0 = n_off + nt*8 + col;
            float bv0 = bias[n0], bv1 = bias[n0+1];
            __half2 v0 = __halves2half2(__float2half(lrelu(acc[mt][nt][0] + bv0)),
                                        __float2half(lrelu(acc[mt][nt][1] + bv1)));
            __half2 v1 = __halves2half2(__float2half(lrelu(acc[mt][nt][2] + bv0)),
                                        __float2half(lrelu(acc[mt][nt][3] + bv1)));
            *reinterpret_cast<__half2*>(obase + (size_t)m0*BN + n0)       = v0;
            *reinterpret_cast<__half2*>(obase + (size_t)(m0+8)*BN + n0)   = v1;
        }
    }
}

// ---------------- dist1: 5x1 conv 32->25(pad32) via mma -> g_d1 NHWC fp32 ----------------
__global__ void __launch_bounds__(448) dist1_mma(const __half* __restrict__ act,
                                                 const float* __restrict__ b1){
    constexpr int SBS = 40;
    constexpr int ABUF = 224*48;
    constexpr int BBUF = 16*SBS*2;
    __shared__ __align__(16) __half sA[2*224*24];
    __shared__ __align__(16) __half sB[2*16*SBS];

    int tid = threadIdx.x, wid = tid >> 5, lane = tid & 31;
    int b = blockIdx.z, y = blockIdx.y;
    int x0 = blockIdx.x * 224;
    int warp_m = wid % 7, warp_n = wid / 7;
    int m_off = warp_m * 32, n_off = warp_n * 16;

    uint32_t sAu = smem_u32(sA), sBu = smem_u32(sB);

    int gylist[5]; int nky = 0;
    #pragma unroll
    for (int ky = 0; ky < 5; ky++){
        int gy = y + ky - 2;
        if (gy >= 0 && gy < HH){ gylist[nky] = (ky << 16) | gy; nky++; }
    }
    int N = nky * 2;

    float acc[2][2][4];
    #pragma unroll
    for (int mt = 0; mt < 2; mt++)
        #pragma unroll
        for (int nt = 0; nt < 2; nt++)
            #pragma unroll
            for (int r = 0; r < 4; r++) acc[mt][nt][r] = 0.f;

    const size_t brow = (size_t)b * HH;

    auto stage = [&](int it){
        int buf = it & 1;
        int kykey = gylist[it >> 1];
        int ky = kykey >> 16, gy = kykey & 0xffff;
        int kc = it & 1;
        const __half* arowb = act + ((brow + gy)*WW + x0)*32 + kc*16;
        uint32_t adst = sAu + buf*ABUF;
        {
            int c = tid;
            int r = c >> 1, hf = c & 1;
            cp16(adst + r*48 + hf*16, arowb + (size_t)r*32 + hf*8, 16);
        }
        const __half* wsrc = g_wpd + ((ky*2 + kc)*16) * 32;
        uint32_t bdst = sBu + buf*BBUF;
        if (tid < 64){
            int r = tid >> 2, cu = tid & 3;
            cp16(bdst + (r*SBS + cu*8)*2, wsrc + r*32 + cu*8, 16);
        }
        CP_COMMIT();
    };

    stage(0);
    for (int it = 0; it < N; it++){
        CP_WAIT0();
        __syncthreads();
        if (it + 1 < N) stage(it+1);
        int buf = it & 1;
        uint32_t aBase = sAu + buf*ABUF + ((lane & 15)*48) + ((lane >> 4)*16);
        uint32_t bBase = sBu + buf*BBUF + ((lane & 15)*SBS + n_off)*2 + ((lane >> 4)*16);
        uint32_t afr[2][4];
        ldsm_x4(afr[0], aBase + m_off*48);
        ldsm_x4(afr[1], aBase + (m_off + 16)*48);
        uint32_t r4[4];
        ldsm_x4t(r4, bBase);
        uint32_t bfr[2][2];
        bfr[0][0] = r4[0]; bfr[0][1] = r4[1];
        bfr[1][0] = r4[2]; bfr[1][1] = r4[3];
        #pragma unroll
        for (int mt = 0; mt < 2; mt++)
            #pragma unroll
            for (int nt = 0; nt < 2; nt++)
                mma16816(acc[mt][nt], afr[mt], bfr[nt]);
    }

    int row = lane >> 2, col = (lane & 3)*2;
    float* obase = g_d1 + ((brow + y)*WW + x0) * 32;
    #pragma unroll
    for (int mt = 0; mt < 2; mt++){
        int m0 = m_off + mt*16 + row;
        #pragma unroll
        for (int nt = 0; nt < 2; nt++){
            int n0 = n_off + nt*8 + col;
            float bv0 = (n0   < 25) ? b1[n0]   : 0.f;
            float bv1 = (n0+1 < 25) ? b1[n0+1] : 0.f;
            float2 v0 = make_float2(acc[mt][nt][0] + bv0, acc[mt][nt][1] + bv1);
            float2 v1 = make_float2(acc[mt][nt][2] + bv0, acc[mt][nt][3] + bv1);
            *reinterpret_cast<float2*>(obase + (size_t)m0*32 + n0)     = v0;
            *reinterpret_cast<float2*>(obase + (size_t)(m0+8)*32 + n0) = v1;
        }
    }
}

// ---------------- dist2 (1x5) + softmax + unfold-weighted flow avg ----------------
__global__ void __launch_bounds__(224) final_kernel(
        const float* __restrict__ w2, const float* __restrict__ b2,
        const float* __restrict__ flow,
        const float* __restrict__ sxw, const float* __restrict__ sxb,
        const float* __restrict__ syw, const float* __restrict__ syb,
        float* __restrict__ out){
    int blk  = blockIdx.x;
    int half = blk & 1;
    int bh   = blk >> 1;
    int b = bh / HH, h = bh % HH;
    int x0 = half * 224;

    __shared__ float sd[25][228];
    __shared__ float sw2[25*25*5];
    // coalesced NHWC load: each thread reads one pixel's 28 contiguous channels
    for (int t = threadIdx.x; t < 228; t += 224){
        int gx = x0 + t - 2;
        if (gx >= 0 && gx < WW){
            const float4* src = reinterpret_cast<const float4*>(
                g_d1 + ((size_t)(b*HH + h)*WW + gx)*32);
            #pragma unroll
            for (int q = 0; q < 7; q++){
                float4 v = src[q];
                int c0 = q*4;
                if (c0     < 25) sd[c0][t]   = v.x;
                if (c0 + 1 < 25) sd[c0+1][t] = v.y;
                if (c0 + 2 < 25) sd[c0+2][t] = v.z;
                if (c0 + 3 < 25) sd[c0+3][t] = v.w;
            }
        } else {
            #pragma unroll
            for (int ci = 0; ci < 25; ci++) sd[ci][t] = 0.f;
        }
    }
    for (int i = threadIdx.x; i < 25*25*5; i += 224) sw2[i] = w2[i];
    __syncthreads();

    int lx = threadIdx.x;
    int x  = x0 + lx;
    float acc[25];
    #pragma unroll
    for (int co = 0; co < 25; co++) acc[co] = 0.f;
    for (int ci = 0; ci < 25; ci++){
        #pragma unroll
        for (int kw = 0; kw < 5; kw++){
            float v = sd[ci][lx + kw];
            #pragma unroll
            for (int co = 0; co < 25; co++)
                acc[co] = fmaf(v, sw2[(co*25+ci)*5 + kw], acc[co]);
        }
    }
    float m = -1e30f;
    #pragma unroll
    for (int co = 0; co < 25; co++){
        float d = acc[co] + b2[co];
        d = -(d*d);
        acc[co] = d;
        m = fmaxf(m, d);
    }
    float s = 0.f;
    #pragma unroll
    for (int co = 0; co < 25; co++){ acc[co] = expf(acc[co] - m); s += acc[co]; }
    float dv = 1.f / s;

    const float* f0 = flow + (b*2+0)*HWSZ;
    const float* f1 = flow + (b*2+1)*HWSZ;
    float sx = sxb[0], sy = syb[0];
    #pragma unroll
    for (int k = 0; k < 25; k++){
        int kh = k / 5, kw = k % 5;
        int gy = h + kh - 2, gx = x + kw - 2;
        float u1 = 0.f, u2 = 0.f;
        if (gy >= 0 && gy < HH && gx >= 0 && gx < WW){
            u1 = f0[gy*WW + gx];
            u2 = f1[gy*WW + gx];
        }
        sx = fmaf(sxw[k], acc[k]*u1, sx);
        sy = fmaf(syw[k], acc[k]*u2, sy);
    }
    out[(b*2+0)*HWSZ + h*WW + x] = sx * dv;
    out[(b*2+1)*HWSZ + h*WW + x] = sy * dv;
}

extern "C" void kernel_launch(void* const* d_in, const int* in_sizes, int n_in,
                              void* d_out, int out_size){
    const float* t1     = (const float*)d_in[0];
    const float* t2     = (const float*)d_in[1];
    const float* ft1    = (const float*)d_in[2];
    const float* flow   = (const float*)d_in[4];
    const float* feat_w = (const float*)d_in[5];
    const float* feat_b = (const float*)d_in[6];
    const float* mw1 = (const float*)d_in[7];  const float* mb1 = (const float*)d_in[8];
    const float* mw2 = (const float*)d_in[9];  const float* mb2 = (const float*)d_in[10];
    const float* mw3 = (const float*)d_in[11]; const float* mb3 = (const float*)d_in[12];
    const float* mw4 = (const float*)d_in[13]; const float* mb4 = (const float*)d_in[14];
    const float* mw5 = (const float*)d_in[15]; const float* mb5 = (const float*)d_in[16];
    const float* mw6 = (const float*)d_in[17]; const float* mb6 = (const float*)d_in[18];
    const float* dw1 = (const float*)d_in[19]; const float* db1 = (const float*)d_in[20];
    const float* dw2 = (const float*)d_in[21]; const float* db2 = (const float*)d_in[22];
    const float* sxw = (const float*)d_in[23]; const float* sxb = (const float*)d_in[24];
    const float* syw = (const float*)d_in[25]; const float* syb = (const float*)d_in[26];
    float* out = (float*)d_out;

    __half *px = nullptr, *pa = nullptr, *pb = nullptr;
    cudaGetSymbolAddress((void**)&px, g_x);
    cudaGetSymbolAddress((void**)&pa, g_a);
    cudaGetSymbolAddress((void**)&pb, g_b);

    prep_all<<<(PREP_TOTAL + 255)/256, 256>>>(mw1, mw2, mw3, mw4, mw5, mw6, feat_w, dw1);
    flow_mean_kernel<<<64, 256>>>(flow);
    assemble_kernel<<<(BB*HWSZ + 255)/256, 256>>>(t1, t2, flow);

    dim3 fgrid(7, HH, BB);
    feat_mma<<<fgrid, 256>>>(ft1, feat_b);

    dim3 cgrid(2, HH, BB);
    conv3x3_nhwc<128><<<cgrid, 448>>>(px, 144, 9, mb1, pa, 0);
    conv3x3_nhwc<128><<<cgrid, 448>>>(pa, 128, 8, mb2, pb, 165888);
    conv3x3_nhwc< 64><<<cgrid, 448>>>(pb, 128, 8, mb3, pa, 313344);
    conv3x3_nhwc< 64><<<cgrid, 448>>>(pa,  64, 4, mb4, pb, 387072);
    conv3x3_nhwc< 32><<<cgrid, 448>>>(pb,  64, 4, mb5, pa, 423936);
    conv3x3_nhwc< 32><<<cgrid, 448>>>(pa,  32, 2, mb6, pb, 442368);

    dist1_mma<<<cgrid, 448>>>(pb, db1);
    final_kernel<<<BB*HH*2, 224>>>(dw2, db2, flow, sxw, sxb, syw, syb, out);
}

// round 10
// speedup vs baseline: 12.1792x; 1.0169x over previous
#include <cuda_runtime.h>
#include <cuda_fp16.h>
#include <math.h>
#include <stdint.h>

#define HH 192
#define WW 448
#define HWSZ (HH*WW)
#define BB 4

// ---------------- scratch (__device__ globals; no allocation) ----------------
__device__ __half g_x[BB*HWSZ*144];
__device__ __half g_a[BB*HWSZ*128];   // ping
__device__ __half g_b[BB*HWSZ*128];   // pong
__device__ float  g_d1[BB*HWSZ*32];   // dist after 5x1 conv (NHWC fp32, ch 0..24 valid)
__device__ float  g_fpart[64];        // flow mean partials [bc][chunk]
#define WP_TOTAL 460800
__device__ __align__(16) __half g_wp[WP_TOTAL];
__device__ __align__(16) __half g_wpf[64*128];       // feat 1x1 weights [ci][co]
__device__ __align__(16) __half g_wpd[5*2*16*32];    // dist1 weights [ky][kc][krow][co32]

__device__ __forceinline__ float lrelu(float v){ return v >= 0.f ? v : 0.1f*v; }

__device__ __forceinline__ uint32_t smem_u32(const void* p){
    uint32_t a;
    asm("{ .reg .u64 t; cvta.to.shared.u64 t, %1; cvt.u32.u64 %0, t; }" : "=r"(a) : "l"(p));
    return a;
}
__device__ __forceinline__ void cp16(uint32_t dst, const void* src, int srcsz){
    asm volatile("cp.async.ca.shared.global [%0], [%1], 16, %2;"
        :: "r"(dst), "l"(src), "r"(srcsz) : "memory");
}
#define CP_COMMIT() asm volatile("cp.async.commit_group;" ::: "memory")
#define CP_WAIT0()  asm volatile("cp.async.wait_group 0;"  ::: "memory")

__device__ __forceinline__ void ldsm_x4(uint32_t* r, uint32_t a){
    asm volatile("ldmatrix.sync.aligned.m8n8.x4.shared.b16 {%0,%1,%2,%3}, [%4];"
        : "=r"(r[0]),"=r"(r[1]),"=r"(r[2]),"=r"(r[3]) : "r"(a));
}
__device__ __forceinline__ void ldsm_x4t(uint32_t* r, uint32_t a){
    asm volatile("ldmatrix.sync.aligned.m8n8.x4.trans.shared.b16 {%0,%1,%2,%3}, [%4];"
        : "=r"(r[0]),"=r"(r[1]),"=r"(r[2]),"=r"(r[3]) : "r"(a));
}
__device__ __forceinline__ void mma16816(float* c, const uint32_t* a, const uint32_t* b){
    asm volatile("mma.sync.aligned.m16n8k16.row.col.f32.f16.f16.f32 "
        "{%0,%1,%2,%3}, {%4,%5,%6,%7}, {%8,%9}, {%0,%1,%2,%3};"
        : "+f"(c[0]),"+f"(c[1]),"+f"(c[2]),"+f"(c[3])
        : "r"(a[0]),"r"(a[1]),"r"(a[2]),"r"(a[3]), "r"(b[0]),"r"(b[1]));
}

// ---------------- fused weight prep + flow-mean partials ----------------
__device__ __forceinline__ void prep_conv_one(const float* w, int idx,
        int BN, int Cin, int KC, int base, int permL1){
    int co = idx % BN; int r = idx / BN;
    int krow = r % 16; r /= 16;
    int kx = r % 3; r /= 3;
    int kc = r % KC; int ky = r / KC;
    int ci = kc*16 + krow;
    int tap = ky*3 + kx;
    float v = 0.f;
    if (ci < Cin){
        int srcci = permL1 ? (ci < 128 ? ci + 3 : ci - 128) : ci;
        v = w[(co*Cin + srcci)*9 + tap];
    }
    g_wp[base + (((ky*KC + kc)*3 + kx)*16 + krow)*BN + co] = __float2half(v);
}

#define PREP_TOTAL (165888+147456+73728+36864+18432+9216+8192+5120)
#define PREP_BLOCKS ((PREP_TOTAL + 255)/256)

__global__ void prep_all(const float* __restrict__ mw1, const float* __restrict__ mw2,
                         const float* __restrict__ mw3, const float* __restrict__ mw4,
                         const float* __restrict__ mw5, const float* __restrict__ mw6,
                         const float* __restrict__ fw,  const float* __restrict__ dw1,
                         const float* __restrict__ flow){
    __shared__ float red[256];
    if (blockIdx.x >= PREP_BLOCKS){
        // flow-mean partials: 64 blocks, one (bc, chunk) each
        int fb = blockIdx.x - PREP_BLOCKS;
        int bc = fb >> 3, chunk = fb & 7;
        const float* p = flow + bc*HWSZ + chunk*(HWSZ/8);
        float s = 0.f;
        for (int i = threadIdx.x; i < HWSZ/8; i += 256) s += p[i];
        red[threadIdx.x] = s; __syncthreads();
        for (int o = 128; o > 0; o >>= 1){
            if (threadIdx.x < o) red[threadIdx.x] += red[threadIdx.x+o];
            __syncthreads();
        }
        if (threadIdx.x == 0) g_fpart[fb] = red[0] / (float)HWSZ;
        return;
    }
    int idx = blockIdx.x*256 + threadIdx.x;
    if (idx < 165888){ prep_conv_one(mw1, idx, 128, 131, 9, 0, 1); return; }
    idx -= 165888;
    if (idx < 147456){ prep_conv_one(mw2, idx, 128, 128, 8, 165888, 0); return; }
    idx -= 147456;
    if (idx < 73728){ prep_conv_one(mw3, idx, 64, 128, 8, 313344, 0); return; }
    idx -= 73728;
    if (idx < 36864){ prep_conv_one(mw4, idx, 64, 64, 4, 387072, 0); return; }
    idx -= 36864;
    if (idx < 18432){ prep_conv_one(mw5, idx, 32, 64, 4, 423936, 0); return; }
    idx -= 18432;
    if (idx < 9216){ prep_conv_one(mw6, idx, 32, 32, 2, 442368, 0); return; }
    idx -= 9216;
    if (idx < 64*128){
        int ci = idx >> 7, co = idx & 127;
        g_wpf[ci*128 + co] = __float2half(fw[co*64 + ci]);
        return;
    }
    idx -= 64*128;
    if (idx < 5*2*16*32){
        int co = idx & 31; int r = idx >> 5;
        int krow = r % 16; r /= 16;
        int kc = r & 1; int ky = r >> 1;
        int ci = kc*16 + krow;
        float v = (co < 25) ? dw1[(co*32 + ci)*5 + ky] : 0.f;
        g_wpd[idx] = __float2half(v);
    }
}

// ---------------- backwarp diff + centered flow -> g_x ch 128..143 ----------------
__global__ void assemble_kernel(const float* __restrict__ t1,
                                const float* __restrict__ t2,
                                const float* __restrict__ flow){
    int idx = blockIdx.x*256 + threadIdx.x;
    if (idx >= BB*HWSZ) return;
    int b = idx / HWSZ, p = idx % HWSZ;
    int h = p / WW, w = p % WW;
    float mean0 = 0.f, mean1 = 0.f;
    #pragma unroll
    for (int i = 0; i < 8; i++){
        mean0 += g_fpart[(b*2+0)*8 + i];
        mean1 += g_fpart[(b*2+1)*8 + i];
    }
    float f0 = flow[(b*2+0)*HWSZ + p];
    float f1 = flow[(b*2+1)*HWSZ + p];
    float x = (float)w + f0*5.0f;
    float y = (float)h + f1*5.0f;
    float x0f = floorf(x), y0f = floorf(y);
    int x0 = (int)x0f, y0 = (int)y0f;
    float wx1 = x - x0f, wy1 = y - y0f;
    float wx0 = 1.f - wx1, wy0 = 1.f - wy1;
    float d2 = 0.f;
    #pragma unroll
    for (int c = 0; c < 3; c++){
        const float* img = t2 + (b*3+c)*HWSZ;
        float v00 = (y0   >= 0 && y0   < HH && x0   >= 0 && x0   < WW) ? img[y0*WW + x0]       : 0.f;
        float v01 = (y0   >= 0 && y0   < HH && x0+1 >= 0 && x0+1 < WW) ? img[y0*WW + x0+1]     : 0.f;
        float v10 = (y0+1 >= 0 && y0+1 < HH && x0   >= 0 && x0   < WW) ? img[(y0+1)*WW + x0]   : 0.f;
        float v11 = (y0+1 >= 0 && y0+1 < HH && x0+1 >= 0 && x0+1 < WW) ? img[(y0+1)*WW + x0+1] : 0.f;
        float warp = v00*(wy0*wx0) + v01*(wy0*wx1) + v10*(wy1*wx0) + v11*(wy1*wx1);
        float dv = t1[(b*3+c)*HWSZ + p] - warp;
        d2 += dv*dv;
    }
    __half hv[16];
    hv[0] = __float2half(sqrtf(d2));
    hv[1] = __float2half(f0 - mean0);
    hv[2] = __float2half(f1 - mean1);
    #pragma unroll
    for (int i = 3; i < 16; i++) hv[i] = __float2half(0.f);
    uint4* dst = reinterpret_cast<uint4*>(g_x + ((size_t)idx)*144 + 128);
    const uint4* srcv = reinterpret_cast<const uint4*>(hv);
    dst[0] = srcv[0]; dst[1] = srcv[1];
}

// ---------------- feat: 1x1 conv 64->128 via mma, high occupancy ----------------
__global__ void __launch_bounds__(256) feat_mma(const float* __restrict__ fin,
                                                const float* __restrict__ fb){
    __shared__ __align__(16) __half sA[64*72];    // [ci][px], stride 72
    __shared__ __align__(16) __half sB[64*136];   // [ci][co], stride 136

    int tid = threadIdx.x, wid = tid >> 5, lane = tid & 31;
    int b = blockIdx.z, y = blockIdx.y;
    int x0 = blockIdx.x * 64;
    int warp_m = wid & 3, warp_n = wid >> 2;
    int m_off = warp_m * 16, n_off = warp_n * 64;

    uint32_t sAu = smem_u32(sA), sBu = smem_u32(sB);
    int a_krow = (lane & 7) + ((lane >> 4) << 3);
    int a_mcol = m_off + (((lane >> 3) & 1) << 3);
    uint32_t aBase = sAu + (uint32_t)((a_krow*72 + a_mcol) * 2);
    uint32_t bBase = sBu + (uint32_t)(((lane & 15)*136 + n_off) * 2) + ((lane >> 4) << 4);

    float acc[8][4];
    #pragma unroll
    for (int nt = 0; nt < 8; nt++)
        #pragma unroll
        for (int r = 0; r < 4; r++) acc[nt][r] = 0.f;

    const float* fbase = fin + (size_t)b*64*HWSZ + (size_t)y*WW + x0;

    #pragma unroll
    for (int k = 0; k < 4; k++){
        int c = tid + k*256;
        int row = c >> 4, q = c & 15;
        float4 v = *reinterpret_cast<const float4*>(fbase + (size_t)row*HWSZ + q*4);
        __half2 h0 = __floats2half2_rn(v.x, v.y);
        __half2 h1 = __floats2half2_rn(v.z, v.w);
        uint32_t dst = sAu + (uint32_t)((row*72 + q*4) * 2);
        asm volatile("st.shared.v2.b32 [%0], {%1, %2};"
            :: "r"(dst), "r"(*(uint32_t*)&h0), "r"(*(uint32_t*)&h1) : "memory");
    }
    #pragma unroll
    for (int k = 0; k < 4; k++){
        int c = tid + k*256;
        int r = c >> 4, cu = c & 15;
        *reinterpret_cast<uint4*>(sB + r*136 + cu*8) =
            *reinterpret_cast<const uint4*>(g_wpf + r*128 + cu*8);
    }
    __syncthreads();

    #pragma unroll
    for (int kci = 0; kci < 4; kci++){
        uint32_t afr[4];
        ldsm_x4t(afr, aBase + (uint32_t)(kci*16*72*2));
        uint32_t bfr[8][2];
        #pragma unroll
        for (int np = 0; np < 4; np++){
            uint32_t r4[4];
            ldsm_x4t(r4, bBase + (uint32_t)(kci*16*136*2 + np*16*2));
            bfr[2*np][0] = r4[0]; bfr[2*np][1] = r4[1];
            bfr[2*np+1][0] = r4[2]; bfr[2*np+1][1] = r4[3];
        }
        #pragma unroll
        for (int nt = 0; nt < 8; nt++)
            mma16816(acc[nt], afr, bfr[nt]);
    }

    int row = lane >> 2, col = (lane & 3)*2;
    __half* obase = g_x + ((size_t)(b*HH + y)*WW + x0)*144;
    int m0 = m_off + row;
    #pragma unroll
    for (int nt = 0; nt < 8; nt++){
        int n0 = n_off + nt*8 + col;
        float bv0 = fb[n0], bv1 = fb[n0+1];
        __half2 v0 = __halves2half2(__float2half(lrelu(acc[nt][0] + bv0)),
                                    __float2half(lrelu(acc[nt][1] + bv1)));
        __half2 v1 = __halves2half2(__float2half(lrelu(acc[nt][2] + bv0)),
                                    __float2half(lrelu(acc[nt][3] + bv1)));
        *reinterpret_cast<__half2*>(obase + (size_t)m0*144 + n0)     = v0;
        *reinterpret_cast<__half2*>(obase + (size_t)(m0+8)*144 + n0) = v1;
    }
}

// ---------------- NHWC implicit-GEMM 3x3 conv: M=128, 256 threads, 2 CTAs/SM ----------------
template<int BN>
__global__ void __launch_bounds__(256, 2) conv3x3_nhwc(
        const __half* __restrict__ act, int CX, int KC,
        const float* __restrict__ bias, __half* __restrict__ out, int wp_base){
    constexpr int NT  = BN/16;
    constexpr int SBS = BN + 8;
    constexpr int ABUF = 130*48;        // bytes per A buffer (row stride 48B)
    constexpr int BBUF = 48*SBS*2;
    __shared__ __align__(16) __half sA[2*130*24];
    __shared__ __align__(16) __half sB[2*48*SBS];

    int tid = threadIdx.x, wid = tid >> 5, lane = tid & 31;
    int b = blockIdx.z, y = blockIdx.y;
    int x0 = blockIdx.x * 128; if (x0 > WW-128) x0 = WW-128;   // 0,128,256,320 (overlap OK)
    int warp_m = wid & 3, warp_n = wid >> 2;
    int m_off = warp_m * 32, n_off = warp_n * (BN/2);

    uint32_t sAu = smem_u32(sA), sBu = smem_u32(sB);

    int gylist[3]; int nky = 0;
    #pragma unroll
    for (int ky = 0; ky < 3; ky++){
        int gy = y + ky - 1;
        if (gy >= 0 && gy < HH){ gylist[nky] = (ky << 16) | gy; nky++; }
    }
    int N = nky * KC;

    float acc[2][NT][4];
    #pragma unroll
    for (int mt = 0; mt < 2; mt++)
        #pragma unroll
        for (int nt = 0; nt < NT; nt++)
            #pragma unroll
            for (int r = 0; r < 4; r++) acc[mt][nt][r] = 0.f;

    const size_t brow = (size_t)b * HH;

    auto stage = [&](int it){
        int buf = it & 1;
        int kykey = gylist[it / KC];
        int ky = kykey >> 16, gy = kykey & 0xffff;
        int kc = it % KC;
        const __half* arowb = act + ((brow + gy)*WW)*CX + kc*16;
        uint32_t adst = sAu + buf*ABUF;
        for (int c = tid; c < 260; c += 256){
            int r = c >> 1, hf = c & 1;
            int gx = x0 - 1 + r;
            int ok = (gx >= 0 && gx < WW) ? 16 : 0;
            int gxc = gx < 0 ? 0 : (gx >= WW ? WW-1 : gx);
            cp16(adst + r*48 + hf*16, arowb + (size_t)gxc*CX + hf*8, ok);
        }
        const __half* wsrc = g_wp + wp_base + (size_t)((ky*KC + kc)*48) * BN;
        uint32_t bdst = sBu + buf*BBUF;
        constexpr int CPR = BN/8;
        for (int c = tid; c < 48*CPR; c += 256){
            int r = c / CPR, cu = c % CPR;
            cp16(bdst + (r*SBS + cu*8)*2, wsrc + (size_t)r*BN + cu*8, 16);
        }
        CP_COMMIT();
    };

    stage(0);
    for (int it = 0; it < N; it++){
        CP_WAIT0();
        __syncthreads();
        if (it + 1 < N) stage(it+1);
        int buf = it & 1;
        uint32_t aBase = sAu + buf*ABUF + ((lane & 15)*48) + ((lane >> 4)*16);
        uint32_t bBase = sBu + buf*BBUF + ((lane & 15)*SBS + n_off)*2 + ((lane >> 4)*16);
        #pragma unroll
        for (int kx = 0; kx < 3; kx++){
            uint32_t afr[2][4];
            ldsm_x4(afr[0], aBase + (m_off + kx)*48);
            ldsm_x4(afr[1], aBase + (m_off + kx + 16)*48);
            uint32_t bfr[NT][2];
            #pragma unroll
            for (int np = 0; np < NT/2; np++){
                uint32_t r4[4];
                ldsm_x4t(r4, bBase + (kx*16)*SBS*2 + np*16*2);
                bfr[2*np][0] = r4[0]; bfr[2*np][1] = r4[1];
                bfr[2*np+1][0] = r4[2]; bfr[2*np+1][1] = r4[3];
            }
            #pragma unroll
            for (int mt = 0; mt < 2; mt++)
                #pragma unroll
                for (int nt = 0; nt < NT; nt++)
                    mma16816(acc[mt][nt], afr[mt], bfr[nt]);
        }
    }

    int row = lane >> 2, col = (lane & 3)*2;
    __half* obase = out + ((brow + y)*WW + x0) * BN;
    #pragma unroll
    for (int mt = 0; mt < 2; mt++){
        int m0 = m_off + mt*16 + row;
        #pragma unroll
        for (int nt = 0; nt < NT; nt++){
            int n0 = n_off + nt*8 + col;
            float bv0 = bias[n0], bv1 = bias[n0+1];
            __half2 v0 = __halves2half2(__float2half(lrelu(acc[mt][nt][0] + bv0)),
                                        __float2half(lrelu(acc[mt][nt][1] + bv1)));
            __half2 v1 = __halves2half2(__float2half(lrelu(acc[mt][nt][2] + bv0)),
                                        __float2half(lrelu(acc[mt][nt][3] + bv1)));
            *reinterpret_cast<__half2*>(obase + (size_t)m0*BN + n0)       = v0;
            *reinterpret_cast<__half2*>(obase + (size_t)(m0+8)*BN + n0)   = v1;
        }
    }
}

// ---------------- dist1: 5x1 conv 32->25(pad32) via mma -> g_d1 NHWC fp32 ----------------
__global__ void __launch_bounds__(448) dist1_mma(const __half* __restrict__ act,
                                                 const float* __restrict__ b1){
    constexpr int SBS = 40;
    constexpr int ABUF = 224*48;
    constexpr int BBUF = 16*SBS*2;
    __shared__ __align__(16) __half sA[2*224*24];
    __shared__ __align__(16) __half sB[2*16*SBS];

    int tid = threadIdx.x, wid = tid >> 5, lane = tid & 31;
    int b = blockIdx.z, y = blockIdx.y;
    int x0 = blockIdx.x * 224;
    int warp_m = wid % 7, warp_n = wid / 7;
    int m_off = warp_m * 32, n_off = warp_n * 16;

    uint32_t sAu = smem_u32(sA), sBu = smem_u32(sB);

    int gylist[5]; int nky = 0;
    #pragma unroll
    for (int ky = 0; ky < 5; ky++){
        int gy = y + ky - 2;
        if (gy >= 0 && gy < HH){ gylist[nky] = (ky << 16) | gy; nky++; }
    }
    int N = nky * 2;

    float acc[2][2][4];
    #pragma unroll
    for (int mt = 0; mt < 2; mt++)
        #pragma unroll
        for (int nt = 0; nt < 2; nt++)
            #pragma unroll
            for (int r = 0; r < 4; r++) acc[mt][nt][r] = 0.f;

    const size_t brow = (size_t)b * HH;

    auto stage = [&](int it){
        int buf = it & 1;
        int kykey = gylist[it >> 1];
        int ky = kykey >> 16, gy = kykey & 0xffff;
        int kc = it & 1;
        const __half* arowb = act + ((brow + gy)*WW + x0)*32 + kc*16;
        uint32_t adst = sAu + buf*ABUF;
        {
            int c = tid;
            int r = c >> 1, hf = c & 1;
            cp16(adst + r*48 + hf*16, arowb + (size_t)r*32 + hf*8, 16);
        }
        const __half* wsrc = g_wpd + ((ky*2 + kc)*16) * 32;
        uint32_t bdst = sBu + buf*BBUF;
        if (tid < 64){
            int r = tid >> 2, cu = tid & 3;
            cp16(bdst + (r*SBS + cu*8)*2, wsrc + r*32 + cu*8, 16);
        }
        CP_COMMIT();
    };

    stage(0);
    for (int it = 0; it < N; it++){
        CP_WAIT0();
        __syncthreads();
        if (it + 1 < N) stage(it+1);
        int buf = it & 1;
        uint32_t aBase = sAu + buf*ABUF + ((lane & 15)*48) + ((lane >> 4)*16);
        uint32_t bBase = sBu + buf*BBUF + ((lane & 15)*SBS + n_off)*2 + ((lane >> 4)*16);
        uint32_t afr[2][4];
        ldsm_x4(afr[0], aBase + m_off*48);
        ldsm_x4(afr[1], aBase + (m_off + 16)*48);
        uint32_t r4[4];
        ldsm_x4t(r4, bBase);
        uint32_t bfr[2][2];
        bfr[0][0] = r4[0]; bfr[0][1] = r4[1];
        bfr[1][0] = r4[2]; bfr[1][1] = r4[3];
        #pragma unroll
        for (int mt = 0; mt < 2; mt++)
            #pragma unroll
            for (int nt = 0; nt < 2; nt++)
                mma16816(acc[mt][nt], afr[mt], bfr[nt]);
    }

    int row = lane >> 2, col = (lane & 3)*2;
    float* obase = g_d1 + ((brow + y)*WW + x0) * 32;
    #pragma unroll
    for (int mt = 0; mt < 2; mt++){
        int m0 = m_off + mt*16 + row;
        #pragma unroll
        for (int nt = 0; nt < 2; nt++){
            int n0 = n_off + nt*8 + col;
            float bv0 = (n0   < 25) ? b1[n0]   : 0.f;
            float bv1 = (n0+1 < 25) ? b1[n0+1] : 0.f;
            float2 v0 = make_float2(acc[mt][nt][0] + bv0, acc[mt][nt][1] + bv1);
            float2 v1 = make_float2(acc[mt][nt][2] + bv0, acc[mt][nt][3] + bv1);
            *reinterpret_cast<float2*>(obase + (size_t)m0*32 + n0)     = v0;
            *reinterpret_cast<float2*>(obase + (size_t)(m0+8)*32 + n0) = v1;
        }
    }
}

// ---------------- dist2 (1x5) + softmax + unfold-weighted flow avg ----------------
__global__ void __launch_bounds__(224) final_kernel(
        const float* __restrict__ w2, const float* __restrict__ b2,
        const float* __restrict__ flow,
        const float* __restrict__ sxw, const float* __restrict__ sxb,
        const float* __restrict__ syw, const float* __restrict__ syb,
        float* __restrict__ out){
    int blk  = blockIdx.x;
    int half = blk & 1;
    int bh   = blk >> 1;
    int b = bh / HH, h = bh % HH;
    int x0 = half * 224;

    __shared__ float sd[25][228];
    __shared__ float sw2[25*25*5];
    for (int t = threadIdx.x; t < 228; t += 224){
        int gx = x0 + t - 2;
        if (gx >= 0 && gx < WW){
            const float4* src = reinterpret_cast<const float4*>(
                g_d1 + ((size_t)(b*HH + h)*WW + gx)*32);
            #pragma unroll
            for (int q = 0; q < 7; q++){
                float4 v = src[q];
                int c0 = q*4;
                if (c0     < 25) sd[c0][t]   = v.x;
                if (c0 + 1 < 25) sd[c0+1][t] = v.y;
                if (c0 + 2 < 25) sd[c0+2][t] = v.z;
                if (c0 + 3 < 25) sd[c0+3][t] = v.w;
            }
        } else {
            #pragma unroll
            for (int ci = 0; ci < 25; ci++) sd[ci][t] = 0.f;
        }
    }
    for (int i = threadIdx.x; i < 25*25*5; i += 224) sw2[i] = w2[i];
    __syncthreads();

    int lx = threadIdx.x;
    int x  = x0 + lx;
    float acc[25];
    #pragma unroll
    for (int co = 0; co < 25; co++) acc[co] = 0.f;
    for (int ci = 0; ci < 25; ci++){
        #pragma unroll
        for (int kw = 0; kw < 5; kw++){
            float v = sd[ci][lx + kw];
            #pragma unroll
            for (int co = 0; co < 25; co++)
                acc[co] = fmaf(v, sw2[(co*25+ci)*5 + kw], acc[co]);
        }
    }
    float m = -1e30f;
    #pragma unroll
    for (int co = 0; co < 25; co++){
        float d = acc[co] + b2[co];
        d = -(d*d);
        acc[co] = d;
        m = fmaxf(m, d);
    }
    float s = 0.f;
    #pragma unroll
    for (int co = 0; co < 25; co++){ acc[co] = expf(acc[co] - m); s += acc[co]; }
    float dv = 1.f / s;

    const float* f0 = flow + (b*2+0)*HWSZ;
    const float* f1 = flow + (b*2+1)*HWSZ;
    float sx = sxb[0], sy = syb[0];
    #pragma unroll
    for (int k = 0; k < 25; k++){
        int kh = k / 5, kw = k % 5;
        int gy = h + kh - 2, gx = x + kw - 2;
        float u1 = 0.f, u2 = 0.f;
        if (gy >= 0 && gy < HH && gx >= 0 && gx < WW){
            u1 = f0[gy*WW + gx];
            u2 = f1[gy*WW + gx];
        }
        sx = fmaf(sxw[k], acc[k]*u1, sx);
        sy = fmaf(syw[k], acc[k]*u2, sy);
    }
    out[(b*2+0)*HWSZ + h*WW + x] = sx * dv;
    out[(b*2+1)*HWSZ + h*WW + x] = sy * dv;
}

extern "C" void kernel_launch(void* const* d_in, const int* in_sizes, int n_in,
                              void* d_out, int out_size){
    const float* t1     = (const float*)d_in[0];
    const float* t2     = (const float*)d_in[1];
    const float* ft1    = (const float*)d_in[2];
    const float* flow   = (const float*)d_in[4];
    const float* feat_w = (const float*)d_in[5];
    const float* feat_b = (const float*)d_in[6];
    const float* mw1 = (const float*)d_in[7];  const float* mb1 = (const float*)d_in[8];
    const float* mw2 = (const float*)d_in[9];  const float* mb2 = (const float*)d_in[10];
    const float* mw3 = (const float*)d_in[11]; const float* mb3 = (const float*)d_in[12];
    const float* mw4 = (const float*)d_in[13]; const float* mb4 = (const float*)d_in[14];
    const float* mw5 = (const float*)d_in[15]; const float* mb5 = (const float*)d_in[16];
    const float* mw6 = (const float*)d_in[17]; const float* mb6 = (const float*)d_in[18];
    const float* dw1 = (const float*)d_in[19]; const float* db1 = (const float*)d_in[20];
    const float* dw2 = (const float*)d_in[21]; const float* db2 = (const float*)d_in[22];
    const float* sxw = (const float*)d_in[23]; const float* sxb = (const float*)d_in[24];
    const float* syw = (const float*)d_in[25]; const float* syb = (const float*)d_in[26];
    float* out = (float*)d_out;

    __half *px = nullptr, *pa = nullptr, *pb = nullptr;
    cudaGetSymbolAddress((void**)&px, g_x);
    cudaGetSymbolAddress((void**)&pa, g_a);
    cudaGetSymbolAddress((void**)&pb, g_b);

    // launch 1: fused weight prep + flow-mean partials
    prep_all<<<PREP_BLOCKS + 64, 256>>>(mw1, mw2, mw3, mw4, mw5, mw6, feat_w, dw1, flow);
    // launch 2
    assemble_kernel<<<(BB*HWSZ + 255)/256, 256>>>(t1, t2, flow);
    // launch 3
    dim3 fgrid(7, HH, BB);
    feat_mma<<<fgrid, 256>>>(ft1, feat_b);

    // launch 4 = conv layer 1 (captured by ncu with 2 hidden harness launches + skip 5)
    dim3 cgrid(4, HH, BB);
    conv3x3_nhwc<128><<<cgrid, 256>>>(px, 144, 9, mb1, pa, 0);
    conv3x3_nhwc<128><<<cgrid, 256>>>(pa, 128, 8, mb2, pb, 165888);
    conv3x3_nhwc< 64><<<cgrid, 256>>>(pb, 128, 8, mb3, pa, 313344);
    conv3x3_nhwc< 64><<<cgrid, 256>>>(pa,  64, 4, mb4, pb, 387072);
    conv3x3_nhwc< 32><<<cgrid, 256>>>(pb,  64, 4, mb5, pa, 423936);
    conv3x3_nhwc< 32><<<cgrid, 256>>>(pa,  32, 2, mb6, pb, 442368);

    dim3 dgrid(2, HH, BB);
    dist1_mma<<<dgrid, 448>>>(pb, db1);
    final_kernel<<<BB*HH*2, 224>>>(dw2, db2, flow, sxw, sxb, syw, syb, out);
}

// round 11
// speedup vs baseline: 12.3445x; 1.0136x over previous
#include <cuda_runtime.h>
#include <cuda_fp16.h>
#include <math.h>
#include <stdint.h>

#define HH 192
#define WW 448
#define HWSZ (HH*WW)
#define BB 4

// ---------------- scratch (__device__ globals; no allocation) ----------------
__device__ __half g_x[BB*HWSZ*144];
__device__ __half g_a[BB*HWSZ*128];   // ping
__device__ __half g_b[BB*HWSZ*128];   // pong
__device__ float  g_d1[BB*HWSZ*32];   // dist after 5x1 conv (NHWC fp32, ch 0..24 valid)
__device__ float  g_fpart[64];        // flow mean partials [bc][chunk]
#define WP_TOTAL 460800
__device__ __align__(16) __half g_wp[WP_TOTAL];
__device__ __align__(16) __half g_wpf[64*128];       // feat 1x1 weights [ci][co]
__device__ __align__(16) __half g_wpd[5*2*16*32];    // dist1 weights [ky][kc][krow][co32]

__device__ __forceinline__ float lrelu(float v){ return v >= 0.f ? v : 0.1f*v; }

__device__ __forceinline__ uint32_t smem_u32(const void* p){
    uint32_t a;
    asm("{ .reg .u64 t; cvta.to.shared.u64 t, %1; cvt.u32.u64 %0, t; }" : "=r"(a) : "l"(p));
    return a;
}
__device__ __forceinline__ void cp16(uint32_t dst, const void* src, int srcsz){
    asm volatile("cp.async.ca.shared.global [%0], [%1], 16, %2;"
        :: "r"(dst), "l"(src), "r"(srcsz) : "memory");
}
#define CP_COMMIT() asm volatile("cp.async.commit_group;" ::: "memory")
#define CP_WAIT0()  asm volatile("cp.async.wait_group 0;"  ::: "memory")

__device__ __forceinline__ void ldsm_x4(uint32_t* r, uint32_t a){
    asm volatile("ldmatrix.sync.aligned.m8n8.x4.shared.b16 {%0,%1,%2,%3}, [%4];"
        : "=r"(r[0]),"=r"(r[1]),"=r"(r[2]),"=r"(r[3]) : "r"(a));
}
__device__ __forceinline__ void ldsm_x4t(uint32_t* r, uint32_t a){
    asm volatile("ldmatrix.sync.aligned.m8n8.x4.trans.shared.b16 {%0,%1,%2,%3}, [%4];"
        : "=r"(r[0]),"=r"(r[1]),"=r"(r[2]),"=r"(r[3]) : "r"(a));
}
__device__ __forceinline__ void mma16816(float* c, const uint32_t* a, const uint32_t* b){
    asm volatile("mma.sync.aligned.m16n8k16.row.col.f32.f16.f16.f32 "
        "{%0,%1,%2,%3}, {%4,%5,%6,%7}, {%8,%9}, {%0,%1,%2,%3};"
        : "+f"(c[0]),"+f"(c[1]),"+f"(c[2]),"+f"(c[3])
        : "r"(a[0]),"r"(a[1]),"r"(a[2]),"r"(a[3]), "r"(b[0]),"r"(b[1]));
}

// ---------------- fused weight prep + flow-mean partials ----------------
__device__ __forceinline__ void prep_conv_one(const float* w, int idx,
        int BN, int Cin, int KC, int base, int permL1){
    int co = idx % BN; int r = idx / BN;
    int krow = r % 16; r /= 16;
    int kx = r % 3; r /= 3;
    int kc = r % KC; int ky = r / KC;
    int ci = kc*16 + krow;
    int tap = ky*3 + kx;
    float v = 0.f;
    if (ci < Cin){
        int srcci = permL1 ? (ci < 128 ? ci + 3 : ci - 128) : ci;
        v = w[(co*Cin + srcci)*9 + tap];
    }
    g_wp[base + (((ky*KC + kc)*3 + kx)*16 + krow)*BN + co] = __float2half(v);
}

#define PREP_TOTAL (165888+147456+73728+36864+18432+9216+8192+5120)
#define PREP_BLOCKS ((PREP_TOTAL + 255)/256)

__global__ void prep_all(const float* __restrict__ mw1, const float* __restrict__ mw2,
                         const float* __restrict__ mw3, const float* __restrict__ mw4,
                         const float* __restrict__ mw5, const float* __restrict__ mw6,
                         const float* __restrict__ fw,  const float* __restrict__ dw1,
                         const float* __restrict__ flow){
    __shared__ float red[256];
    if (blockIdx.x >= PREP_BLOCKS){
        int fb = blockIdx.x - PREP_BLOCKS;
        int bc = fb >> 3, chunk = fb & 7;
        const float* p = flow + bc*HWSZ + chunk*(HWSZ/8);
        float s = 0.f;
        for (int i = threadIdx.x; i < HWSZ/8; i += 256) s += p[i];
        red[threadIdx.x] = s; __syncthreads();
        for (int o = 128; o > 0; o >>= 1){
            if (threadIdx.x < o) red[threadIdx.x] += red[threadIdx.x+o];
            __syncthreads();
        }
        if (threadIdx.x == 0) g_fpart[fb] = red[0] / (float)HWSZ;
        return;
    }
    int idx = blockIdx.x*256 + threadIdx.x;
    if (idx < 165888){ prep_conv_one(mw1, idx, 128, 131, 9, 0, 1); return; }
    idx -= 165888;
    if (idx < 147456){ prep_conv_one(mw2, idx, 128, 128, 8, 165888, 0); return; }
    idx -= 147456;
    if (idx < 73728){ prep_conv_one(mw3, idx, 64, 128, 8, 313344, 0); return; }
    idx -= 73728;
    if (idx < 36864){ prep_conv_one(mw4, idx, 64, 64, 4, 387072, 0); return; }
    idx -= 36864;
    if (idx < 18432){ prep_conv_one(mw5, idx, 32, 64, 4, 423936, 0); return; }
    idx -= 18432;
    if (idx < 9216){ prep_conv_one(mw6, idx, 32, 32, 2, 442368, 0); return; }
    idx -= 9216;
    if (idx < 64*128){
        int ci = idx >> 7, co = idx & 127;
        g_wpf[ci*128 + co] = __float2half(fw[co*64 + ci]);
        return;
    }
    idx -= 64*128;
    if (idx < 5*2*16*32){
        int co = idx & 31; int r = idx >> 5;
        int krow = r % 16; r /= 16;
        int kc = r & 1; int ky = r >> 1;
        int ci = kc*16 + krow;
        float v = (co < 25) ? dw1[(co*32 + ci)*5 + ky] : 0.f;
        g_wpd[idx] = __float2half(v);
    }
}

// ---------------- backwarp diff + centered flow -> g_x ch 128..143 ----------------
__global__ void assemble_kernel(const float* __restrict__ t1,
                                const float* __restrict__ t2,
                                const float* __restrict__ flow){
    int idx = blockIdx.x*256 + threadIdx.x;
    if (idx >= BB*HWSZ) return;
    int b = idx / HWSZ, p = idx % HWSZ;
    int h = p / WW, w = p % WW;
    float mean0 = 0.f, mean1 = 0.f;
    #pragma unroll
    for (int i = 0; i < 8; i++){
        mean0 += g_fpart[(b*2+0)*8 + i];
        mean1 += g_fpart[(b*2+1)*8 + i];
    }
    float f0 = flow[(b*2+0)*HWSZ + p];
    float f1 = flow[(b*2+1)*HWSZ + p];
    float x = (float)w + f0*5.0f;
    float y = (float)h + f1*5.0f;
    float x0f = floorf(x), y0f = floorf(y);
    int x0 = (int)x0f, y0 = (int)y0f;
    float wx1 = x - x0f, wy1 = y - y0f;
    float wx0 = 1.f - wx1, wy0 = 1.f - wy1;
    float d2 = 0.f;
    #pragma unroll
    for (int c = 0; c < 3; c++){
        const float* img = t2 + (b*3+c)*HWSZ;
        float v00 = (y0   >= 0 && y0   < HH && x0   >= 0 && x0   < WW) ? img[y0*WW + x0]       : 0.f;
        float v01 = (y0   >= 0 && y0   < HH && x0+1 >= 0 && x0+1 < WW) ? img[y0*WW + x0+1]     : 0.f;
        float v10 = (y0+1 >= 0 && y0+1 < HH && x0   >= 0 && x0   < WW) ? img[(y0+1)*WW + x0]   : 0.f;
        float v11 = (y0+1 >= 0 && y0+1 < HH && x0+1 >= 0 && x0+1 < WW) ? img[(y0+1)*WW + x0+1] : 0.f;
        float warp = v00*(wy0*wx0) + v01*(wy0*wx1) + v10*(wy1*wx0) + v11*(wy1*wx1);
        float dv = t1[(b*3+c)*HWSZ + p] - warp;
        d2 += dv*dv;
    }
    __half hv[16];
    hv[0] = __float2half(sqrtf(d2));
    hv[1] = __float2half(f0 - mean0);
    hv[2] = __float2half(f1 - mean1);
    #pragma unroll
    for (int i = 3; i < 16; i++) hv[i] = __float2half(0.f);
    uint4* dst = reinterpret_cast<uint4*>(g_x + ((size_t)idx)*144 + 128);
    const uint4* srcv = reinterpret_cast<const uint4*>(hv);
    dst[0] = srcv[0]; dst[1] = srcv[1];
}

// ---------------- feat: 1x1 conv 64->128 via mma ----------------
__global__ void __launch_bounds__(256) feat_mma(const float* __restrict__ fin,
                                                const float* __restrict__ fb){
    __shared__ __align__(16) __half sA[64*72];
    __shared__ __align__(16) __half sB[64*136];

    int tid = threadIdx.x, wid = tid >> 5, lane = tid & 31;
    int b = blockIdx.z, y = blockIdx.y;
    int x0 = blockIdx.x * 64;
    int warp_m = wid & 3, warp_n = wid >> 2;
    int m_off = warp_m * 16, n_off = warp_n * 64;

    uint32_t sAu = smem_u32(sA), sBu = smem_u32(sB);
    int a_krow = (lane & 7) + ((lane >> 4) << 3);
    int a_mcol = m_off + (((lane >> 3) & 1) << 3);
    uint32_t aBase = sAu + (uint32_t)((a_krow*72 + a_mcol) * 2);
    uint32_t bBase = sBu + (uint32_t)(((lane & 15)*136 + n_off) * 2) + ((lane >> 4) << 4);

    float acc[8][4];
    #pragma unroll
    for (int nt = 0; nt < 8; nt++)
        #pragma unroll
        for (int r = 0; r < 4; r++) acc[nt][r] = 0.f;

    const float* fbase = fin + (size_t)b*64*HWSZ + (size_t)y*WW + x0;

    #pragma unroll
    for (int k = 0; k < 4; k++){
        int c = tid + k*256;
        int row = c >> 4, q = c & 15;
        float4 v = *reinterpret_cast<const float4*>(fbase + (size_t)row*HWSZ + q*4);
        __half2 h0 = __floats2half2_rn(v.x, v.y);
        __half2 h1 = __floats2half2_rn(v.z, v.w);
        uint32_t dst = sAu + (uint32_t)((row*72 + q*4) * 2);
        asm volatile("st.shared.v2.b32 [%0], {%1, %2};"
            :: "r"(dst), "r"(*(uint32_t*)&h0), "r"(*(uint32_t*)&h1) : "memory");
    }
    #pragma unroll
    for (int k = 0; k < 4; k++){
        int c = tid + k*256;
        int r = c >> 4, cu = c & 15;
        *reinterpret_cast<uint4*>(sB + r*136 + cu*8) =
            *reinterpret_cast<const uint4*>(g_wpf + r*128 + cu*8);
    }
    __syncthreads();

    #pragma unroll
    for (int kci = 0; kci < 4; kci++){
        uint32_t afr[4];
        ldsm_x4t(afr, aBase + (uint32_t)(kci*16*72*2));
        uint32_t bfr[8][2];
        #pragma unroll
        for (int np = 0; np < 4; np++){
            uint32_t r4[4];
            ldsm_x4t(r4, bBase + (uint32_t)(kci*16*136*2 + np*16*2));
            bfr[2*np][0] = r4[0]; bfr[2*np][1] = r4[1];
            bfr[2*np+1][0] = r4[2]; bfr[2*np+1][1] = r4[3];
        }
        #pragma unroll
        for (int nt = 0; nt < 8; nt++)
            mma16816(acc[nt], afr, bfr[nt]);
    }

    int row = lane >> 2, col = (lane & 3)*2;
    __half* obase = g_x + ((size_t)(b*HH + y)*WW + x0)*144;
    int m0 = m_off + row;
    #pragma unroll
    for (int nt = 0; nt < 8; nt++){
        int n0 = n_off + nt*8 + col;
        float bv0 = fb[n0], bv1 = fb[n0+1];
        __half2 v0 = __halves2half2(__float2half(lrelu(acc[nt][0] + bv0)),
                                    __float2half(lrelu(acc[nt][1] + bv1)));
        __half2 v1 = __halves2half2(__float2half(lrelu(acc[nt][2] + bv0)),
                                    __float2half(lrelu(acc[nt][3] + bv1)));
        *reinterpret_cast<__half2*>(obase + (size_t)m0*144 + n0)     = v0;
        *reinterpret_cast<__half2*>(obase + (size_t)(m0+8)*144 + n0) = v1;
    }
}

// ---------------- BN=128 conv: 128 threads, 4 warps (2m x 2n), warp tile 64x64 ----------------
__global__ void __launch_bounds__(128, 2) conv3x3_big(
        const __half* __restrict__ act, int CX, int KC,
        const float* __restrict__ bias, __half* __restrict__ out, int wp_base){
    constexpr int BN  = 128;
    constexpr int SBS = BN + 8;
    constexpr int ABUF = 130*48;        // bytes per A buffer
    constexpr int BBUF = 48*SBS*2;
    __shared__ __align__(16) __half sA[2*130*24];
    __shared__ __align__(16) __half sB[2*48*SBS];

    int tid = threadIdx.x, wid = tid >> 5, lane = tid & 31;
    int b = blockIdx.z, y = blockIdx.y;
    int x0 = blockIdx.x * 128; if (x0 > WW-128) x0 = WW-128;
    int warp_m = wid & 1, warp_n = wid >> 1;
    int m_off = warp_m * 64, n_off = warp_n * 64;

    uint32_t sAu = smem_u32(sA), sBu = smem_u32(sB);

    int gylist[3]; int nky = 0;
    #pragma unroll
    for (int ky = 0; ky < 3; ky++){
        int gy = y + ky - 1;
        if (gy >= 0 && gy < HH){ gylist[nky] = (ky << 16) | gy; nky++; }
    }
    int N = nky * KC;

    float acc[4][8][4];
    #pragma unroll
    for (int mt = 0; mt < 4; mt++)
        #pragma unroll
        for (int nt = 0; nt < 8; nt++)
            #pragma unroll
            for (int r = 0; r < 4; r++) acc[mt][nt][r] = 0.f;

    const size_t brow = (size_t)b * HH;

    auto stage = [&](int it){
        int buf = it & 1;
        int kykey = gylist[it / KC];
        int ky = kykey >> 16, gy = kykey & 0xffff;
        int kc = it % KC;
        const __half* arowb = act + ((brow + gy)*WW)*CX + kc*16;
        uint32_t adst = sAu + buf*ABUF;
        for (int c = tid; c < 260; c += 128){
            int r = c >> 1, hf = c & 1;
            int gx = x0 - 1 + r;
            int ok = (gx >= 0 && gx < WW) ? 16 : 0;
            int gxc = gx < 0 ? 0 : (gx >= WW ? WW-1 : gx);
            cp16(adst + r*48 + hf*16, arowb + (size_t)gxc*CX + hf*8, ok);
        }
        const __half* wsrc = g_wp + wp_base + (size_t)((ky*KC + kc)*48) * BN;
        uint32_t bdst = sBu + buf*BBUF;
        for (int c = tid; c < 48*16; c += 128){
            int r = c >> 4, cu = c & 15;
            cp16(bdst + (r*SBS + cu*8)*2, wsrc + (size_t)r*BN + cu*8, 16);
        }
        CP_COMMIT();
    };

    stage(0);
    for (int it = 0; it < N; it++){
        CP_WAIT0();
        __syncthreads();
        if (it + 1 < N) stage(it+1);
        int buf = it & 1;
        uint32_t aBase = sAu + buf*ABUF + ((lane & 15)*48) + ((lane >> 4)*16);
        uint32_t bBase = sBu + buf*BBUF + ((lane & 15)*SBS + n_off)*2 + ((lane >> 4)*16);
        #pragma unroll
        for (int kx = 0; kx < 3; kx++){
            uint32_t afr[4][4];
            #pragma unroll
            for (int mt = 0; mt < 4; mt++)
                ldsm_x4(afr[mt], aBase + (m_off + mt*16 + kx)*48);
            uint32_t bfr[8][2];
            #pragma unroll
            for (int np = 0; np < 4; np++){
                uint32_t r4[4];
                ldsm_x4t(r4, bBase + (kx*16)*SBS*2 + np*16*2);
                bfr[2*np][0] = r4[0]; bfr[2*np][1] = r4[1];
                bfr[2*np+1][0] = r4[2]; bfr[2*np+1][1] = r4[3];
            }
            #pragma unroll
            for (int mt = 0; mt < 4; mt++)
                #pragma unroll
                for (int nt = 0; nt < 8; nt++)
                    mma16816(acc[mt][nt], afr[mt], bfr[nt]);
        }
    }

    int row = lane >> 2, col = (lane & 3)*2;
    __half* obase = out + ((brow + y)*WW + x0) * BN;
    #pragma unroll
    for (int mt = 0; mt < 4; mt++){
        int m0 = m_off + mt*16 + row;
        #pragma unroll
        for (int nt = 0; nt < 8; nt++){
            int n0 = n_off + nt*8 + col;
            float bv0 = bias[n0], bv1 = bias[n0+1];
            __half2 v0 = __halves2half2(__float2half(lrelu(acc[mt][nt][0] + bv0)),
                                        __float2half(lrelu(acc[mt][nt][1] + bv1)));
            __half2 v1 = __halves2half2(__float2half(lrelu(acc[mt][nt][2] + bv0)),
                                        __float2half(lrelu(acc[mt][nt][3] + bv1)));
            *reinterpret_cast<__half2*>(obase + (size_t)m0*BN + n0)       = v0;
            *reinterpret_cast<__half2*>(obase + (size_t)(m0+8)*BN + n0)   = v1;
        }
    }
}

// ---------------- NHWC conv, BN<=64: M=128, 256 threads, 2 CTAs/SM ----------------
template<int BN>
__global__ void __launch_bounds__(256, 2) conv3x3_nhwc(
        const __half* __restrict__ act, int CX, int KC,
        const float* __restrict__ bias, __half* __restrict__ out, int wp_base){
    constexpr int NT  = BN/16;
    constexpr int SBS = BN + 8;
    constexpr int ABUF = 130*48;
    constexpr int BBUF = 48*SBS*2;
    __shared__ __align__(16) __half sA[2*130*24];
    __shared__ __align__(16) __half sB[2*48*SBS];

    int tid = threadIdx.x, wid = tid >> 5, lane = tid & 31;
    int b = blockIdx.z, y = blockIdx.y;
    int x0 = blockIdx.x * 128; if (x0 > WW-128) x0 = WW-128;
    int warp_m = wid & 3, warp_n = wid >> 2;
    int m_off = warp_m * 32, n_off = warp_n * (BN/2);

    uint32_t sAu = smem_u32(sA), sBu = smem_u32(sB);

    int gylist[3]; int nky = 0;
    #pragma unroll
    for (int ky = 0; ky < 3; ky++){
        int gy = y + ky - 1;
        if (gy >= 0 && gy < HH){ gylist[nky] = (ky << 16) | gy; nky++; }
    }
    int N = nky * KC;

    float acc[2][NT][4];
    #pragma unroll
    for (int mt = 0; mt < 2; mt++)
        #pragma unroll
        for (int nt = 0; nt < NT; nt++)
            #pragma unroll
            for (int r = 0; r < 4; r++) acc[mt][nt][r] = 0.f;

    const size_t brow = (size_t)b * HH;

    auto stage = [&](int it){
        int buf = it & 1;
        int kykey = gylist[it / KC];
        int ky = kykey >> 16, gy = kykey & 0xffff;
        int kc = it % KC;
        const __half* arowb = act + ((brow + gy)*WW)*CX + kc*16;
        uint32_t adst = sAu + buf*ABUF;
        for (int c = tid; c < 260; c += 256){
            int r = c >> 1, hf = c & 1;
            int gx = x0 - 1 + r;
            int ok = (gx >= 0 && gx < WW) ? 16 : 0;
            int gxc = gx < 0 ? 0 : (gx >= WW ? WW-1 : gx);
            cp16(adst + r*48 + hf*16, arowb + (size_t)gxc*CX + hf*8, ok);
        }
        const __half* wsrc = g_wp + wp_base + (size_t)((ky*KC + kc)*48) * BN;
        uint32_t bdst = sBu + buf*BBUF;
        constexpr int CPR = BN/8;
        for (int c = tid; c < 48*CPR; c += 256){
            int r = c / CPR, cu = c % CPR;
            cp16(bdst + (r*SBS + cu*8)*2, wsrc + (size_t)r*BN + cu*8, 16);
        }
        CP_COMMIT();
    };

    stage(0);
    for (int it = 0; it < N; it++){
        CP_WAIT0();
        __syncthreads();
        if (it + 1 < N) stage(it+1);
        int buf = it & 1;
        uint32_t aBase = sAu + buf*ABUF + ((lane & 15)*48) + ((lane >> 4)*16);
        uint32_t bBase = sBu + buf*BBUF + ((lane & 15)*SBS + n_off)*2 + ((lane >> 4)*16);
        #pragma unroll
        for (int kx = 0; kx < 3; kx++){
            uint32_t afr[2][4];
            ldsm_x4(afr[0], aBase + (m_off + kx)*48);
            ldsm_x4(afr[1], aBase + (m_off + kx + 16)*48);
            uint32_t bfr[NT][2];
            #pragma unroll
            for (int np = 0; np < NT/2; np++){
                uint32_t r4[4];
                ldsm_x4t(r4, bBase + (kx*16)*SBS*2 + np*16*2);
                bfr[2*np][0] = r4[0]; bfr[2*np][1] = r4[1];
                bfr[2*np+1][0] = r4[2]; bfr[2*np+1][1] = r4[3];
            }
            #pragma unroll
            for (int mt = 0; mt < 2; mt++)
                #pragma unroll
                for (int nt = 0; nt < NT; nt++)
                    mma16816(acc[mt][nt], afr[mt], bfr[nt]);
        }
    }

    int row = lane >> 2, col = (lane & 3)*2;
    __half* obase = out + ((brow + y)*WW + x0) * BN;
    #pragma unroll
    for (int mt = 0; mt < 2; mt++){
        int m0 = m_off + mt*16 + row;
        #pragma unroll
        for (int nt = 0; nt < NT; nt++){
            int n0 = n_off + nt*8 + col;
            float bv0 = bias[n0], bv1 = bias[n0+1];
            __half2 v0 = __halves2half2(__float2half(lrelu(acc[mt][nt][0] + bv0)),
                                        __float2half(lrelu(acc[mt][nt][1] + bv1)));
            __half2 v1 = __halves2half2(__float2half(lrelu(acc[mt][nt][2] + bv0)),
                                        __float2half(lrelu(acc[mt][nt][3] + bv1)));
            *reinterpret_cast<__half2*>(obase + (size_t)m0*BN + n0)       = v0;
            *reinterpret_cast<__half2*>(obase + (size_t)(m0+8)*BN + n0)   = v1;
        }
    }
}

// ---------------- dist1: 5x1 conv 32->25(pad32) via mma -> g_d1 NHWC fp32 ----------------
__global__ void __launch_bounds__(448) dist1_mma(const __half* __restrict__ act,
                                                 const float* __restrict__ b1){
    constexpr int SBS = 40;
    constexpr int ABUF = 224*48;
    constexpr int BBUF = 16*SBS*2;
    __shared__ __align__(16) __half sA[2*224*24];
    __shared__ __align__(16) __half sB[2*16*SBS];

    int tid = threadIdx.x, wid = tid >> 5, lane = tid & 31;
    int b = blockIdx.z, y = blockIdx.y;
    int x0 = blockIdx.x * 224;
    int warp_m = wid % 7, warp_n = wid / 7;
    int m_off = warp_m * 32, n_off = warp_n * 16;

    uint32_t sAu = smem_u32(sA), sBu = smem_u32(sB);

    int gylist[5]; int nky = 0;
    #pragma unroll
    for (int ky = 0; ky < 5; ky++){
        int gy = y + ky - 2;
        if (gy >= 0 && gy < HH){ gylist[nky] = (ky << 16) | gy; nky++; }
    }
    int N = nky * 2;

    float acc[2][2][4];
    #pragma unroll
    for (int mt = 0; mt < 2; mt++)
        #pragma unroll
        for (int nt = 0; nt < 2; nt++)
            #pragma unroll
            for (int r = 0; r < 4; r++) acc[mt][nt][r] = 0.f;

    const size_t brow = (size_t)b * HH;

    auto stage = [&](int it){
        int buf = it & 1;
        int kykey = gylist[it >> 1];
        int ky = kykey >> 16, gy = kykey & 0xffff;
        int kc = it & 1;
        const __half* arowb = act + ((brow + gy)*WW + x0)*32 + kc*16;
        uint32_t adst = sAu + buf*ABUF;
        {
            int c = tid;
            int r = c >> 1, hf = c & 1;
            cp16(adst + r*48 + hf*16, arowb + (size_t)r*32 + hf*8, 16);
        }
        const __half* wsrc = g_wpd + ((ky*2 + kc)*16) * 32;
        uint32_t bdst = sBu + buf*BBUF;
        if (tid < 64){
            int r = tid >> 2, cu = tid & 3;
            cp16(bdst + (r*SBS + cu*8)*2, wsrc + r*32 + cu*8, 16);
        }
        CP_COMMIT();
    };

    stage(0);
    for (int it = 0; it < N; it++){
        CP_WAIT0();
        __syncthreads();
        if (it + 1 < N) stage(it+1);
        int buf = it & 1;
        uint32_t aBase = sAu + buf*ABUF + ((lane & 15)*48) + ((lane >> 4)*16);
        uint32_t bBase = sBu + buf*BBUF + ((lane & 15)*SBS + n_off)*2 + ((lane >> 4)*16);
        uint32_t afr[2][4];
        ldsm_x4(afr[0], aBase + m_off*48);
        ldsm_x4(afr[1], aBase + (m_off + 16)*48);
        uint32_t r4[4];
        ldsm_x4t(r4, bBase);
        uint32_t bfr[2][2];
        bfr[0][0] = r4[0]; bfr[0][1] = r4[1];
        bfr[1][0] = r4[2]; bfr[1][1] = r4[3];
        #pragma unroll
        for (int mt = 0; mt < 2; mt++)
            #pragma unroll
            for (int nt = 0; nt < 2; nt++)
                mma16816(acc[mt][nt], afr[mt], bfr[nt]);
    }

    int row = lane >> 2, col = (lane & 3)*2;
    float* obase = g_d1 + ((brow + y)*WW + x0) * 32;
    #pragma unroll
    for (int mt = 0; mt < 2; mt++){
        int m0 = m_off + mt*16 + row;
        #pragma unroll
        for (int nt = 0; nt < 2; nt++){
            int n0 = n_off + nt*8 + col;
            float bv0 = (n0   < 25) ? b1[n0]   : 0.f;
            float bv1 = (n0+1 < 25) ? b1[n0+1] : 0.f;
            float2 v0 = make_float2(acc[mt][nt][0] + bv0, acc[mt][nt][1] + bv1);
            float2 v1 = make_float2(acc[mt][nt][2] + bv0, acc[mt][nt][3] + bv1);
            *reinterpret_cast<float2*>(obase + (size_t)m0*32 + n0)     = v0;
            *reinterpret_cast<float2*>(obase + (size_t)(m0+8)*32 + n0) = v1;
        }
    }
}

// ---------------- dist2 (1x5) + softmax + unfold-weighted flow avg ----------------
__global__ void __launch_bounds__(224) final_kernel(
        const float* __restrict__ w2, const float* __restrict__ b2,
        const float* __restrict__ flow,
        const float* __restrict__ sxw, const float* __restrict__ sxb,
        const float* __restrict__ syw, const float* __restrict__ syb,
        float* __restrict__ out){
    int blk  = blockIdx.x;
    int half = blk & 1;
    int bh   = blk >> 1;
    int b = bh / HH, h = bh % HH;
    int x0 = half * 224;

    __shared__ float sd[25][228];
    __shared__ float sw2[25*25*5];
    for (int t = threadIdx.x; t < 228; t += 224){
        int gx = x0 + t - 2;
        if (gx >= 0 && gx < WW){
            const float4* src = reinterpret_cast<const float4*>(
                g_d1 + ((size_t)(b*HH + h)*WW + gx)*32);
            #pragma unroll
            for (int q = 0; q < 7; q++){
                float4 v = src[q];
                int c0 = q*4;
                if (c0     < 25) sd[c0][t]   = v.x;
                if (c0 + 1 < 25) sd[c0+1][t] = v.y;
                if (c0 + 2 < 25) sd[c0+2][t] = v.z;
                if (c0 + 3 < 25) sd[c0+3][t] = v.w;
            }
        } else {
            #pragma unroll
            for (int ci = 0; ci < 25; ci++) sd[ci][t] = 0.f;
        }
    }
    for (int i = threadIdx.x; i < 25*25*5; i += 224) sw2[i] = w2[i];
    __syncthreads();

    int lx = threadIdx.x;
    int x  = x0 + lx;
    float acc[25];
    #pragma unroll
    for (int co = 0; co < 25; co++) acc[co] = 0.f;
    for (int ci = 0; ci < 25; ci++){
        #pragma unroll
        for (int kw = 0; kw < 5; kw++){
            float v = sd[ci][lx + kw];
            #pragma unroll
            for (int co = 0; co < 25; co++)
                acc[co] = fmaf(v, sw2[(co*25+ci)*5 + kw], acc[co]);
        }
    }
    float m = -1e30f;
    #pragma unroll
    for (int co = 0; co < 25; co++){
        float d = acc[co] + b2[co];
        d = -(d*d);
        acc[co] = d;
        m = fmaxf(m, d);
    }
    float s = 0.f;
    #pragma unroll
    for (int co = 0; co < 25; co++){ acc[co] = expf(acc[co] - m); s += acc[co]; }
    float dv = 1.f / s;

    const float* f0 = flow + (b*2+0)*HWSZ;
    const float* f1 = flow + (b*2+1)*HWSZ;
    float sx = sxb[0], sy = syb[0];
    #pragma unroll
    for (int k = 0; k < 25; k++){
        int kh = k / 5, kw = k % 5;
        int gy = h + kh - 2, gx = x + kw - 2;
        float u1 = 0.f, u2 = 0.f;
        if (gy >= 0 && gy < HH && gx >= 0 && gx < WW){
            u1 = f0[gy*WW + gx];
            u2 = f1[gy*WW + gx];
        }
        sx = fmaf(sxw[k], acc[k]*u1, sx);
        sy = fmaf(syw[k], acc[k]*u2, sy);
    }
    out[(b*2+0)*HWSZ + h*WW + x] = sx * dv;
    out[(b*2+1)*HWSZ + h*WW + x] = sy * dv;
}

extern "C" void kernel_launch(void* const* d_in, const int* in_sizes, int n_in,
                              void* d_out, int out_size){
    const float* t1     = (const float*)d_in[0];
    const float* t2     = (const float*)d_in[1];
    const float* ft1    = (const float*)d_in[2];
    const float* flow   = (const float*)d_in[4];
    const float* feat_w = (const float*)d_in[5];
    const float* feat_b = (const float*)d_in[6];
    const float* mw1 = (const float*)d_in[7];  const float* mb1 = (const float*)d_in[8];
    const float* mw2 = (const float*)d_in[9];  const float* mb2 = (const float*)d_in[10];
    const float* mw3 = (const float*)d_in[11]; const float* mb3 = (const float*)d_in[12];
    const float* mw4 = (const float*)d_in[13]; const float* mb4 = (const float*)d_in[14];
    const float* mw5 = (const float*)d_in[15]; const float* mb5 = (const float*)d_in[16];
    const float* mw6 = (const float*)d_in[17]; const float* mb6 = (const float*)d_in[18];
    const float* dw1 = (const float*)d_in[19]; const float* db1 = (const float*)d_in[20];
    const float* dw2 = (const float*)d_in[21]; const float* db2 = (const float*)d_in[22];
    const float* sxw = (const float*)d_in[23]; const float* sxb = (const float*)d_in[24];
    const float* syw = (const float*)d_in[25]; const float* syb = (const float*)d_in[26];
    float* out = (float*)d_out;

    __half *px = nullptr, *pa = nullptr, *pb = nullptr;
    cudaGetSymbolAddress((void**)&px, g_x);
    cudaGetSymbolAddress((void**)&pa, g_a);
    cudaGetSymbolAddress((void**)&pb, g_b);

    prep_all<<<PREP_BLOCKS + 64, 256>>>(mw1, mw2, mw3, mw4, mw5, mw6, feat_w, dw1, flow);
    assemble_kernel<<<(BB*HWSZ + 255)/256, 256>>>(t1, t2, flow);
    dim3 fgrid(7, HH, BB);
    feat_mma<<<fgrid, 256>>>(ft1, feat_b);

    // launch 4 = conv layer 1 (captured by ncu)
    dim3 cgrid(4, HH, BB);
    conv3x3_big<<<cgrid, 128>>>(px, 144, 9, mb1, pa, 0);
    conv3x3_big<<<cgrid, 128>>>(pa, 128, 8, mb2, pb, 165888);
    conv3x3_nhwc< 64><<<cgrid, 256>>>(pb, 128, 8, mb3, pa, 313344);
    conv3x3_nhwc< 64><<<cgrid, 256>>>(pa,  64, 4, mb4, pb, 387072);
    conv3x3_nhwc< 32><<<cgrid, 256>>>(pb,  64, 4, mb5, pa, 423936);
    conv3x3_nhwc< 32><<<cgrid, 256>>>(pa,  32, 2, mb6, pb, 442368);

    dim3 dgrid(2, HH, BB);
    dist1_mma<<<dgrid, 448>>>(pb, db1);
    final_kernel<<<BB*HH*2, 224>>>(dw2, db2, flow, sxw, sxb, syw, syb, out);
}

// round 12
// speedup vs baseline: 13.3020x; 1.0776x over previous
#include <cuda_runtime.h>
#include <cuda_fp16.h>
#include <math.h>
#include <stdint.h>

#define HH 192
#define WW 448
#define HWSZ (HH*WW)
#define BB 4

// ---------------- scratch (__device__ globals; no allocation) ----------------
__device__ __half g_x[BB*HWSZ*144];
__device__ __half g_a[BB*HWSZ*128];   // ping
__device__ __half g_b[BB*HWSZ*128];   // pong
__device__ float  g_d1[BB*HWSZ*32];   // dist after 5x1 conv (NHWC fp32, ch 0..24 valid)
__device__ float  g_fpart[64];        // flow mean partials [bc][chunk]
#define WP_TOTAL 460800
__device__ __align__(16) __half g_wp[WP_TOTAL];
__device__ __align__(16) __half g_wpf[64*128];       // feat 1x1 weights [ci][co]
__device__ __align__(16) __half g_wpd[5*2*16*32];    // dist1 weights [ky][kc][krow][co32]

__device__ __forceinline__ float lrelu(float v){ return v >= 0.f ? v : 0.1f*v; }

__device__ __forceinline__ uint32_t smem_u32(const void* p){
    uint32_t a;
    asm("{ .reg .u64 t; cvta.to.shared.u64 t, %1; cvt.u32.u64 %0, t; }" : "=r"(a) : "l"(p));
    return a;
}
__device__ __forceinline__ void cp16(uint32_t dst, const void* src, int srcsz){
    asm volatile("cp.async.ca.shared.global [%0], [%1], 16, %2;"
        :: "r"(dst), "l"(src), "r"(srcsz) : "memory");
}
#define CP_COMMIT() asm volatile("cp.async.commit_group;" ::: "memory")
#define CP_WAIT0()  asm volatile("cp.async.wait_group 0;"  ::: "memory")

__device__ __forceinline__ void ldsm_x4(uint32_t* r, uint32_t a){
    asm volatile("ldmatrix.sync.aligned.m8n8.x4.shared.b16 {%0,%1,%2,%3}, [%4];"
        : "=r"(r[0]),"=r"(r[1]),"=r"(r[2]),"=r"(r[3]) : "r"(a));
}
__device__ __forceinline__ void ldsm_x4t(uint32_t* r, uint32_t a){
    asm volatile("ldmatrix.sync.aligned.m8n8.x4.trans.shared.b16 {%0,%1,%2,%3}, [%4];"
        : "=r"(r[0]),"=r"(r[1]),"=r"(r[2]),"=r"(r[3]) : "r"(a));
}
__device__ __forceinline__ void mma16816(float* c, const uint32_t* a, const uint32_t* b){
    asm volatile("mma.sync.aligned.m16n8k16.row.col.f32.f16.f16.f32 "
        "{%0,%1,%2,%3}, {%4,%5,%6,%7}, {%8,%9}, {%0,%1,%2,%3};"
        : "+f"(c[0]),"+f"(c[1]),"+f"(c[2]),"+f"(c[3])
        : "r"(a[0]),"r"(a[1]),"r"(a[2]),"r"(a[3]), "r"(b[0]),"r"(b[1]));
}

// ---------------- fused weight prep + flow-mean partials ----------------
__device__ __forceinline__ void prep_conv_one(const float* w, int idx,
        int BN, int Cin, int KC, int base, int permL1){
    int co = idx % BN; int r = idx / BN;
    int krow = r % 16; r /= 16;
    int kx = r % 3; r /= 3;
    int kc = r % KC; int ky = r / KC;
    int ci = kc*16 + krow;
    int tap = ky*3 + kx;
    float v = 0.f;
    if (ci < Cin){
        int srcci = permL1 ? (ci < 128 ? ci + 3 : ci - 128) : ci;
        v = w[(co*Cin + srcci)*9 + tap];
    }
    g_wp[base + (((ky*KC + kc)*3 + kx)*16 + krow)*BN + co] = __float2half(v);
}

#define PREP_TOTAL (165888+147456+73728+36864+18432+9216+8192+5120)
#define PREP_BLOCKS ((PREP_TOTAL + 255)/256)

__global__ void prep_all(const float* __restrict__ mw1, const float* __restrict__ mw2,
                         const float* __restrict__ mw3, const float* __restrict__ mw4,
                         const float* __restrict__ mw5, const float* __restrict__ mw6,
                         const float* __restrict__ fw,  const float* __restrict__ dw1,
                         const float* __restrict__ flow){
    __shared__ float red[256];
    if (blockIdx.x >= PREP_BLOCKS){
        int fb = blockIdx.x - PREP_BLOCKS;
        int bc = fb >> 3, chunk = fb & 7;
        const float* p = flow + bc*HWSZ + chunk*(HWSZ/8);
        float s = 0.f;
        for (int i = threadIdx.x; i < HWSZ/8; i += 256) s += p[i];
        red[threadIdx.x] = s; __syncthreads();
        for (int o = 128; o > 0; o >>= 1){
            if (threadIdx.x < o) red[threadIdx.x] += red[threadIdx.x+o];
            __syncthreads();
        }
        if (threadIdx.x == 0) g_fpart[fb] = red[0] / (float)HWSZ;
        return;
    }
    int idx = blockIdx.x*256 + threadIdx.x;
    if (idx < 165888){ prep_conv_one(mw1, idx, 128, 131, 9, 0, 1); return; }
    idx -= 165888;
    if (idx < 147456){ prep_conv_one(mw2, idx, 128, 128, 8, 165888, 0); return; }
    idx -= 147456;
    if (idx < 73728){ prep_conv_one(mw3, idx, 64, 128, 8, 313344, 0); return; }
    idx -= 73728;
    if (idx < 36864){ prep_conv_one(mw4, idx, 64, 64, 4, 387072, 0); return; }
    idx -= 36864;
    if (idx < 18432){ prep_conv_one(mw5, idx, 32, 64, 4, 423936, 0); return; }
    idx -= 18432;
    if (idx < 9216){ prep_conv_one(mw6, idx, 32, 32, 2, 442368, 0); return; }
    idx -= 9216;
    if (idx < 64*128){
        int ci = idx >> 7, co = idx & 127;
        g_wpf[ci*128 + co] = __float2half(fw[co*64 + ci]);
        return;
    }
    idx -= 64*128;
    if (idx < 5*2*16*32){
        int co = idx & 31; int r = idx >> 5;
        int krow = r % 16; r /= 16;
        int kc = r & 1; int ky = r >> 1;
        int ci = kc*16 + krow;
        float v = (co < 25) ? dw1[(co*32 + ci)*5 + ky] : 0.f;
        g_wpd[idx] = __float2half(v);
    }
}

// ---------------- backwarp diff + centered flow -> g_x ch 128..143 ----------------
__global__ void assemble_kernel(const float* __restrict__ t1,
                                const float* __restrict__ t2,
                                const float* __restrict__ flow){
    int idx = blockIdx.x*256 + threadIdx.x;
    if (idx >= BB*HWSZ) return;
    int b = idx / HWSZ, p = idx % HWSZ;
    int h = p / WW, w = p % WW;
    float mean0 = 0.f, mean1 = 0.f;
    #pragma unroll
    for (int i = 0; i < 8; i++){
        mean0 += g_fpart[(b*2+0)*8 + i];
        mean1 += g_fpart[(b*2+1)*8 + i];
    }
    float f0 = flow[(b*2+0)*HWSZ + p];
    float f1 = flow[(b*2+1)*HWSZ + p];
    float x = (float)w + f0*5.0f;
    float y = (float)h + f1*5.0f;
    float x0f = floorf(x), y0f = floorf(y);
    int x0 = (int)x0f, y0 = (int)y0f;
    float wx1 = x - x0f, wy1 = y - y0f;
    float wx0 = 1.f - wx1, wy0 = 1.f - wy1;
    float d2 = 0.f;
    #pragma unroll
    for (int c = 0; c < 3; c++){
        const float* img = t2 + (b*3+c)*HWSZ;
        float v00 = (y0   >= 0 && y0   < HH && x0   >= 0 && x0   < WW) ? img[y0*WW + x0]       : 0.f;
        float v01 = (y0   >= 0 && y0   < HH && x0+1 >= 0 && x0+1 < WW) ? img[y0*WW + x0+1]     : 0.f;
        float v10 = (y0+1 >= 0 && y0+1 < HH && x0   >= 0 && x0   < WW) ? img[(y0+1)*WW + x0]   : 0.f;
        float v11 = (y0+1 >= 0 && y0+1 < HH && x0+1 >= 0 && x0+1 < WW) ? img[(y0+1)*WW + x0+1] : 0.f;
        float warp = v00*(wy0*wx0) + v01*(wy0*wx1) + v10*(wy1*wx0) + v11*(wy1*wx1);
        float dv = t1[(b*3+c)*HWSZ + p] - warp;
        d2 += dv*dv;
    }
    __half hv[16];
    hv[0] = __float2half(sqrtf(d2));
    hv[1] = __float2half(f0 - mean0);
    hv[2] = __float2half(f1 - mean1);
    #pragma unroll
    for (int i = 3; i < 16; i++) hv[i] = __float2half(0.f);
    uint4* dst = reinterpret_cast<uint4*>(g_x + ((size_t)idx)*144 + 128);
    const uint4* srcv = reinterpret_cast<const uint4*>(hv);
    dst[0] = srcv[0]; dst[1] = srcv[1];
}

// ---------------- feat: 1x1 conv 64->128 via mma ----------------
__global__ void __launch_bounds__(256) feat_mma(const float* __restrict__ fin,
                                                const float* __restrict__ fb){
    __shared__ __align__(16) __half sA[64*72];
    __shared__ __align__(16) __half sB[64*136];

    int tid = threadIdx.x, wid = tid >> 5, lane = tid & 31;
    int b = blockIdx.z, y = blockIdx.y;
    int x0 = blockIdx.x * 64;
    int warp_m = wid & 3, warp_n = wid >> 2;
    int m_off = warp_m * 16, n_off = warp_n * 64;

    uint32_t sAu = smem_u32(sA), sBu = smem_u32(sB);
    int a_krow = (lane & 7) + ((lane >> 4) << 3);
    int a_mcol = m_off + (((lane >> 3) & 1) << 3);
    uint32_t aBase = sAu + (uint32_t)((a_krow*72 + a_mcol) * 2);
    uint32_t bBase = sBu + (uint32_t)(((lane & 15)*136 + n_off) * 2) + ((lane >> 4) << 4);

    float acc[8][4];
    #pragma unroll
    for (int nt = 0; nt < 8; nt++)
        #pragma unroll
        for (int r = 0; r < 4; r++) acc[nt][r] = 0.f;

    const float* fbase = fin + (size_t)b*64*HWSZ + (size_t)y*WW + x0;

    #pragma unroll
    for (int k = 0; k < 4; k++){
        int c = tid + k*256;
        int row = c >> 4, q = c & 15;
        float4 v = *reinterpret_cast<const float4*>(fbase + (size_t)row*HWSZ + q*4);
        __half2 h0 = __floats2half2_rn(v.x, v.y);
        __half2 h1 = __floats2half2_rn(v.z, v.w);
        uint32_t dst = sAu + (uint32_t)((row*72 + q*4) * 2);
        asm volatile("st.shared.v2.b32 [%0], {%1, %2};"
            :: "r"(dst), "r"(*(uint32_t*)&h0), "r"(*(uint32_t*)&h1) : "memory");
    }
    #pragma unroll
    for (int k = 0; k < 4; k++){
        int c = tid + k*256;
        int r = c >> 4, cu = c & 15;
        *reinterpret_cast<uint4*>(sB + r*136 + cu*8) =
            *reinterpret_cast<const uint4*>(g_wpf + r*128 + cu*8);
    }
    __syncthreads();

    #pragma unroll
    for (int kci = 0; kci < 4; kci++){
        uint32_t afr[4];
        ldsm_x4t(afr, aBase + (uint32_t)(kci*16*72*2));
        uint32_t bfr[8][2];
        #pragma unroll
        for (int np = 0; np < 4; np++){
            uint32_t r4[4];
            ldsm_x4t(r4, bBase + (uint32_t)(kci*16*136*2 + np*16*2));
            bfr[2*np][0] = r4[0]; bfr[2*np][1] = r4[1];
            bfr[2*np+1][0] = r4[2]; bfr[2*np+1][1] = r4[3];
        }
        #pragma unroll
        for (int nt = 0; nt < 8; nt++)
            mma16816(acc[nt], afr, bfr[nt]);
    }

    int row = lane >> 2, col = (lane & 3)*2;
    __half* obase = g_x + ((size_t)(b*HH + y)*WW + x0)*144;
    int m0 = m_off + row;
    #pragma unroll
    for (int nt = 0; nt < 8; nt++){
        int n0 = n_off + nt*8 + col;
        float bv0 = fb[n0], bv1 = fb[n0+1];
        __half2 v0 = __halves2half2(__float2half(lrelu(acc[nt][0] + bv0)),
                                    __float2half(lrelu(acc[nt][1] + bv1)));
        __half2 v1 = __halves2half2(__float2half(lrelu(acc[nt][2] + bv0)),
                                    __float2half(lrelu(acc[nt][3] + bv1)));
        *reinterpret_cast<__half2*>(obase + (size_t)m0*144 + n0)     = v0;
        *reinterpret_cast<__half2*>(obase + (size_t)(m0+8)*144 + n0) = v1;
    }
}

// ---------------- unified NHWC conv: block 224 px x BNB co, 224 thr, 7 warps 32xBNB ----------------
// BNB: block Cout (64 or 32); BNW: packed weight row width; BNO: output tensor channel stride
template<int BNB, int BNW, int BNO>
__global__ void __launch_bounds__(224, 2) conv3x3_u(
        const __half* __restrict__ act, int CX, int KC, int cosplit,
        const float* __restrict__ bias, __half* __restrict__ out, int wp_base){
    constexpr int NT  = BNB/8;          // n8 tiles per warp
    constexpr int SBS = BNB + 8;
    constexpr int ABUF = 226*48;        // bytes per A buffer (row stride 48B)
    constexpr int BBUF = 48*SBS*2;
    __shared__ __align__(16) __half sA[2*226*24];
    __shared__ __align__(16) __half sB[2*48*SBS];

    int tid = threadIdx.x, wid = tid >> 5, lane = tid & 31;
    int z = blockIdx.z;
    int b = z / cosplit, cog = z % cosplit;
    int n_base = cog * BNB;
    int y = blockIdx.y;
    int x0 = blockIdx.x * 224;          // 2 x-tiles, exact
    int m_off = wid * 32;

    uint32_t sAu = smem_u32(sA), sBu = smem_u32(sB);

    int gylist[3]; int nky = 0;
    #pragma unroll
    for (int ky = 0; ky < 3; ky++){
        int gy = y + ky - 1;
        if (gy >= 0 && gy < HH){ gylist[nky] = (ky << 16) | gy; nky++; }
    }
    int N = nky * KC;

    float acc[2][NT][4];
    #pragma unroll
    for (int mt = 0; mt < 2; mt++)
        #pragma unroll
        for (int nt = 0; nt < NT; nt++)
            #pragma unroll
            for (int r = 0; r < 4; r++) acc[mt][nt][r] = 0.f;

    const size_t brow = (size_t)b * HH;

    auto stage = [&](int it){
        int buf = it & 1;
        int kykey = gylist[it / KC];
        int ky = kykey >> 16, gy = kykey & 0xffff;
        int kc = it % KC;
        const __half* arowb = act + ((brow + gy)*WW)*CX + kc*16;
        uint32_t adst = sAu + buf*ABUF;
        for (int c = tid; c < 452; c += 224){
            int r = c >> 1, hf = c & 1;
            int gx = x0 - 1 + r;
            int ok = (gx >= 0 && gx < WW) ? 16 : 0;
            int gxc = gx < 0 ? 0 : (gx >= WW ? WW-1 : gx);
            cp16(adst + r*48 + hf*16, arowb + (size_t)gxc*CX + hf*8, ok);
        }
        const __half* wsrc = g_wp + wp_base + (size_t)((ky*KC + kc)*48) * BNW + n_base;
        uint32_t bdst = sBu + buf*BBUF;
        constexpr int CPR = BNB/8;          // 16B chunks per row
        for (int c = tid; c < 48*CPR; c += 224){
            int r = c / CPR, cu = c % CPR;
            cp16(bdst + (r*SBS + cu*8)*2, wsrc + (size_t)r*BNW + cu*8, 16);
        }
        CP_COMMIT();
    };

    stage(0);
    for (int it = 0; it < N; it++){
        CP_WAIT0();
        __syncthreads();
        if (it + 1 < N) stage(it+1);
        int buf = it & 1;
        uint32_t aBase = sAu + buf*ABUF + ((lane & 15)*48) + ((lane >> 4)*16);
        uint32_t bBase = sBu + buf*BBUF + ((lane & 15)*SBS)*2 + ((lane >> 4)*16);
        #pragma unroll
        for (int kx = 0; kx < 3; kx++){
            uint32_t afr[2][4];
            ldsm_x4(afr[0], aBase + (m_off + kx)*48);
            ldsm_x4(afr[1], aBase + (m_off + kx + 16)*48);
            uint32_t bfr[NT][2];
            #pragma unroll
            for (int np = 0; np < NT/2; np++){
                uint32_t r4[4];
                ldsm_x4t(r4, bBase + (kx*16)*SBS*2 + np*16*2);
                bfr[2*np][0] = r4[0]; bfr[2*np][1] = r4[1];
                bfr[2*np+1][0] = r4[2]; bfr[2*np+1][1] = r4[3];
            }
            #pragma unroll
            for (int mt = 0; mt < 2; mt++)
                #pragma unroll
                for (int nt = 0; nt < NT; nt++)
                    mma16816(acc[mt][nt], afr[mt], bfr[nt]);
        }
    }

    int row = lane >> 2, col = (lane & 3)*2;
    __half* obase = out + ((brow + y)*WW + x0) * BNO + n_base;
    #pragma unroll
    for (int mt = 0; mt < 2; mt++){
        int m0 = m_off + mt*16 + row;
        #pragma unroll
        for (int nt = 0; nt < NT; nt++){
            int n0 = nt*8 + col;
            float bv0 = bias[n_base + n0], bv1 = bias[n_base + n0 + 1];
            __half2 v0 = __halves2half2(__float2half(lrelu(acc[mt][nt][0] + bv0)),
                                        __float2half(lrelu(acc[mt][nt][1] + bv1)));
            __half2 v1 = __halves2half2(__float2half(lrelu(acc[mt][nt][2] + bv0)),
                                        __float2half(lrelu(acc[mt][nt][3] + bv1)));
            *reinterpret_cast<__half2*>(obase + (size_t)m0*BNO + n0)       = v0;
            *reinterpret_cast<__half2*>(obase + (size_t)(m0+8)*BNO + n0)   = v1;
        }
    }
}

// ---------------- dist1: 5x1 conv 32->25(pad32) via mma -> g_d1 NHWC fp32 ----------------
__global__ void __launch_bounds__(448) dist1_mma(const __half* __restrict__ act,
                                                 const float* __restrict__ b1){
    constexpr int SBS = 40;
    constexpr int ABUF = 224*48;
    constexpr int BBUF = 16*SBS*2;
    __shared__ __align__(16) __half sA[2*224*24];
    __shared__ __align__(16) __half sB[2*16*SBS];

    int tid = threadIdx.x, wid = tid >> 5, lane = tid & 31;
    int b = blockIdx.z, y = blockIdx.y;
    int x0 = blockIdx.x * 224;
    int warp_m = wid % 7, warp_n = wid / 7;
    int m_off = warp_m * 32, n_off = warp_n * 16;

    uint32_t sAu = smem_u32(sA), sBu = smem_u32(sB);

    int gylist[5]; int nky = 0;
    #pragma unroll
    for (int ky = 0; ky < 5; ky++){
        int gy = y + ky - 2;
        if (gy >= 0 && gy < HH){ gylist[nky] = (ky << 16) | gy; nky++; }
    }
    int N = nky * 2;

    float acc[2][2][4];
    #pragma unroll
    for (int mt = 0; mt < 2; mt++)
        #pragma unroll
        for (int nt = 0; nt < 2; nt++)
            #pragma unroll
            for (int r = 0; r < 4; r++) acc[mt][nt][r] = 0.f;

    const size_t brow = (size_t)b * HH;

    auto stage = [&](int it){
        int buf = it & 1;
        int kykey = gylist[it >> 1];
        int ky = kykey >> 16, gy = kykey & 0xffff;
        int kc = it & 1;
        const __half* arowb = act + ((brow + gy)*WW + x0)*32 + kc*16;
        uint32_t adst = sAu + buf*ABUF;
        {
            int c = tid;
            int r = c >> 1, hf = c & 1;
            cp16(adst + r*48 + hf*16, arowb + (size_t)r*32 + hf*8, 16);
        }
        const __half* wsrc = g_wpd + ((ky*2 + kc)*16) * 32;
        uint32_t bdst = sBu + buf*BBUF;
        if (tid < 64){
            int r = tid >> 2, cu = tid & 3;
            cp16(bdst + (r*SBS + cu*8)*2, wsrc + r*32 + cu*8, 16);
        }
        CP_COMMIT();
    };

    stage(0);
    for (int it = 0; it < N; it++){
        CP_WAIT0();
        __syncthreads();
        if (it + 1 < N) stage(it+1);
        int buf = it & 1;
        uint32_t aBase = sAu + buf*ABUF + ((lane & 15)*48) + ((lane >> 4)*16);
        uint32_t bBase = sBu + buf*BBUF + ((lane & 15)*SBS + n_off)*2 + ((lane >> 4)*16);
        uint32_t afr[2][4];
        ldsm_x4(afr[0], aBase + m_off*48);
        ldsm_x4(afr[1], aBase + (m_off + 16)*48);
        uint32_t r4[4];
        ldsm_x4t(r4, bBase);
        uint32_t bfr[2][2];
        bfr[0][0] = r4[0]; bfr[0][1] = r4[1];
        bfr[1][0] = r4[2]; bfr[1][1] = r4[3];
        #pragma unroll
        for (int mt = 0; mt < 2; mt++)
            #pragma unroll
            for (int nt = 0; nt < 2; nt++)
                mma16816(acc[mt][nt], afr[mt], bfr[nt]);
    }

    int row = lane >> 2, col = (lane & 3)*2;
    float* obase = g_d1 + ((brow + y)*WW + x0) * 32;
    #pragma unroll
    for (int mt = 0; mt < 2; mt++){
        int m0 = m_off + mt*16 + row;
        #pragma unroll
        for (int nt = 0; nt < 2; nt++){
            int n0 = n_off + nt*8 + col;
            float bv0 = (n0   < 25) ? b1[n0]   : 0.f;
            float bv1 = (n0+1 < 25) ? b1[n0+1] : 0.f;
            float2 v0 = make_float2(acc[mt][nt][0] + bv0, acc[mt][nt][1] + bv1);
            float2 v1 = make_float2(acc[mt][nt][2] + bv0, acc[mt][nt][3] + bv1);
            *reinterpret_cast<float2*>(obase + (size_t)m0*32 + n0)     = v0;
            *reinterpret_cast<float2*>(obase + (size_t)(m0+8)*32 + n0) = v1;
        }
    }
}

// ---------------- dist2 (1x5) + softmax + unfold-weighted flow avg ----------------
__global__ void __launch_bounds__(224) final_kernel(
        const float* __restrict__ w2, const float* __restrict__ b2,
        const float* __restrict__ flow,
        const float* __restrict__ sxw, const float* __restrict__ sxb,
        const float* __restrict__ syw, const float* __restrict__ syb,
        float* __restrict__ out){
    int blk  = blockIdx.x;
    int half = blk & 1;
    int bh   = blk >> 1;
    int b = bh / HH, h = bh % HH;
    int x0 = half * 224;

    __shared__ float sd[25][228];
    __shared__ float sw2[25*25*5];
    for (int t = threadIdx.x; t < 228; t += 224){
        int gx = x0 + t - 2;
        if (gx >= 0 && gx < WW){
            const float4* src = reinterpret_cast<const float4*>(
                g_d1 + ((size_t)(b*HH + h)*WW + gx)*32);
            #pragma unroll
            for (int q = 0; q < 7; q++){
                float4 v = src[q];
                int c0 = q*4;
                if (c0     < 25) sd[c0][t]   = v.x;
                if (c0 + 1 < 25) sd[c0+1][t] = v.y;
                if (c0 + 2 < 25) sd[c0+2][t] = v.z;
                if (c0 + 3 < 25) sd[c0+3][t] = v.w;
            }
        } else {
            #pragma unroll
            for (int ci = 0; ci < 25; ci++) sd[ci][t] = 0.f;
        }
    }
    for (int i = threadIdx.x; i < 25*25*5; i += 224) sw2[i] = w2[i];
    __syncthreads();

    int lx = threadIdx.x;
    int x  = x0 + lx;
    float acc[25];
    #pragma unroll
    for (int co = 0; co < 25; co++) acc[co] = 0.f;
    for (int ci = 0; ci < 25; ci++){
        #pragma unroll
        for (int kw = 0; kw < 5; kw++){
            float v = sd[ci][lx + kw];
            #pragma unroll
            for (int co = 0; co < 25; co++)
                acc[co] = fmaf(v, sw2[(co*25+ci)*5 + kw], acc[co]);
        }
    }
    float m = -1e30f;
    #pragma unroll
    for (int co = 0; co < 25; co++){
        float d = acc[co] + b2[co];
        d = -(d*d);
        acc[co] = d;
        m = fmaxf(m, d);
    }
    float s = 0.f;
    #pragma unroll
    for (int co = 0; co < 25; co++){ acc[co] = expf(acc[co] - m); s += acc[co]; }
    float dv = 1.f / s;

    const float* f0 = flow + (b*2+0)*HWSZ;
    const float* f1 = flow + (b*2+1)*HWSZ;
    float sx = sxb[0], sy = syb[0];
    #pragma unroll
    for (int k = 0; k < 25; k++){
        int kh = k / 5, kw = k % 5;
        int gy = h + kh - 2, gx = x + kw - 2;
        float u1 = 0.f, u2 = 0.f;
        if (gy >= 0 && gy < HH && gx >= 0 && gx < WW){
            u1 = f0[gy*WW + gx];
            u2 = f1[gy*WW + gx];
        }
        sx = fmaf(sxw[k], acc[k]*u1, sx);
        sy = fmaf(syw[k], acc[k]*u2, sy);
    }
    out[(b*2+0)*HWSZ + h*WW + x] = sx * dv;
    out[(b*2+1)*HWSZ + h*WW + x] = sy * dv;
}

extern "C" void kernel_launch(void* const* d_in, const int* in_sizes, int n_in,
                              void* d_out, int out_size){
    const float* t1     = (const float*)d_in[0];
    const float* t2     = (const float*)d_in[1];
    const float* ft1    = (const float*)d_in[2];
    const float* flow   = (const float*)d_in[4];
    const float* feat_w = (const float*)d_in[5];
    const float* feat_b = (const float*)d_in[6];
    const float* mw1 = (const float*)d_in[7];  const float* mb1 = (const float*)d_in[8];
    const float* mw2 = (const float*)d_in[9];  const float* mb2 = (const float*)d_in[10];
    const float* mw3 = (const float*)d_in[11]; const float* mb3 = (const float*)d_in[12];
    const float* mw4 = (const float*)d_in[13]; const float* mb4 = (const float*)d_in[14];
    const float* mw5 = (const float*)d_in[15]; const float* mb5 = (const float*)d_in[16];
    const float* mw6 = (const float*)d_in[17]; const float* mb6 = (const float*)d_in[18];
    const float* dw1 = (const float*)d_in[19]; const float* db1 = (const float*)d_in[20];
    const float* dw2 = (const float*)d_in[21]; const float* db2 = (const float*)d_in[22];
    const float* sxw = (const float*)d_in[23]; const float* sxb = (const float*)d_in[24];
    const float* syw = (const float*)d_in[25]; const float* syb = (const float*)d_in[26];
    float* out = (float*)d_out;

    __half *px = nullptr, *pa = nullptr, *pb = nullptr;
    cudaGetSymbolAddress((void**)&px, g_x);
    cudaGetSymbolAddress((void**)&pa, g_a);
    cudaGetSymbolAddress((void**)&pb, g_b);

    prep_all<<<PREP_BLOCKS + 64, 256>>>(mw1, mw2, mw3, mw4, mw5, mw6, feat_w, dw1, flow);
    assemble_kernel<<<(BB*HWSZ + 255)/256, 256>>>(t1, t2, flow);
    dim3 fgrid(7, HH, BB);
    feat_mma<<<fgrid, 256>>>(ft1, feat_b);

    // exact tiling: 2 x-tiles of 224; BN=128 layers split Cout over grid.z
    dim3 cgrid2(2, HH, BB*2);   // cosplit=2
    dim3 cgrid1(2, HH, BB);     // cosplit=1
    conv3x3_u< 64,128,128><<<cgrid2, 224>>>(px, 144, 9, 2, mb1, pa, 0);
    conv3x3_u< 64,128,128><<<cgrid2, 224>>>(pa, 128, 8, 2, mb2, pb, 165888);
    conv3x3_u< 64, 64, 64><<<cgrid1, 224>>>(pb, 128, 8, 1, mb3, pa, 313344);
    conv3x3_u< 64, 64, 64><<<cgrid1, 224>>>(pa,  64, 4, 1, mb4, pb, 387072);
    conv3x3_u< 32, 32, 32><<<cgrid1, 224>>>(pb,  64, 4, 1, mb5, pa, 423936);
    conv3x3_u< 32, 32, 32><<<cgrid1, 224>>>(pa,  32, 2, 1, mb6, pb, 442368);

    dim3 dgrid(2, HH, BB);
    dist1_mma<<<dgrid, 448>>>(pb, db1);
    final_kernel<<<BB*HH*2, 224>>>(dw2, db2, flow, sxw, sxb, syw, syb, out);
}

// round 14
// speedup vs baseline: 14.1414x; 1.0631x over previous
#include <cuda_runtime.h>
#include <cuda_fp16.h>
#include <math.h>
#include <stdint.h>

#define HH 192
#define WW 448
#define HWSZ (HH*WW)
#define BB 4

// ---------------- scratch (__device__ globals; no allocation) ----------------
__device__ __half g_x[BB*HWSZ*144];
__device__ __half g_a[BB*HWSZ*128];   // ping
__device__ __half g_b[BB*HWSZ*128];   // pong
__device__ float  g_d1[BB*HWSZ*32];   // dist after 5x1 conv (NHWC fp32, ch 0..24 valid)
__device__ float  g_fpart[64];        // flow mean partials [bc][chunk]
#define WP_TOTAL 460800
__device__ __align__(16) __half g_wp[WP_TOTAL];
__device__ __align__(16) __half g_wpf[64*128];       // feat 1x1 weights [ci][co]
__device__ __align__(16) __half g_wpd[5*2*16*32];    // dist1 weights [ky][kc][krow][co32]
__device__ __align__(16) float  g_wpd2[160*32];      // dist2 weights tf32 [k=kw*32+ci][co32]

__device__ __forceinline__ float lrelu(float v){ return v >= 0.f ? v : 0.1f*v; }

__device__ __forceinline__ uint32_t smem_u32(const void* p){
    uint32_t a;
    asm("{ .reg .u64 t; cvta.to.shared.u64 t, %1; cvt.u32.u64 %0, t; }" : "=r"(a) : "l"(p));
    return a;
}
__device__ __forceinline__ void cp16(uint32_t dst, const void* src, int srcsz){
    asm volatile("cp.async.ca.shared.global [%0], [%1], 16, %2;"
        :: "r"(dst), "l"(src), "r"(srcsz) : "memory");
}
#define CP_COMMIT() asm volatile("cp.async.commit_group;" ::: "memory")
#define CP_WAIT0()  asm volatile("cp.async.wait_group 0;"  ::: "memory")

__device__ __forceinline__ void ldsm_x4(uint32_t* r, uint32_t a){
    asm volatile("ldmatrix.sync.aligned.m8n8.x4.shared.b16 {%0,%1,%2,%3}, [%4];"
        : "=r"(r[0]),"=r"(r[1]),"=r"(r[2]),"=r"(r[3]) : "r"(a));
}
__device__ __forceinline__ void ldsm_x4t(uint32_t* r, uint32_t a){
    asm volatile("ldmatrix.sync.aligned.m8n8.x4.trans.shared.b16 {%0,%1,%2,%3}, [%4];"
        : "=r"(r[0]),"=r"(r[1]),"=r"(r[2]),"=r"(r[3]) : "r"(a));
}
__device__ __forceinline__ void mma16816(float* c, const uint32_t* a, const uint32_t* b){
    asm volatile("mma.sync.aligned.m16n8k16.row.col.f32.f16.f16.f32 "
        "{%0,%1,%2,%3}, {%4,%5,%6,%7}, {%8,%9}, {%0,%1,%2,%3};"
        : "+f"(c[0]),"+f"(c[1]),"+f"(c[2]),"+f"(c[3])
        : "r"(a[0]),"r"(a[1]),"r"(a[2]),"r"(a[3]), "r"(b[0]),"r"(b[1]));
}
__device__ __forceinline__ void mma_tf32(float* c, const uint32_t* a, const uint32_t* b){
    asm volatile("mma.sync.aligned.m16n8k8.row.col.f32.tf32.tf32.f32 "
        "{%0,%1,%2,%3}, {%4,%5,%6,%7}, {%8,%9}, {%0,%1,%2,%3};"
        : "+f"(c[0]),"+f"(c[1]),"+f"(c[2]),"+f"(c[3])
        : "r"(a[0]),"r"(a[1]),"r"(a[2]),"r"(a[3]), "r"(b[0]),"r"(b[1]));
}
__device__ __forceinline__ float to_tf32(float v){
    uint32_t r;
    asm("cvt.rna.tf32.f32 %0, %1;" : "=r"(r) : "f"(v));
    return __uint_as_float(r);
}
// fast exp on fma pipe: exp(x) for x <= 0; rel err ~1.5e-5
__device__ __forceinline__ float fexp(float x){
    float t = x * 1.4426950408889634f;
    float fi = floorf(t);
    float f = t - fi;                      // [0,1)
    float p = 1.3333558146e-3f;
    p = fmaf(p, f, 9.6181291076e-3f);
    p = fmaf(p, f, 5.5504108664e-2f);
    p = fmaf(p, f, 2.4022650696e-1f);
    p = fmaf(p, f, 6.9314718056e-1f);
    p = fmaf(p, f, 1.0f);
    int e = (int)fi;
    if (e < -126) e = -126;
    float s = __int_as_float((uint32_t)(e + 127) << 23);
    return p * s;
}

// ---------------- fused weight prep + flow-mean partials ----------------
__device__ __forceinline__ void prep_conv_one(const float* w, int idx,
        int BN, int Cin, int KC, int base, int permL1){
    int co = idx % BN; int r = idx / BN;
    int krow = r % 16; r /= 16;
    int kx = r % 3; r /= 3;
    int kc = r % KC; int ky = r / KC;
    int ci = kc*16 + krow;
    int tap = ky*3 + kx;
    float v = 0.f;
    if (ci < Cin){
        int srcci = permL1 ? (ci < 128 ? ci + 3 : ci - 128) : ci;
        v = w[(co*Cin + srcci)*9 + tap];
    }
    g_wp[base + (((ky*KC + kc)*3 + kx)*16 + krow)*BN + co] = __float2half(v);
}

#define PREP_TOTAL (165888+147456+73728+36864+18432+9216+8192+5120+5120)
#define PREP_BLOCKS ((PREP_TOTAL + 255)/256)

__global__ void prep_all(const float* __restrict__ mw1, const float* __restrict__ mw2,
                         const float* __restrict__ mw3, const float* __restrict__ mw4,
                         const float* __restrict__ mw5, const float* __restrict__ mw6,
                         const float* __restrict__ fw,  const float* __restrict__ dw1,
                         const float* __restrict__ dw2, const float* __restrict__ flow){
    __shared__ float red[256];
    if (blockIdx.x >= PREP_BLOCKS){
        int fb = blockIdx.x - PREP_BLOCKS;
        int bc = fb >> 3, chunk = fb & 7;
        const float* p = flow + bc*HWSZ + chunk*(HWSZ/8);
        float s = 0.f;
        for (int i = threadIdx.x; i < HWSZ/8; i += 256) s += p[i];
        red[threadIdx.x] = s; __syncthreads();
        for (int o = 128; o > 0; o >>= 1){
            if (threadIdx.x < o) red[threadIdx.x] += red[threadIdx.x+o];
            __syncthreads();
        }
        if (threadIdx.x == 0) g_fpart[fb] = red[0] / (float)HWSZ;
        return;
    }
    int idx = blockIdx.x*256 + threadIdx.x;
    if (idx < 165888){ prep_conv_one(mw1, idx, 128, 131, 9, 0, 1); return; }
    idx -= 165888;
    if (idx < 147456){ prep_conv_one(mw2, idx, 128, 128, 8, 165888, 0); return; }
    idx -= 147456;
    if (idx < 73728){ prep_conv_one(mw3, idx, 64, 128, 8, 313344, 0); return; }
    idx -= 73728;
    if (idx < 36864){ prep_conv_one(mw4, idx, 64, 64, 4, 387072, 0); return; }
    idx -= 36864;
    if (idx < 18432){ prep_conv_one(mw5, idx, 32, 64, 4, 423936, 0); return; }
    idx -= 18432;
    if (idx < 9216){ prep_conv_one(mw6, idx, 32, 32, 2, 442368, 0); return; }
    idx -= 9216;
    if (idx < 64*128){
        int ci = idx >> 7, co = idx & 127;
        g_wpf[ci*128 + co] = __float2half(fw[co*64 + ci]);
        return;
    }
    idx -= 64*128;
    if (idx < 5*2*16*32){
        int co = idx & 31; int r = idx >> 5;
        int krow = r % 16; r /= 16;
        int kc = r & 1; int ky = r >> 1;
        int ci = kc*16 + krow;
        float v = (co < 25) ? dw1[(co*32 + ci)*5 + ky] : 0.f;
        g_wpd[idx] = __float2half(v);
        return;
    }
    idx -= 5*2*16*32;
    if (idx < 160*32){
        int co = idx & 31; int k = idx >> 5;
        int kw = k >> 5, ci = k & 31;
        float v = (ci < 25 && co < 25) ? dw2[(co*25 + ci)*5 + kw] : 0.f;
        g_wpd2[idx] = to_tf32(v);
    }
}

// ---------------- backwarp diff + centered flow -> g_x ch 128..143 ----------------
__global__ void assemble_kernel(const float* __restrict__ t1,
                                const float* __restrict__ t2,
                                const float* __restrict__ flow){
    int idx = blockIdx.x*256 + threadIdx.x;
    if (idx >= BB*HWSZ) return;
    int b = idx / HWSZ, p = idx % HWSZ;
    int h = p / WW, w = p % WW;
    float mean0 = 0.f, mean1 = 0.f;
    #pragma unroll
    for (int i = 0; i < 8; i++){
        mean0 += g_fpart[(b*2+0)*8 + i];
        mean1 += g_fpart[(b*2+1)*8 + i];
    }
    float f0 = flow[(b*2+0)*HWSZ + p];
    float f1 = flow[(b*2+1)*HWSZ + p];
    float x = (float)w + f0*5.0f;
    float y = (float)h + f1*5.0f;
    float x0f = floorf(x), y0f = floorf(y);
    int x0 = (int)x0f, y0 = (int)y0f;
    float wx1 = x - x0f, wy1 = y - y0f;
    float wx0 = 1.f - wx1, wy0 = 1.f - wy1;
    float d2 = 0.f;
    #pragma unroll
    for (int c = 0; c < 3; c++){
        const float* img = t2 + (b*3+c)*HWSZ;
        float v00 = (y0   >= 0 && y0   < HH && x0   >= 0 && x0   < WW) ? img[y0*WW + x0]       : 0.f;
        float v01 = (y0   >= 0 && y0   < HH && x0+1 >= 0 && x0+1 < WW) ? img[y0*WW + x0+1]     : 0.f;
        float v10 = (y0+1 >= 0 && y0+1 < HH && x0   >= 0 && x0   < WW) ? img[(y0+1)*WW + x0]   : 0.f;
        float v11 = (y0+1 >= 0 && y0+1 < HH && x0+1 >= 0 && x0+1 < WW) ? img[(y0+1)*WW + x0+1] : 0.f;
        float warp = v00*(wy0*wx0) + v01*(wy0*wx1) + v10*(wy1*wx0) + v11*(wy1*wx1);
        float dv = t1[(b*3+c)*HWSZ + p] - warp;
        d2 += dv*dv;
    }
    __half hv[16];
    hv[0] = __float2half(sqrtf(d2));
    hv[1] = __float2half(f0 - mean0);
    hv[2] = __float2half(f1 - mean1);
    #pragma unroll
    for (int i = 3; i < 16; i++) hv[i] = __float2half(0.f);
    uint4* dst = reinterpret_cast<uint4*>(g_x + ((size_t)idx)*144 + 128);
    const uint4* srcv = reinterpret_cast<const uint4*>(hv);
    dst[0] = srcv[0]; dst[1] = srcv[1];
}

// ---------------- feat: 1x1 conv 64->128 via mma ----------------
__global__ void __launch_bounds__(256) feat_mma(const float* __restrict__ fin,
                                                const float* __restrict__ fb){
    __shared__ __align__(16) __half sA[64*72];
    __shared__ __align__(16) __half sB[64*136];

    int tid = threadIdx.x, wid = tid >> 5, lane = tid & 31;
    int b = blockIdx.z, y = blockIdx.y;
    int x0 = blockIdx.x * 64;
    int warp_m = wid & 3, warp_n = wid >> 2;
    int m_off = warp_m * 16, n_off = warp_n * 64;

    uint32_t sAu = smem_u32(sA), sBu = smem_u32(sB);
    int a_krow = (lane & 7) + ((lane >> 4) << 3);
    int a_mcol = m_off + (((lane >> 3) & 1) << 3);
    uint32_t aBase = sAu + (uint32_t)((a_krow*72 + a_mcol) * 2);
    uint32_t bBase = sBu + (uint32_t)(((lane & 15)*136 + n_off) * 2) + ((lane >> 4) << 4);

    float acc[8][4];
    #pragma unroll
    for (int nt = 0; nt < 8; nt++)
        #pragma unroll
        for (int r = 0; r < 4; r++) acc[nt][r] = 0.f;

    const float* fbase = fin + (size_t)b*64*HWSZ + (size_t)y*WW + x0;

    #pragma unroll
    for (int k = 0; k < 4; k++){
        int c = tid + k*256;
        int row = c >> 4, q = c & 15;
        float4 v = *reinterpret_cast<const float4*>(fbase + (size_t)row*HWSZ + q*4);
        __half2 h0 = __floats2half2_rn(v.x, v.y);
        __half2 h1 = __floats2half2_rn(v.z, v.w);
        uint32_t dst = sAu + (uint32_t)((row*72 + q*4) * 2);
        asm volatile("st.shared.v2.b32 [%0], {%1, %2};"
            :: "r"(dst), "r"(*(uint32_t*)&h0), "r"(*(uint32_t*)&h1) : "memory");
    }
    #pragma unroll
    for (int k = 0; k < 4; k++){
        int c = tid + k*256;
        int r = c >> 4, cu = c & 15;
        *reinterpret_cast<uint4*>(sB + r*136 + cu*8) =
            *reinterpret_cast<const uint4*>(g_wpf + r*128 + cu*8);
    }
    __syncthreads();

    #pragma unroll
    for (int kci = 0; kci < 4; kci++){
        uint32_t afr[4];
        ldsm_x4t(afr, aBase + (uint32_t)(kci*16*72*2));
        uint32_t bfr[8][2];
        #pragma unroll
        for (int np = 0; np < 4; np++){
            uint32_t r4[4];
            ldsm_x4t(r4, bBase + (uint32_t)(kci*16*136*2 + np*16*2));
            bfr[2*np][0] = r4[0]; bfr[2*np][1] = r4[1];
            bfr[2*np+1][0] = r4[2]; bfr[2*np+1][1] = r4[3];
        }
        #pragma unroll
        for (int nt = 0; nt < 8; nt++)
            mma16816(acc[nt], afr, bfr[nt]);
    }

    int row = lane >> 2, col = (lane & 3)*2;
    __half* obase = g_x + ((size_t)(b*HH + y)*WW + x0)*144;
    int m0 = m_off + row;
    #pragma unroll
    for (int nt = 0; nt < 8; nt++){
        int n0 = n_off + nt*8 + col;
        float bv0 = fb[n0], bv1 = fb[n0+1];
        __half2 v0 = __halves2half2(__float2half(lrelu(acc[nt][0] + bv0)),
                                    __float2half(lrelu(acc[nt][1] + bv1)));
        __half2 v1 = __halves2half2(__float2half(lrelu(acc[nt][2] + bv0)),
                                    __float2half(lrelu(acc[nt][3] + bv1)));
        *reinterpret_cast<__half2*>(obase + (size_t)m0*144 + n0)     = v0;
        *reinterpret_cast<__half2*>(obase + (size_t)(m0+8)*144 + n0) = v1;
    }
}

// ---------------- unified NHWC conv: block 224 px x BNB co, 224 thr, 7 warps 32xBNB ----------------
template<int BNB, int BNW, int BNO>
__global__ void __launch_bounds__(224, 2) conv3x3_u(
        const __half* __restrict__ act, int CX, int KC, int cosplit,
        const float* __restrict__ bias, __half* __restrict__ out, int wp_base){
    constexpr int NT  = BNB/8;
    constexpr int SBS = BNB + 8;
    constexpr int ABUF = 226*48;
    constexpr int BBUF = 48*SBS*2;
    __shared__ __align__(16) __half sA[2*226*24];
    __shared__ __align__(16) __half sB[2*48*SBS];

    int tid = threadIdx.x, wid = tid >> 5, lane = tid & 31;
    int z = blockIdx.z;
    int b = z / cosplit, cog = z % cosplit;
    int n_base = cog * BNB;
    int y = blockIdx.y;
    int x0 = blockIdx.x * 224;
    int m_off = wid * 32;

    uint32_t sAu = smem_u32(sA), sBu = smem_u32(sB);

    int gylist[3]; int nky = 0;
    #pragma unroll
    for (int ky = 0; ky < 3; ky++){
        int gy = y + ky - 1;
        if (gy >= 0 && gy < HH){ gylist[nky] = (ky << 16) | gy; nky++; }
    }
    int N = nky * KC;

    float acc[2][NT][4];
    #pragma unroll
    for (int mt = 0; mt < 2; mt++)
        #pragma unroll
        for (int nt = 0; nt < NT; nt++)
            #pragma unroll
            for (int r = 0; r < 4; r++) acc[mt][nt][r] = 0.f;

    const size_t brow = (size_t)b * HH;

    auto stage = [&](int it){
        int buf = it & 1;
        int kykey = gylist[it / KC];
        int ky = kykey >> 16, gy = kykey & 0xffff;
        int kc = it % KC;
        const __half* arowb = act + ((brow + gy)*WW)*CX + kc*16;
        uint32_t adst = sAu + buf*ABUF;
        for (int c = tid; c < 452; c += 224){
            int r = c >> 1, hf = c & 1;
            int gx = x0 - 1 + r;
            int ok = (gx >= 0 && gx < WW) ? 16 : 0;
            int gxc = gx < 0 ? 0 : (gx >= WW ? WW-1 : gx);
            cp16(adst + r*48 + hf*16, arowb + (size_t)gxc*CX + hf*8, ok);
        }
        const __half* wsrc = g_wp + wp_base + (size_t)((ky*KC + kc)*48) * BNW + n_base;
        uint32_t bdst = sBu + buf*BBUF;
        constexpr int CPR = BNB/8;
        for (int c = tid; c < 48*CPR; c += 224){
            int r = c / CPR, cu = c % CPR;
            cp16(bdst + (r*SBS + cu*8)*2, wsrc + (size_t)r*BNW + cu*8, 16);
        }
        CP_COMMIT();
    };

    stage(0);
    for (int it = 0; it < N; it++){
        CP_WAIT0();
        __syncthreads();
        if (it + 1 < N) stage(it+1);
        int buf = it & 1;
        uint32_t aBase = sAu + buf*ABUF + ((lane & 15)*48) + ((lane >> 4)*16);
        uint32_t bBase = sBu + buf*BBUF + ((lane & 15)*SBS)*2 + ((lane >> 4)*16);
        #pragma unroll
        for (int kx = 0; kx < 3; kx++){
            uint32_t afr[2][4];
            ldsm_x4(afr[0], aBase + (m_off + kx)*48);
            ldsm_x4(afr[1], aBase + (m_off + kx + 16)*48);
            uint32_t bfr[NT][2];
            #pragma unroll
            for (int np = 0; np < NT/2; np++){
                uint32_t r4[4];
                ldsm_x4t(r4, bBase + (kx*16)*SBS*2 + np*16*2);
                bfr[2*np][0] = r4[0]; bfr[2*np][1] = r4[1];
                bfr[2*np+1][0] = r4[2]; bfr[2*np+1][1] = r4[3];
            }
            #pragma unroll
            for (int mt = 0; mt < 2; mt++)
                #pragma unroll
                for (int nt = 0; nt < NT; nt++)
                    mma16816(acc[mt][nt], afr[mt], bfr[nt]);
        }
    }

    int row = lane >> 2, col = (lane & 3)*2;
    __half* obase = out + ((brow + y)*WW + x0) * BNO + n_base;
    #pragma unroll
    for (int mt = 0; mt < 2; mt++){
        int m0 = m_off + mt*16 + row;
        #pragma unroll
        for (int nt = 0; nt < NT; nt++){
            int n0 = nt*8 + col;
            float bv0 = bias[n_base + n0], bv1 = bias[n_base + n0 + 1];
            __half2 v0 = __halves2half2(__float2half(lrelu(acc[mt][nt][0] + bv0)),
                                        __float2half(lrelu(acc[mt][nt][1] + bv1)));
            __half2 v1 = __halves2half2(__float2half(lrelu(acc[mt][nt][2] + bv0)),
                                        __float2half(lrelu(acc[mt][nt][3] + bv1)));
            *reinterpret_cast<__half2*>(obase + (size_t)m0*BNO + n0)       = v0;
            *reinterpret_cast<__half2*>(obase + (size_t)(m0+8)*BNO + n0)   = v1;
        }
    }
}

// ---------------- dist1: 5x1 conv 32->25(pad32) via mma -> g_d1 NHWC fp32 ----------------
__global__ void __launch_bounds__(448) dist1_mma(const __half* __restrict__ act,
                                                 const float* __restrict__ b1){
    constexpr int SBS = 40;
    constexpr int ABUF = 224*48;
    constexpr int BBUF = 16*SBS*2;
    __shared__ __align__(16) __half sA[2*224*24];
    __shared__ __align__(16) __half sB[2*16*SBS];

    int tid = threadIdx.x, wid = tid >> 5, lane = tid & 31;
    int b = blockIdx.z, y = blockIdx.y;
    int x0 = blockIdx.x * 224;
    int warp_m = wid % 7, warp_n = wid / 7;
    int m_off = warp_m * 32, n_off = warp_n * 16;

    uint32_t sAu = smem_u32(sA), sBu = smem_u32(sB);

    int gylist[5]; int nky = 0;
    #pragma unroll
    for (int ky = 0; ky < 5; ky++){
        int gy = y + ky - 2;
        if (gy >= 0 && gy < HH){ gylist[nky] = (ky << 16) | gy; nky++; }
    }
    int N = nky * 2;

    float acc[2][2][4];
    #pragma unroll
    for (int mt = 0; mt < 2; mt++)
        #pragma unroll
        for (int nt = 0; nt < 2; nt++)
            #pragma unroll
            for (int r = 0; r < 4; r++) acc[mt][nt][r] = 0.f;

    const size_t brow = (size_t)b * HH;

    auto stage = [&](int it){
        int buf = it & 1;
        int kykey = gylist[it >> 1];
        int ky = kykey >> 16, gy = kykey & 0xffff;
        int kc = it & 1;
        const __half* arowb = act + ((brow + gy)*WW + x0)*32 + kc*16;
        uint32_t adst = sAu + buf*ABUF;
        {
            int c = tid;
            int r = c >> 1, hf = c & 1;
            cp16(adst + r*48 + hf*16, arowb + (size_t)r*32 + hf*8, 16);
        }
        const __half* wsrc = g_wpd + ((ky*2 + kc)*16) * 32;
        uint32_t bdst = sBu + buf*BBUF;
        if (tid < 64){
            int r = tid >> 2, cu = tid & 3;
            cp16(bdst + (r*SBS + cu*8)*2, wsrc + r*32 + cu*8, 16);
        }
        CP_COMMIT();
    };

    stage(0);
    for (int it = 0; it < N; it++){
        CP_WAIT0();
        __syncthreads();
        if (it + 1 < N) stage(it+1);
        int buf = it & 1;
        uint32_t aBase = sAu + buf*ABUF + ((lane & 15)*48) + ((lane >> 4)*16);
        uint32_t bBase = sBu + buf*BBUF + ((lane & 15)*SBS + n_off)*2 + ((lane >> 4)*16);
        uint32_t afr[2][4];
        ldsm_x4(afr[0], aBase + m_off*48);
        ldsm_x4(afr[1], aBase + (m_off + 16)*48);
        uint32_t r4[4];
        ldsm_x4t(r4, bBase);
        uint32_t bfr[2][2];
        bfr[0][0] = r4[0]; bfr[0][1] = r4[1];
        bfr[1][0] = r4[2]; bfr[1][1] = r4[3];
        #pragma unroll
        for (int mt = 0; mt < 2; mt++)
            #pragma unroll
            for (int nt = 0; nt < 2; nt++)
                mma16816(acc[mt][nt], afr[mt], bfr[nt]);
    }

    int row = lane >> 2, col = (lane & 3)*2;
    float* obase = g_d1 + ((brow + y)*WW + x0) * 32;
    #pragma unroll
    for (int mt = 0; mt < 2; mt++){
        int m0 = m_off + mt*16 + row;
        #pragma unroll
        for (int nt = 0; nt < 2; nt++){
            int n0 = n_off + nt*8 + col;
            float bv0 = (n0   < 25) ? b1[n0]   : 0.f;
            float bv1 = (n0+1 < 25) ? b1[n0+1] : 0.f;
            float2 v0 = make_float2(acc[mt][nt][0] + bv0, acc[mt][nt][1] + bv1);
            float2 v1 = make_float2(acc[mt][nt][2] + bv0, acc[mt][nt][3] + bv1);
            *reinterpret_cast<float2*>(obase + (size_t)m0*32 + n0)     = v0;
            *reinterpret_cast<float2*>(obase + (size_t)(m0+8)*32 + n0) = v1;
        }
    }
}

// ---------------- final: dist2 via tf32 mma + softmax + unfold (fused) ----------------
// block = 224 px of one row; 224 threads, 7 warps, warp tile 32px x 32co; K=160 (5kw x 32ci)
__global__ void __launch_bounds__(224) final_mma(
        const float* __restrict__ b2, const float* __restrict__ flow,
        const float* __restrict__ sxw, const float* __restrict__ sxb,
        const float* __restrict__ syw, const float* __restrict__ syb,
        float* __restrict__ out){
    __shared__ __align__(16) float sd[6064];   // [ci(0..24, 25=zero)]*233 + px; reused as sdo[224][26]
    __shared__ __align__(16) float sB[160*32]; // dist2 weights [k][co]

    int tid = threadIdx.x, wid = tid >> 5, lane = tid & 31;
    int b = blockIdx.z, y = blockIdx.y;
    int x0 = blockIdx.x * 224;
    int gid = lane >> 2, tig = lane & 3;

    // stage dist1 row with +-2 halo (zero padded), tf32-rounded
    for (int c = tid; c < 228; c += 224){
        int gx = x0 + c - 2;
        if (gx >= 0 && gx < WW){
            const float4* src = reinterpret_cast<const float4*>(
                g_d1 + ((size_t)(b*HH + y)*WW + gx)*32);
            #pragma unroll
            for (int q = 0; q < 7; q++){
                float4 v = src[q];
                int c0 = q*4;
                if (c0     < 25) sd[(c0  )*233 + c] = to_tf32(v.x);
                if (c0 + 1 < 25) sd[(c0+1)*233 + c] = to_tf32(v.y);
                if (c0 + 2 < 25) sd[(c0+2)*233 + c] = to_tf32(v.z);
                if (c0 + 3 < 25) sd[(c0+3)*233 + c] = to_tf32(v.w);
            }
        } else {
            #pragma unroll
            for (int ci = 0; ci < 25; ci++) sd[ci*233 + c] = 0.f;
        }
    }
    for (int c = tid; c < 233; c += 224) sd[25*233 + c] = 0.f;   // zero row for ci-pad
    for (int c = tid; c < 1280; c += 224)
        *reinterpret_cast<float4*>(sB + c*4) = *reinterpret_cast<const float4*>(g_wpd2 + c*4);
    __syncthreads();

    int m0 = wid * 32;
    float acc[2][4][4];
    #pragma unroll
    for (int mt = 0; mt < 2; mt++)
        #pragma unroll
        for (int nt = 0; nt < 4; nt++)
            #pragma unroll
            for (int r = 0; r < 4; r++) acc[mt][nt][r] = 0.f;

    #pragma unroll
    for (int ch = 0; ch < 20; ch++){
        int kw = ch >> 2, ci0 = (ch & 3) * 8;
        int cia = ci0 + tig;       int ca = cia < 25 ? cia : 25;
        int cib = cia + 4;         int cb = cib < 25 ? cib : 25;
        uint32_t afr[2][4];
        #pragma unroll
        for (int mt = 0; mt < 2; mt++){
            int px = m0 + mt*16 + gid;
            afr[mt][0] = __float_as_uint(sd[ca*233 + px + kw]);
            afr[mt][1] = __float_as_uint(sd[ca*233 + px + 8 + kw]);
            afr[mt][2] = __float_as_uint(sd[cb*233 + px + kw]);
            afr[mt][3] = __float_as_uint(sd[cb*233 + px + 8 + kw]);
        }
        uint32_t bfr[4][2];
        int k0 = ch * 8;
        #pragma unroll
        for (int nt = 0; nt < 4; nt++){
            bfr[nt][0] = __float_as_uint(sB[(k0 + tig    )*32 + nt*8 + gid]);
            bfr[nt][1] = __float_as_uint(sB[(k0 + tig + 4)*32 + nt*8 + gid]);
        }
        #pragma unroll
        for (int mt = 0; mt < 2; mt++)
            #pragma unroll
            for (int nt = 0; nt < 4; nt++)
                mma_tf32(acc[mt][nt], afr[mt], bfr[nt]);
    }
    __syncthreads();

    // scatter acc -> sdo[px][co] (stride 26), co<25 only
    float* sdo = sd;
    #pragma unroll
    for (int mt = 0; mt < 2; mt++){
        int px = m0 + mt*16 + gid;
        #pragma unroll
        for (int nt = 0; nt < 4; nt++){
            int co = nt*8 + 2*tig;
            if (co < 25){
                sdo[px*26 + co]       = acc[mt][nt][0];
                sdo[(px+8)*26 + co]   = acc[mt][nt][2];
            }
            if (co + 1 < 25){
                sdo[px*26 + co + 1]     = acc[mt][nt][1];
                sdo[(px+8)*26 + co + 1] = acc[mt][nt][3];
            }
        }
    }
    __syncthreads();

    // epilogue: per-thread pixel softmax + unfold-weighted flow average
    int px = tid, x = x0 + px;
    float v[25];
    float m = -1e30f;
    #pragma unroll
    for (int co = 0; co < 25; co++){
        float d = sdo[px*26 + co] + b2[co];
        d = -(d*d);
        v[co] = d;
        m = fmaxf(m, d);
    }
    float s = 0.f;
    #pragma unroll
    for (int co = 0; co < 25; co++){ v[co] = fexp(v[co] - m); s += v[co]; }
    float dv = __fdividef(1.f, s);

    const float* f0 = flow + (b*2+0)*HWSZ;
    const float* f1 = flow + (b*2+1)*HWSZ;
    float sx = sxb[0], sy = syb[0];
    #pragma unroll
    for (int k = 0; k < 25; k++){
        int kh = k / 5, kw = k % 5;
        int gy = y + kh - 2, gx = x + kw - 2;
        float u1 = 0.f, u2 = 0.f;
        if (gy >= 0 && gy < HH && gx >= 0 && gx < WW){
            u1 = f0[gy*WW + gx];
            u2 = f1[gy*WW + gx];
        }
        sx = fmaf(sxw[k], v[k]*u1, sx);
        sy = fmaf(syw[k], v[k]*u2, sy);
    }
    out[(b*2+0)*HWSZ + y*WW + x] = sx * dv;
    out[(b*2+1)*HWSZ + y*WW + x] = sy * dv;
}

extern "C" void kernel_launch(void* const* d_in, const int* in_sizes, int n_in,
                              void* d_out, int out_size){
    const float* t1     = (const float*)d_in[0];
    const float* t2     = (const float*)d_in[1];
    const float* ft1    = (const float*)d_in[2];
    const float* flow   = (const float*)d_in[4];
    const float* feat_w = (const float*)d_in[5];
    const float* feat_b = (const float*)d_in[6];
    const float* mw1 = (const float*)d_in[7];  const float* mb1 = (const float*)d_in[8];
    const float* mw2 = (const float*)d_in[9];  const float* mb2 = (const float*)d_in[10];
    const float* mw3 = (const float*)d_in[11]; const float* mb3 = (const float*)d_in[12];
    const float* mw4 = (const float*)d_in[13]; const float* mb4 = (const float*)d_in[14];
    const float* mw5 = (const float*)d_in[15]; const float* mb5 = (const float*)d_in[16];
    const float* mw6 = (const float*)d_in[17]; const float* mb6 = (const float*)d_in[18];
    const float* dw1 = (const float*)d_in[19]; const float* db1 = (const float*)d_in[20];
    const float* dw2 = (const float*)d_in[21]; const float* db2 = (const float*)d_in[22];
    const float* sxw = (const float*)d_in[23]; const float* sxb = (const float*)d_in[24];
    const float* syw = (const float*)d_in[25]; const float* syb = (const float*)d_in[26];
    float* out = (float*)d_out;

    __half *px = nullptr, *pa = nullptr, *pb = nullptr;
    cudaGetSymbolAddress((void**)&px, g_x);
    cudaGetSymbolAddress((void**)&pa, g_a);
    cudaGetSymbolAddress((void**)&pb, g_b);

    prep_all<<<PREP_BLOCKS + 64, 256>>>(mw1, mw2, mw3, mw4, mw5, mw6, feat_w, dw1, dw2, flow);
    assemble_kernel<<<(BB*HWSZ + 255)/256, 256>>>(t1, t2, flow);
    dim3 fgrid(7, HH, BB);
    feat_mma<<<fgrid, 256>>>(ft1, feat_b);

    dim3 cgrid2(2, HH, BB*2);
    dim3 cgrid1(2, HH, BB);
    conv3x3_u< 64,128,128><<<cgrid2, 224>>>(px, 144, 9, 2, mb1, pa, 0);
    conv3x3_u< 64,128,128><<<cgrid2, 224>>>(pa, 128, 8, 2, mb2, pb, 165888);
    conv3x3_u< 64, 64, 64><<<cgrid1, 224>>>(pb, 128, 8, 1, mb3, pa, 313344);
    conv3x3_u< 64, 64, 64><<<cgrid1, 224>>>(pa,  64, 4, 1, mb4, pb, 387072);
    conv3x3_u< 32, 32, 32><<<cgrid1, 224>>>(pb,  64, 4, 1, mb5, pa, 423936);
    conv3x3_u< 32, 32, 32><<<cgrid1, 224>>>(pa,  32, 2, 1, mb6, pb, 442368);

    dim3 dgrid(2, HH, BB);
    dist1_mma<<<dgrid, 448>>>(pb, db1);
    final_mma<<<dgrid, 224>>>(db2, flow, sxw, sxb, syw, syb, out);
}